// round 1
// baseline (speedup 1.0000x reference)
#include <cuda_runtime.h>
#include <cuda_bf16.h>
#include <math.h>

// Problem constants
#define BB 2
#define SS_ 2048
#define DD 2048
#define HH 16
#define KVH 8
#define HD 128
#define KVR 512
#define ROWS (BB*SS_)          // 4096
#define QCOLS (HH*2*HD)        // 4096
#define KVCOLS (KVR+HD)        // 640
#define KVBCOLS (KVH*2*HD)     // 2048

// Scratch (device globals; no allocation allowed)
__device__ float g_q   [(size_t)ROWS*QCOLS];     // [row][h*256+d], pe roped in-place
__device__ float g_kv  [(size_t)ROWS*KVCOLS];
__device__ float g_kvc [(size_t)ROWS*KVR];
__device__ float g_kpe [(size_t)ROWS*HD];        // roped
__device__ float g_kvb [(size_t)ROWS*KVBCOLS];
__device__ float g_k   [(size_t)BB*KVH*SS_*256]; // [b][hk][s][256]
__device__ float g_v   [(size_t)BB*KVH*SS_*128]; // [b][hk][s][128]
__device__ float g_attn[(size_t)ROWS*(HH*HD)];   // [row][h*128+d]
__device__ float g_cos [SS_*64];
__device__ float g_sin [SS_*64];

// ---------------------------------------------------------------------------
// Trig table: freqs in fp64 (match JAX's correctly-rounded fp32 pow), angle in
// fp32 (matches reference pos*freq in fp32), cos/sin of that angle in fp64.
// ---------------------------------------------------------------------------
__global__ void trig_kernel(const int* __restrict__ pos_ids) {
    int s = blockIdx.x;
    int i = threadIdx.x;  // 0..63
    double freq = 40.0 * pow(10000.0, -((double)(2*i)) / 128.0);
    float fr = (float)freq;
    float ang = (float)pos_ids[s] * fr;
    g_cos[s*64 + i] = (float)cos((double)ang);
    g_sin[s*64 + i] = (float)sin((double)ang);
}

// ---------------------------------------------------------------------------
// SGEMM: C[M,N] = A[M,K] @ B[K,N], row-major. 128x128x8 tile, 256 thr, 8x8/thr.
// All M,N multiples of 128; K multiple of 8.
// ---------------------------------------------------------------------------
__global__ void sgemm128(const float* __restrict__ A, const float* __restrict__ Bm,
                         float* __restrict__ C, int M, int N, int K) {
    __shared__ float As[8][132];
    __shared__ float Bs[8][128];
    int tid = threadIdx.x;
    int tx = tid & 15, ty = tid >> 4;
    int row0 = blockIdx.y * 128;
    int col0 = blockIdx.x * 128;

    float acc[8][8];
#pragma unroll
    for (int i = 0; i < 8; i++)
#pragma unroll
        for (int j = 0; j < 8; j++) acc[i][j] = 0.f;

    int ar  = tid >> 1;            // 0..127
    int ac4 = (tid & 1) * 4;       // 0 or 4
    int bk  = tid >> 5;            // 0..7
    int bc4 = (tid & 31) * 4;      // 0..124

    for (int k0 = 0; k0 < K; k0 += 8) {
        float4 av = *reinterpret_cast<const float4*>(&A[(size_t)(row0 + ar)*K + k0 + ac4]);
        As[ac4+0][ar] = av.x; As[ac4+1][ar] = av.y;
        As[ac4+2][ar] = av.z; As[ac4+3][ar] = av.w;
        *reinterpret_cast<float4*>(&Bs[bk][bc4]) =
            *reinterpret_cast<const float4*>(&Bm[(size_t)(k0 + bk)*N + col0 + bc4]);
        __syncthreads();
#pragma unroll
        for (int kk = 0; kk < 8; kk++) {
            float a[8], b[8];
#pragma unroll
            for (int i = 0; i < 4; i++) {
                a[i]   = As[kk][ty*4 + i];
                a[4+i] = As[kk][64 + ty*4 + i];
            }
#pragma unroll
            for (int j = 0; j < 4; j++) {
                b[j]   = Bs[kk][tx*4 + j];
                b[4+j] = Bs[kk][64 + tx*4 + j];
            }
#pragma unroll
            for (int i = 0; i < 8; i++)
#pragma unroll
                for (int j = 0; j < 8; j++) acc[i][j] += a[i] * b[j];
        }
        __syncthreads();
    }
#pragma unroll
    for (int i = 0; i < 8; i++) {
        int r = row0 + ((i < 4) ? (ty*4 + i) : (64 + ty*4 + (i - 4)));
        float4 v0 = make_float4(acc[i][0], acc[i][1], acc[i][2], acc[i][3]);
        float4 v1 = make_float4(acc[i][4], acc[i][5], acc[i][6], acc[i][7]);
        *reinterpret_cast<float4*>(&C[(size_t)r*N + col0 + tx*4])      = v0;
        *reinterpret_cast<float4*>(&C[(size_t)r*N + col0 + 64 + tx*4]) = v1;
    }
}

// ---------------------------------------------------------------------------
// LayerNorm(kv[:512]) -> g_kvc ; RoPE(kv[512:640]) -> g_kpe. One block per row.
// ---------------------------------------------------------------------------
__global__ void ln_rope_kv_kernel(const float* __restrict__ kvns) {
    int row = blockIdx.x;
    int tid = threadIdx.x;  // 256
    const float* x = g_kv + (size_t)row * KVCOLS;
    __shared__ float red[256];

    float v0 = x[tid], v1 = x[tid + 256];
    red[tid] = v0 + v1;
    __syncthreads();
#pragma unroll
    for (int off = 128; off > 0; off >>= 1) {
        if (tid < off) red[tid] += red[tid + off];
        __syncthreads();
    }
    float mean = red[0] * (1.f / 512.f);
    __syncthreads();
    float d0 = v0 - mean, d1 = v1 - mean;
    red[tid] = d0*d0 + d1*d1;
    __syncthreads();
#pragma unroll
    for (int off = 128; off > 0; off >>= 1) {
        if (tid < off) red[tid] += red[tid + off];
        __syncthreads();
    }
    float inv = rsqrtf(red[0] * (1.f / 512.f) + 1e-5f);
    size_t o = (size_t)row * KVR;
    g_kvc[o + tid]       = d0 * inv * kvns[tid];
    g_kvc[o + tid + 256] = d1 * inv * kvns[tid + 256];

    if (tid < 64) {
        int s = row & (SS_ - 1);
        float c = g_cos[s*64 + tid], sn = g_sin[s*64 + tid];
        float xr = x[KVR + 2*tid], xi = x[KVR + 2*tid + 1];
        g_kpe[(size_t)row*HD + 2*tid]     = xr*c - xi*sn;
        g_kpe[(size_t)row*HD + 2*tid + 1] = xr*sn + xi*c;
    }
}

// RoPE q_pe in place (q is re-generated by GEMM1 every replay => deterministic)
__global__ void rope_q_kernel() {
    int row = blockIdx.x;
    int t = threadIdx.x;    // 1024
    int h = t >> 6, i = t & 63;
    int s = row & (SS_ - 1);
    float c = g_cos[s*64 + i], sn = g_sin[s*64 + i];
    float* qp = g_q + (size_t)row*QCOLS + h*256 + 128;
    float xr = qp[2*i], xi = qp[2*i + 1];
    qp[2*i]     = xr*c - xi*sn;
    qp[2*i + 1] = xr*sn + xi*c;
}

// Assemble K [b][hk][s][256] = concat(k_nope, k_pe)
__global__ void assemble_k_kernel() {
    size_t idx = (size_t)blockIdx.x * 256 + threadIdx.x;
    int d = (int)(idx & 255);
    size_t t = idx >> 8;
    int s  = (int)(t & (SS_ - 1));
    int hk = (int)((t >> 11) & (KVH - 1));
    int b  = (int)(t >> 14);
    size_t rowbs = (size_t)b*SS_ + s;
    float val;
    if (d < 128) val = g_kvb[rowbs*KVBCOLS + hk*256 + d];
    else         val = g_kpe[rowbs*HD + (d - 128)];
    g_k[idx] = val;
}

__global__ void assemble_v_kernel() {
    size_t idx = (size_t)blockIdx.x * 256 + threadIdx.x;
    int c = (int)(idx & 127);
    size_t t = idx >> 7;
    int s  = (int)(t & (SS_ - 1));
    int hk = (int)((t >> 11) & (KVH - 1));
    int b  = (int)(t >> 14);
    g_v[idx] = g_kvb[((size_t)b*SS_ + s)*KVBCOLS + hk*256 + 128 + c];
}

// ---------------------------------------------------------------------------
// Flash-style causal attention. Block = (b,h, 64-query tile). 256 threads.
// ---------------------------------------------------------------------------
#define QSTR 257
#define KSTR 257
#define VSTR 129
#define SSTR 65
#define ATTN_SMEM_FLOATS (64*QSTR + 64*KSTR + 64*VSTR + 64*SSTR + 192)
#define ATTN_SMEM_BYTES (ATTN_SMEM_FLOATS * 4)

__global__ void attn_kernel() {
    int b  = blockIdx.x >> 4;
    int h  = blockIdx.x & 15;
    int hk = h >> 1;                // H/KVH = 2
    int qt = blockIdx.y;

    extern __shared__ float sm[];
    float* Qs  = sm;
    float* Ksm = Qs  + 64*QSTR;
    float* Vsm = Ksm + 64*KSTR;
    float* Ssm = Vsm + 64*VSTR;
    float* m_s = Ssm + 64*SSTR;
    float* l_s = m_s + 64;
    float* rsc = l_s + 64;

    int tid = threadIdx.x;
    int tx = tid & 15, ty = tid >> 4;

    const float* qbase = g_q + ((size_t)(b*SS_ + qt*64))*QCOLS + h*256;
    for (int l = tid; l < 64*256; l += 256) {
        int i = l >> 8, d = l & 255;
        Qs[i*QSTR + d] = qbase[(size_t)i*QCOLS + d];
    }
    if (tid < 64) { m_s[tid] = -3e38f; l_s[tid] = 0.f; }

    float acc[4][8];
#pragma unroll
    for (int i = 0; i < 4; i++)
#pragma unroll
        for (int c = 0; c < 8; c++) acc[i][c] = 0.f;

    const float scale = 0.08838834764831845f;  // 128^-0.5
    const size_t kvrow = (size_t)(b*KVH + hk) * SS_;

    for (int kt = 0; kt <= qt; kt++) {
        __syncthreads();  // prior tile fully consumed (also covers Qs/m_s init)
        const float* kb = g_k + (kvrow + kt*64)*256;
        const float* vb = g_v + (kvrow + kt*64)*128;
        for (int l = tid; l < 64*256; l += 256) {
            int j = l >> 8, d = l & 255;
            Ksm[j*KSTR + d] = kb[(size_t)j*256 + d];
        }
        for (int l = tid; l < 64*128; l += 256) {
            int j = l >> 7, c = l & 127;
            Vsm[j*VSTR + c] = vb[(size_t)j*128 + c];
        }
        __syncthreads();

        // S = Q K^T (4x4 per thread)
        float s[4][4];
#pragma unroll
        for (int i = 0; i < 4; i++)
#pragma unroll
            for (int j = 0; j < 4; j++) s[i][j] = 0.f;
#pragma unroll 4
        for (int d = 0; d < 256; d++) {
            float a0 = Qs[(ty*4+0)*QSTR + d];
            float a1 = Qs[(ty*4+1)*QSTR + d];
            float a2 = Qs[(ty*4+2)*QSTR + d];
            float a3 = Qs[(ty*4+3)*QSTR + d];
            float b0 = Ksm[(tx*4+0)*KSTR + d];
            float b1 = Ksm[(tx*4+1)*KSTR + d];
            float b2 = Ksm[(tx*4+2)*KSTR + d];
            float b3 = Ksm[(tx*4+3)*KSTR + d];
            s[0][0] += a0*b0; s[0][1] += a0*b1; s[0][2] += a0*b2; s[0][3] += a0*b3;
            s[1][0] += a1*b0; s[1][1] += a1*b1; s[1][2] += a1*b2; s[1][3] += a1*b3;
            s[2][0] += a2*b0; s[2][1] += a2*b1; s[2][2] += a2*b2; s[2][3] += a2*b3;
            s[3][0] += a3*b0; s[3][1] += a3*b1; s[3][2] += a3*b2; s[3][3] += a3*b3;
        }
#pragma unroll
        for (int i = 0; i < 4; i++)
#pragma unroll
            for (int j = 0; j < 4; j++) {
                int gi = ty*4 + i, gj = tx*4 + j;
                float v = s[i][j] * scale;
                if (kt == qt && gj > gi) v = -1e9f;  // NEG, matches reference mask
                Ssm[gi*SSTR + gj] = v;
            }
        __syncthreads();

        // online softmax row stats (4 threads per row)
        {
            int r = tid >> 2, qq = tid & 3;
            float mx = -3e38f;
#pragma unroll
            for (int c = 0; c < 16; c++) mx = fmaxf(mx, Ssm[r*SSTR + qq*16 + c]);
            mx = fmaxf(mx, __shfl_xor_sync(0xffffffffu, mx, 1));
            mx = fmaxf(mx, __shfl_xor_sync(0xffffffffu, mx, 2));
            float m_old = m_s[r];
            float m_new = fmaxf(m_old, mx);
            float sum = 0.f;
#pragma unroll
            for (int c = 0; c < 16; c++) {
                float p = __expf(Ssm[r*SSTR + qq*16 + c] - m_new);
                Ssm[r*SSTR + qq*16 + c] = p;
                sum += p;
            }
            sum += __shfl_xor_sync(0xffffffffu, sum, 1);
            sum += __shfl_xor_sync(0xffffffffu, sum, 2);
            if (qq == 0) {
                float sc = __expf(m_old - m_new);
                rsc[r] = sc;
                l_s[r] = l_s[r]*sc + sum;
                m_s[r] = m_new;
            }
        }
        __syncthreads();

        // O = O*rsc + P @ V   (4x8 per thread)
#pragma unroll
        for (int i = 0; i < 4; i++) {
            float sc = rsc[ty*4 + i];
#pragma unroll
            for (int c = 0; c < 8; c++) acc[i][c] *= sc;
        }
#pragma unroll 2
        for (int j = 0; j < 64; j++) {
            float p0 = Ssm[(ty*4+0)*SSTR + j];
            float p1 = Ssm[(ty*4+1)*SSTR + j];
            float p2 = Ssm[(ty*4+2)*SSTR + j];
            float p3 = Ssm[(ty*4+3)*SSTR + j];
#pragma unroll
            for (int c = 0; c < 8; c++) {
                float vv = Vsm[j*VSTR + tx*8 + c];
                acc[0][c] += p0*vv; acc[1][c] += p1*vv;
                acc[2][c] += p2*vv; acc[3][c] += p3*vv;
            }
        }
    }

    // epilogue: normalize + store
#pragma unroll
    for (int i = 0; i < 4; i++) {
        float invl = 1.f / l_s[ty*4 + i];
        int gi = qt*64 + ty*4 + i;
        float* op = g_attn + ((size_t)(b*SS_ + gi))*(HH*HD) + h*128 + tx*8;
#pragma unroll
        for (int c = 0; c < 8; c++) op[c] = acc[i][c] * invl;
    }
}

// ---------------------------------------------------------------------------
extern "C" void kernel_launch(void* const* d_in, const int* in_sizes, int n_in,
                              void* d_out, int out_size) {
    const float* x     = (const float*)d_in[0];
    const float* wq    = (const float*)d_in[1];
    const float* wkv_a = (const float*)d_in[2];
    const float* kvns  = (const float*)d_in[3];
    const float* wkv_b = (const float*)d_in[4];
    const float* wo    = (const float*)d_in[5];
    // d_in[6] attention_mask: pure causal+NEG, applied analytically in-kernel
    const int*   pos   = (const int*)d_in[7];
    float* out = (float*)d_out;

    float *q, *kv, *kvc, *kvb, *attn;
    cudaGetSymbolAddress((void**)&q,    g_q);
    cudaGetSymbolAddress((void**)&kv,   g_kv);
    cudaGetSymbolAddress((void**)&kvc,  g_kvc);
    cudaGetSymbolAddress((void**)&kvb,  g_kvb);
    cudaGetSymbolAddress((void**)&attn, g_attn);

    cudaFuncSetAttribute(attn_kernel, cudaFuncAttributeMaxDynamicSharedMemorySize,
                         ATTN_SMEM_BYTES);

    trig_kernel<<<SS_, 64>>>(pos);
    // q = x @ wq
    sgemm128<<<dim3(QCOLS/128, ROWS/128), 256>>>(x, wq, q, ROWS, QCOLS, DD);
    // kv = x @ wkv_a
    sgemm128<<<dim3(KVCOLS/128, ROWS/128), 256>>>(x, wkv_a, kv, ROWS, KVCOLS, DD);
    // layernorm + k_pe rope
    ln_rope_kv_kernel<<<ROWS, 256>>>(kvns);
    // kvb = kv_c @ wkv_b
    sgemm128<<<dim3(KVBCOLS/128, ROWS/128), 256>>>(kvc, wkv_b, kvb, ROWS, KVBCOLS, KVR);
    // rope q_pe
    rope_q_kernel<<<ROWS, 1024>>>();
    // assemble K/V head-major
    assemble_k_kernel<<<(BB*KVH*SS_*256)/256, 256>>>();
    assemble_v_kernel<<<(BB*KVH*SS_*128)/256, 256>>>();
    // attention
    attn_kernel<<<dim3(BB*HH, SS_/64), 256, ATTN_SMEM_BYTES>>>();
    // out = attn @ wo
    sgemm128<<<dim3(DD/128, ROWS/128), 256>>>(attn, wo, out, ROWS, DD, HH*HD);
}

// round 3
// speedup vs baseline: 1.3788x; 1.3788x over previous
#include <cuda_runtime.h>
#include <cuda_bf16.h>
#include <math.h>
#include <cstdint>

// Problem constants
#define BB 2
#define SS_ 2048
#define DD 2048
#define HH 16
#define KVH 8
#define HD 128
#define KVR 512
#define ROWS (BB*SS_)          // 4096
#define QCOLS (HH*2*HD)        // 4096
#define KVCOLS (KVR+HD)        // 640
#define KVBCOLS (KVH*2*HD)     // 2048

// fp32 scratch
__device__ float g_q   [(size_t)ROWS*QCOLS];
__device__ float g_kv  [(size_t)ROWS*KVCOLS];
__device__ float g_kvc [(size_t)ROWS*KVR];
__device__ float g_kpe [(size_t)ROWS*HD];
__device__ float g_kvb [(size_t)ROWS*KVBCOLS];
__device__ float g_k   [(size_t)BB*KVH*SS_*256];
__device__ float g_v   [(size_t)BB*KVH*SS_*128];
__device__ float g_attn[(size_t)ROWS*(HH*HD)];
__device__ float g_cos [SS_*64];
__device__ float g_sin [SS_*64];

// split-bf16 A matrices (row-major [M][K])
__device__ __nv_bfloat16 g_xH   [(size_t)ROWS*DD];
__device__ __nv_bfloat16 g_xL   [(size_t)ROWS*DD];
__device__ __nv_bfloat16 g_kvcH [(size_t)ROWS*KVR];
__device__ __nv_bfloat16 g_kvcL [(size_t)ROWS*KVR];
__device__ __nv_bfloat16 g_attnH[(size_t)ROWS*(HH*HD)];
__device__ __nv_bfloat16 g_attnL[(size_t)ROWS*(HH*HD)];

// transposed split-bf16 weights  WT[n][k]
__device__ __nv_bfloat16 g_wqT_hi[(size_t)QCOLS*DD];
__device__ __nv_bfloat16 g_wqT_lo[(size_t)QCOLS*DD];
__device__ __nv_bfloat16 g_waT_hi[(size_t)KVCOLS*DD];
__device__ __nv_bfloat16 g_waT_lo[(size_t)KVCOLS*DD];
__device__ __nv_bfloat16 g_wbT_hi[(size_t)KVBCOLS*KVR];
__device__ __nv_bfloat16 g_wbT_lo[(size_t)KVBCOLS*KVR];
__device__ __nv_bfloat16 g_woT_hi[(size_t)DD*(HH*HD)];
__device__ __nv_bfloat16 g_woT_lo[(size_t)DD*(HH*HD)];

// ---------------------------------------------------------------------------
// helpers
// ---------------------------------------------------------------------------
__device__ __forceinline__ uint32_t smem_u32(const void* p) {
    uint32_t a;
    asm("{ .reg .u64 t; cvta.to.shared.u64 t, %1; cvt.u32.u64 %0, t; }"
        : "=r"(a) : "l"(p));
    return a;
}
#define SWZ(o) ((o) ^ (((o) >> 3) & 0x70))

__device__ __forceinline__ void cp16(uint32_t dst, const void* src) {
    asm volatile("cp.async.cg.shared.global [%0], [%1], 16;" :: "r"(dst), "l"(src));
}
__device__ __forceinline__ void cp_commit() {
    asm volatile("cp.async.commit_group;" ::: "memory");
}
__device__ __forceinline__ void cp_wait1() {
    asm volatile("cp.async.wait_group 1;" ::: "memory");
}
__device__ __forceinline__ void ldsm_x4(uint32_t (&r)[4], uint32_t addr) {
    asm volatile("ldmatrix.sync.aligned.m8n8.x4.shared.b16 {%0,%1,%2,%3}, [%4];"
                 : "=r"(r[0]), "=r"(r[1]), "=r"(r[2]), "=r"(r[3]) : "r"(addr));
}
__device__ __forceinline__ void mma16816(float* d, const uint32_t* a, const uint32_t* b) {
    asm volatile(
        "mma.sync.aligned.m16n8k16.row.col.f32.bf16.bf16.f32 "
        "{%0,%1,%2,%3},{%4,%5,%6,%7},{%8,%9},{%0,%1,%2,%3};"
        : "+f"(d[0]), "+f"(d[1]), "+f"(d[2]), "+f"(d[3])
        : "r"(a[0]), "r"(a[1]), "r"(a[2]), "r"(a[3]), "r"(b[0]), "r"(b[1]));
}

// ---------------------------------------------------------------------------
// Trig table (fp64 freqs to match JAX fp32 pow exactly)
// ---------------------------------------------------------------------------
__global__ void trig_kernel(const int* __restrict__ pos_ids) {
    int s = blockIdx.x;
    int i = threadIdx.x;
    double freq = 40.0 * pow(10000.0, -((double)(2*i)) / 128.0);
    float ang = (float)pos_ids[s] * (float)freq;
    g_cos[s*64 + i] = (float)cos((double)ang);
    g_sin[s*64 + i] = (float)sin((double)ang);
}

// ---------------------------------------------------------------------------
// elementwise fp32 -> split bf16 (hi, lo)
// ---------------------------------------------------------------------------
__global__ void cvt_split(const float* __restrict__ X,
                          __nv_bfloat16* __restrict__ H,
                          __nv_bfloat16* __restrict__ L) {
    size_t i = ((size_t)blockIdx.x * 256 + threadIdx.x) * 4;
    float4 v = *(const float4*)(X + i);
    __nv_bfloat16 h0 = __float2bfloat16(v.x), h1 = __float2bfloat16(v.y);
    __nv_bfloat16 h2 = __float2bfloat16(v.z), h3 = __float2bfloat16(v.w);
    __nv_bfloat16 hl[4] = {h0, h1, h2, h3};
    __nv_bfloat16 ll[4] = {
        __float2bfloat16(v.x - __bfloat162float(h0)),
        __float2bfloat16(v.y - __bfloat162float(h1)),
        __float2bfloat16(v.z - __bfloat162float(h2)),
        __float2bfloat16(v.w - __bfloat162float(h3))};
    *(uint2*)(H + i) = *(uint2*)hl;
    *(uint2*)(L + i) = *(uint2*)ll;
}

// ---------------------------------------------------------------------------
// Weight transpose + split-bf16 convert: W[K][N] -> Thi/Tlo [N][K]
// ---------------------------------------------------------------------------
__global__ void transpose_cvt(const float* __restrict__ W,
                              __nv_bfloat16* __restrict__ Thi,
                              __nv_bfloat16* __restrict__ Tlo, int K, int N) {
    __shared__ float ts[32][33];
    int k0 = blockIdx.y * 32, n0 = blockIdx.x * 32;
    int tx = threadIdx.x & 31, ty = threadIdx.x >> 5;  // 32x8
#pragma unroll
    for (int i = 0; i < 4; i++)
        ts[ty + 8*i][tx] = W[(size_t)(k0 + ty + 8*i)*N + n0 + tx];
    __syncthreads();
#pragma unroll
    for (int i = 0; i < 4; i++) {
        int n = ty + 8*i;
        float v = ts[tx][n];
        __nv_bfloat16 hi = __float2bfloat16(v);
        __nv_bfloat16 lo = __float2bfloat16(v - __bfloat162float(hi));
        size_t o = (size_t)(n0 + n)*K + k0 + tx;
        Thi[o] = hi; Tlo[o] = lo;
    }
}

// ---------------------------------------------------------------------------
// Split-precision bf16 GEMM via mma.sync (HMMA):
//   C[M,N] = A[M,K] @ BT[N,K]^T computed as 3 K-sections:
//     sec0: Ahi*Bhi   sec1: Ahi*Blo   sec2: Alo*Bhi
// CTA tile 128x128, K chunk 64, double-buffered cp.async, 8 warps (2Mx4N).
// ---------------------------------------------------------------------------
#define GEMM_SMEM (2*32768)   // 64 KB

__global__ void __launch_bounds__(256)
mma_gemm(const __nv_bfloat16* __restrict__ Ahi, const __nv_bfloat16* __restrict__ Alo,
         const __nv_bfloat16* __restrict__ Bhi, const __nv_bfloat16* __restrict__ Blo,
         float* __restrict__ C, int M, int N, int K) {
    extern __shared__ char sm[];
    uint32_t sb = smem_u32(sm);
    const int tid = threadIdx.x, lane = tid & 31, wid = tid >> 5;
    const int row0 = blockIdx.y * 128, col0 = blockIdx.x * 128;
    const int wm = (wid >> 2) * 64, wn = (wid & 3) * 32;
    const int cps = K >> 6;      // chunks per section
    const int NC = 3 * cps;

    float acc[4][4][4];
#pragma unroll
    for (int mi = 0; mi < 4; mi++)
#pragma unroll
        for (int ni = 0; ni < 4; ni++)
#pragma unroll
            for (int r = 0; r < 4; r++) acc[mi][ni][r] = 0.f;

    auto load_chunk = [&](int c, int buf) {
        int cc = c, sec = 0;
        if (cc >= cps) { sec = 1; cc -= cps; }
        if (cc >= cps) { sec = 2; cc -= cps; }
        const __nv_bfloat16* gA = ((sec == 2) ? Alo : Ahi) + (size_t)row0 * K + cc * 64;
        const __nv_bfloat16* gB = ((sec == 1) ? Blo : Bhi) + (size_t)col0 * K + cc * 64;
        uint32_t base = sb + (uint32_t)buf * 32768;
#pragma unroll
        for (int i = 0; i < 4; i++) {
            int idx = tid + i * 256;
            int r = idx >> 3, s = idx & 7;
            cp16(base + SWZ((uint32_t)(r * 128 + s * 16)), gA + (size_t)r * K + s * 8);
        }
#pragma unroll
        for (int i = 0; i < 4; i++) {
            int idx = tid + i * 256;
            int r = idx >> 3, s = idx & 7;
            cp16(base + 16384 + SWZ((uint32_t)(r * 128 + s * 16)), gB + (size_t)r * K + s * 8);
        }
    };

    load_chunk(0, 0);
    cp_commit();

    for (int c = 0; c < NC; c++) {
        if (c + 1 < NC) load_chunk(c + 1, (c + 1) & 1);
        cp_commit();
        cp_wait1();
        __syncthreads();

        uint32_t sA = sb + (uint32_t)(c & 1) * 32768;
        uint32_t sB = sA + 16384;
        uint32_t Breg[4][4];
#pragma unroll
        for (int kk = 0; kk < 4; kk++) {
            if ((kk & 1) == 0) {
                int kh = kk >> 1;
#pragma unroll
                for (int ni = 0; ni < 4; ni++) {
                    uint32_t addr = sB + SWZ((uint32_t)((wn + ni*8 + (lane & 7)) * 128
                                                        + kh*64 + (lane >> 3) * 16));
                    ldsm_x4(Breg[ni], addr);
                }
            }
            uint32_t Areg[4][4];
#pragma unroll
            for (int mi = 0; mi < 4; mi++) {
                uint32_t addr = sA + SWZ((uint32_t)((wm + mi*16 + (lane & 15)) * 128
                                                    + kk*32 + (lane >> 4) * 16));
                ldsm_x4(Areg[mi], addr);
            }
#pragma unroll
            for (int mi = 0; mi < 4; mi++)
#pragma unroll
                for (int ni = 0; ni < 4; ni++)
                    mma16816(acc[mi][ni], Areg[mi], &Breg[ni][2 * (kk & 1)]);
        }
        __syncthreads();
    }

    // epilogue: direct stores (float2 per c-pair)
#pragma unroll
    for (int mi = 0; mi < 4; mi++) {
        int r0 = row0 + wm + mi * 16 + (lane >> 2);
#pragma unroll
        for (int ni = 0; ni < 4; ni++) {
            int cc = col0 + wn + ni * 8 + (lane & 3) * 2;
            *(float2*)(C + (size_t)r0 * N + cc)       = make_float2(acc[mi][ni][0], acc[mi][ni][1]);
            *(float2*)(C + (size_t)(r0 + 8) * N + cc) = make_float2(acc[mi][ni][2], acc[mi][ni][3]);
        }
    }
}

// ---------------------------------------------------------------------------
// LayerNorm + k_pe RoPE
// ---------------------------------------------------------------------------
__global__ void ln_rope_kv_kernel(const float* __restrict__ kvns) {
    int row = blockIdx.x;
    int tid = threadIdx.x;
    const float* x = g_kv + (size_t)row * KVCOLS;
    __shared__ float red[256];

    float v0 = x[tid], v1 = x[tid + 256];
    red[tid] = v0 + v1;
    __syncthreads();
#pragma unroll
    for (int off = 128; off > 0; off >>= 1) {
        if (tid < off) red[tid] += red[tid + off];
        __syncthreads();
    }
    float mean = red[0] * (1.f / 512.f);
    __syncthreads();
    float d0 = v0 - mean, d1 = v1 - mean;
    red[tid] = d0*d0 + d1*d1;
    __syncthreads();
#pragma unroll
    for (int off = 128; off > 0; off >>= 1) {
        if (tid < off) red[tid] += red[tid + off];
        __syncthreads();
    }
    float inv = rsqrtf(red[0] * (1.f / 512.f) + 1e-5f);
    size_t o = (size_t)row * KVR;
    g_kvc[o + tid]       = d0 * inv * kvns[tid];
    g_kvc[o + tid + 256] = d1 * inv * kvns[tid + 256];

    if (tid < 64) {
        int s = row & (SS_ - 1);
        float c = g_cos[s*64 + tid], sn = g_sin[s*64 + tid];
        float xr = x[KVR + 2*tid], xi = x[KVR + 2*tid + 1];
        g_kpe[(size_t)row*HD + 2*tid]     = xr*c - xi*sn;
        g_kpe[(size_t)row*HD + 2*tid + 1] = xr*sn + xi*c;
    }
}

__global__ void rope_q_kernel() {
    int row = blockIdx.x;
    int t = threadIdx.x;
    int h = t >> 6, i = t & 63;
    int s = row & (SS_ - 1);
    float c = g_cos[s*64 + i], sn = g_sin[s*64 + i];
    float* qp = g_q + (size_t)row*QCOLS + h*256 + 128;
    float xr = qp[2*i], xi = qp[2*i + 1];
    qp[2*i]     = xr*c - xi*sn;
    qp[2*i + 1] = xr*sn + xi*c;
}

__global__ void assemble_k_kernel() {
    size_t idx = (size_t)blockIdx.x * 256 + threadIdx.x;
    int d = (int)(idx & 255);
    size_t t = idx >> 8;
    int s  = (int)(t & (SS_ - 1));
    int hk = (int)((t >> 11) & (KVH - 1));
    int b  = (int)(t >> 14);
    size_t rowbs = (size_t)b*SS_ + s;
    float val;
    if (d < 128) val = g_kvb[rowbs*KVBCOLS + hk*256 + d];
    else         val = g_kpe[rowbs*HD + (d - 128)];
    g_k[idx] = val;
}

__global__ void assemble_v_kernel() {
    size_t idx = (size_t)blockIdx.x * 256 + threadIdx.x;
    int c = (int)(idx & 127);
    size_t t = idx >> 7;
    int s  = (int)(t & (SS_ - 1));
    int hk = (int)((t >> 11) & (KVH - 1));
    int b  = (int)(t >> 14);
    g_v[idx] = g_kvb[((size_t)b*SS_ + s)*KVBCOLS + hk*256 + 128 + c];
}

// ---------------------------------------------------------------------------
// fp32 flash attention (unchanged from round 1)
// ---------------------------------------------------------------------------
#define QSTR 257
#define KSTR 257
#define VSTR 129
#define SSTR 65
#define ATTN_SMEM_FLOATS (64*QSTR + 64*KSTR + 64*VSTR + 64*SSTR + 192)
#define ATTN_SMEM_BYTES (ATTN_SMEM_FLOATS * 4)

__global__ void attn_kernel() {
    int b  = blockIdx.x >> 4;
    int h  = blockIdx.x & 15;
    int hk = h >> 1;
    int qt = blockIdx.y;

    extern __shared__ float smf[];
    float* Qs  = smf;
    float* Ksm = Qs  + 64*QSTR;
    float* Vsm = Ksm + 64*KSTR;
    float* Ssm = Vsm + 64*VSTR;
    float* m_s = Ssm + 64*SSTR;
    float* l_s = m_s + 64;
    float* rsc = l_s + 64;

    int tid = threadIdx.x;
    int tx = tid & 15, ty = tid >> 4;

    const float* qbase = g_q + ((size_t)(b*SS_ + qt*64))*QCOLS + h*256;
    for (int l = tid; l < 64*256; l += 256) {
        int i = l >> 8, d = l & 255;
        Qs[i*QSTR + d] = qbase[(size_t)i*QCOLS + d];
    }
    if (tid < 64) { m_s[tid] = -3e38f; l_s[tid] = 0.f; }

    float acc[4][8];
#pragma unroll
    for (int i = 0; i < 4; i++)
#pragma unroll
        for (int c = 0; c < 8; c++) acc[i][c] = 0.f;

    const float scale = 0.08838834764831845f;
    const size_t kvrow = (size_t)(b*KVH + hk) * SS_;

    for (int kt = 0; kt <= qt; kt++) {
        __syncthreads();
        const float* kb = g_k + (kvrow + kt*64)*256;
        const float* vb = g_v + (kvrow + kt*64)*128;
        for (int l = tid; l < 64*256; l += 256) {
            int j = l >> 8, d = l & 255;
            Ksm[j*KSTR + d] = kb[(size_t)j*256 + d];
        }
        for (int l = tid; l < 64*128; l += 256) {
            int j = l >> 7, c = l & 127;
            Vsm[j*VSTR + c] = vb[(size_t)j*128 + c];
        }
        __syncthreads();

        float s[4][4];
#pragma unroll
        for (int i = 0; i < 4; i++)
#pragma unroll
            for (int j = 0; j < 4; j++) s[i][j] = 0.f;
#pragma unroll 4
        for (int d = 0; d < 256; d++) {
            float a0 = Qs[(ty*4+0)*QSTR + d];
            float a1 = Qs[(ty*4+1)*QSTR + d];
            float a2 = Qs[(ty*4+2)*QSTR + d];
            float a3 = Qs[(ty*4+3)*QSTR + d];
            float b0 = Ksm[(tx*4+0)*KSTR + d];
            float b1 = Ksm[(tx*4+1)*KSTR + d];
            float b2 = Ksm[(tx*4+2)*KSTR + d];
            float b3 = Ksm[(tx*4+3)*KSTR + d];
            s[0][0] += a0*b0; s[0][1] += a0*b1; s[0][2] += a0*b2; s[0][3] += a0*b3;
            s[1][0] += a1*b0; s[1][1] += a1*b1; s[1][2] += a1*b2; s[1][3] += a1*b3;
            s[2][0] += a2*b0; s[2][1] += a2*b1; s[2][2] += a2*b2; s[2][3] += a2*b3;
            s[3][0] += a3*b0; s[3][1] += a3*b1; s[3][2] += a3*b2; s[3][3] += a3*b3;
        }
#pragma unroll
        for (int i = 0; i < 4; i++)
#pragma unroll
            for (int j = 0; j < 4; j++) {
                int gi = ty*4 + i, gj = tx*4 + j;
                float v = s[i][j] * scale;
                if (kt == qt && gj > gi) v = -1e9f;
                Ssm[gi*SSTR + gj] = v;
            }
        __syncthreads();

        {
            int r = tid >> 2, qq = tid & 3;
            float mx = -3e38f;
#pragma unroll
            for (int c = 0; c < 16; c++) mx = fmaxf(mx, Ssm[r*SSTR + qq*16 + c]);
            mx = fmaxf(mx, __shfl_xor_sync(0xffffffffu, mx, 1));
            mx = fmaxf(mx, __shfl_xor_sync(0xffffffffu, mx, 2));
            float m_old = m_s[r];
            float m_new = fmaxf(m_old, mx);
            float sum = 0.f;
#pragma unroll
            for (int c = 0; c < 16; c++) {
                float p = __expf(Ssm[r*SSTR + qq*16 + c] - m_new);
                Ssm[r*SSTR + qq*16 + c] = p;
                sum += p;
            }
            sum += __shfl_xor_sync(0xffffffffu, sum, 1);
            sum += __shfl_xor_sync(0xffffffffu, sum, 2);
            if (qq == 0) {
                float sc = __expf(m_old - m_new);
                rsc[r] = sc;
                l_s[r] = l_s[r]*sc + sum;
                m_s[r] = m_new;
            }
        }
        __syncthreads();

#pragma unroll
        for (int i = 0; i < 4; i++) {
            float sc = rsc[ty*4 + i];
#pragma unroll
            for (int c = 0; c < 8; c++) acc[i][c] *= sc;
        }
#pragma unroll 2
        for (int j = 0; j < 64; j++) {
            float p0 = Ssm[(ty*4+0)*SSTR + j];
            float p1 = Ssm[(ty*4+1)*SSTR + j];
            float p2 = Ssm[(ty*4+2)*SSTR + j];
            float p3 = Ssm[(ty*4+3)*SSTR + j];
#pragma unroll
            for (int c = 0; c < 8; c++) {
                float vv = Vsm[j*VSTR + tx*8 + c];
                acc[0][c] += p0*vv; acc[1][c] += p1*vv;
                acc[2][c] += p2*vv; acc[3][c] += p3*vv;
            }
        }
    }

#pragma unroll
    for (int i = 0; i < 4; i++) {
        float invl = 1.f / l_s[ty*4 + i];
        int gi = qt*64 + ty*4 + i;
        float* op = g_attn + ((size_t)(b*SS_ + gi))*(HH*HD) + h*128 + tx*8;
#pragma unroll
        for (int c = 0; c < 8; c++) op[c] = acc[i][c] * invl;
    }
}

// ---------------------------------------------------------------------------
extern "C" void kernel_launch(void* const* d_in, const int* in_sizes, int n_in,
                              void* d_out, int out_size) {
    const float* x     = (const float*)d_in[0];
    const float* wq    = (const float*)d_in[1];
    const float* wkv_a = (const float*)d_in[2];
    const float* kvns  = (const float*)d_in[3];
    const float* wkv_b = (const float*)d_in[4];
    const float* wo    = (const float*)d_in[5];
    const int*   pos   = (const int*)d_in[7];
    float* out = (float*)d_out;

    float *q, *kv, *kvc, *kvb, *attn;
    cudaGetSymbolAddress((void**)&q,    g_q);
    cudaGetSymbolAddress((void**)&kv,   g_kv);
    cudaGetSymbolAddress((void**)&kvc,  g_kvc);
    cudaGetSymbolAddress((void**)&kvb,  g_kvb);
    cudaGetSymbolAddress((void**)&attn, g_attn);
    __nv_bfloat16 *xH,*xL,*kvcH,*kvcL,*attnH,*attnL;
    cudaGetSymbolAddress((void**)&xH,    g_xH);    cudaGetSymbolAddress((void**)&xL,    g_xL);
    cudaGetSymbolAddress((void**)&kvcH,  g_kvcH);  cudaGetSymbolAddress((void**)&kvcL,  g_kvcL);
    cudaGetSymbolAddress((void**)&attnH, g_attnH); cudaGetSymbolAddress((void**)&attnL, g_attnL);
    __nv_bfloat16 *wqh,*wql,*wah,*wal,*wbh,*wbl,*woh,*wol;
    cudaGetSymbolAddress((void**)&wqh, g_wqT_hi); cudaGetSymbolAddress((void**)&wql, g_wqT_lo);
    cudaGetSymbolAddress((void**)&wah, g_waT_hi); cudaGetSymbolAddress((void**)&wal, g_waT_lo);
    cudaGetSymbolAddress((void**)&wbh, g_wbT_hi); cudaGetSymbolAddress((void**)&wbl, g_wbT_lo);
    cudaGetSymbolAddress((void**)&woh, g_woT_hi); cudaGetSymbolAddress((void**)&wol, g_woT_lo);

    cudaFuncSetAttribute(attn_kernel, cudaFuncAttributeMaxDynamicSharedMemorySize,
                         ATTN_SMEM_BYTES);
    cudaFuncSetAttribute(mma_gemm, cudaFuncAttributeMaxDynamicSharedMemorySize,
                         GEMM_SMEM);

    trig_kernel<<<SS_, 64>>>(pos);

    // weight transpose + split
    transpose_cvt<<<dim3(QCOLS/32,  DD/32),  256>>>(wq,    wqh, wql, DD,  QCOLS);
    transpose_cvt<<<dim3(KVCOLS/32, DD/32),  256>>>(wkv_a, wah, wal, DD,  KVCOLS);
    transpose_cvt<<<dim3(KVBCOLS/32,KVR/32), 256>>>(wkv_b, wbh, wbl, KVR, KVBCOLS);
    transpose_cvt<<<dim3(DD/32, (HH*HD)/32), 256>>>(wo,    woh, wol, HH*HD, DD);

    // x -> split bf16
    cvt_split<<<((size_t)ROWS*DD)/1024, 256>>>(x, xH, xL);

    // q = x @ wq
    mma_gemm<<<dim3(QCOLS/128, ROWS/128), 256, GEMM_SMEM>>>(xH, xL, wqh, wql, q, ROWS, QCOLS, DD);
    // kv = x @ wkv_a
    mma_gemm<<<dim3(KVCOLS/128, ROWS/128), 256, GEMM_SMEM>>>(xH, xL, wah, wal, kv, ROWS, KVCOLS, DD);
    // layernorm + k_pe rope
    ln_rope_kv_kernel<<<ROWS, 256>>>(kvns);
    // kvc -> split
    cvt_split<<<((size_t)ROWS*KVR)/1024, 256>>>(kvc, kvcH, kvcL);
    // kvb = kv_c @ wkv_b
    mma_gemm<<<dim3(KVBCOLS/128, ROWS/128), 256, GEMM_SMEM>>>(kvcH, kvcL, wbh, wbl, kvb, ROWS, KVBCOLS, KVR);
    // rope q_pe
    rope_q_kernel<<<ROWS, 1024>>>();
    // assemble K/V head-major
    assemble_k_kernel<<<(BB*KVH*SS_*256)/256, 256>>>();
    assemble_v_kernel<<<(BB*KVH*SS_*128)/256, 256>>>();
    // attention
    attn_kernel<<<dim3(BB*HH, SS_/64), 256, ATTN_SMEM_BYTES>>>();
    // attn -> split
    cvt_split<<<((size_t)ROWS*(HH*HD))/1024, 256>>>(attn, attnH, attnL);
    // out = attn @ wo
    mma_gemm<<<dim3(DD/128, ROWS/128), 256, GEMM_SMEM>>>(attnH, attnL, woh, wol, out, ROWS, DD, HH*HD);
}

// round 4
// speedup vs baseline: 3.3142x; 2.4037x over previous
#include <cuda_runtime.h>
#include <cuda_bf16.h>
#include <math.h>
#include <cstdint>

// Problem constants
#define BB 2
#define SS_ 2048
#define DD 2048
#define HH 16
#define KVH 8
#define HD 128
#define KVR 512
#define ROWS (BB*SS_)          // 4096
#define QCOLS (HH*2*HD)        // 4096
#define KVCOLS (KVR+HD)        // 640
#define KVBCOLS (KVH*2*HD)     // 2048

// fp32 scratch
__device__ float g_q   [(size_t)ROWS*QCOLS];
__device__ float g_kv  [(size_t)ROWS*KVCOLS];
__device__ float g_kpe [(size_t)ROWS*HD];
__device__ float g_kvb [(size_t)ROWS*KVBCOLS];
__device__ float g_cos [SS_*64];
__device__ float g_sin [SS_*64];

// split-bf16 activations
__device__ __nv_bfloat16 g_xH   [(size_t)ROWS*DD];
__device__ __nv_bfloat16 g_xL   [(size_t)ROWS*DD];
__device__ __nv_bfloat16 g_kvcH [(size_t)ROWS*KVR];
__device__ __nv_bfloat16 g_kvcL [(size_t)ROWS*KVR];
__device__ __nv_bfloat16 g_attnH[(size_t)ROWS*(HH*HD)];
__device__ __nv_bfloat16 g_attnL[(size_t)ROWS*(HH*HD)];
__device__ __nv_bfloat16 g_qH   [(size_t)ROWS*QCOLS];
__device__ __nv_bfloat16 g_qL   [(size_t)ROWS*QCOLS];
__device__ __nv_bfloat16 g_kH   [(size_t)BB*KVH*SS_*256];
__device__ __nv_bfloat16 g_kL   [(size_t)BB*KVH*SS_*256];
__device__ __nv_bfloat16 g_vH   [(size_t)BB*KVH*SS_*128];
__device__ __nv_bfloat16 g_vL   [(size_t)BB*KVH*SS_*128];

// transposed split-bf16 weights  WT[n][k]
__device__ __nv_bfloat16 g_wqT_hi[(size_t)QCOLS*DD];
__device__ __nv_bfloat16 g_wqT_lo[(size_t)QCOLS*DD];
__device__ __nv_bfloat16 g_waT_hi[(size_t)KVCOLS*DD];
__device__ __nv_bfloat16 g_waT_lo[(size_t)KVCOLS*DD];
__device__ __nv_bfloat16 g_wbT_hi[(size_t)KVBCOLS*KVR];
__device__ __nv_bfloat16 g_wbT_lo[(size_t)KVBCOLS*KVR];
__device__ __nv_bfloat16 g_woT_hi[(size_t)DD*(HH*HD)];
__device__ __nv_bfloat16 g_woT_lo[(size_t)DD*(HH*HD)];

// ---------------------------------------------------------------------------
// helpers
// ---------------------------------------------------------------------------
__device__ __forceinline__ uint32_t smem_u32(const void* p) {
    uint32_t a;
    asm("{ .reg .u64 t; cvta.to.shared.u64 t, %1; cvt.u32.u64 %0, t; }"
        : "=r"(a) : "l"(p));
    return a;
}
#define SWZ(o) ((o) ^ (((o) >> 3) & 0x70))

__device__ __forceinline__ void cp16(uint32_t dst, const void* src) {
    asm volatile("cp.async.cg.shared.global [%0], [%1], 16;" :: "r"(dst), "l"(src));
}
__device__ __forceinline__ void cp_commit() {
    asm volatile("cp.async.commit_group;" ::: "memory");
}
__device__ __forceinline__ void cp_wait1() {
    asm volatile("cp.async.wait_group 1;" ::: "memory");
}
__device__ __forceinline__ void cp_wait0() {
    asm volatile("cp.async.wait_group 0;" ::: "memory");
}
__device__ __forceinline__ void ldsm_x4(uint32_t (&r)[4], uint32_t addr) {
    asm volatile("ldmatrix.sync.aligned.m8n8.x4.shared.b16 {%0,%1,%2,%3}, [%4];"
                 : "=r"(r[0]), "=r"(r[1]), "=r"(r[2]), "=r"(r[3]) : "r"(addr));
}
__device__ __forceinline__ void ldsm_x4_t(uint32_t (&r)[4], uint32_t addr) {
    asm volatile("ldmatrix.sync.aligned.m8n8.x4.trans.shared.b16 {%0,%1,%2,%3}, [%4];"
                 : "=r"(r[0]), "=r"(r[1]), "=r"(r[2]), "=r"(r[3]) : "r"(addr));
}
__device__ __forceinline__ void mma16816(float* d, const uint32_t* a, const uint32_t* b) {
    asm volatile(
        "mma.sync.aligned.m16n8k16.row.col.f32.bf16.bf16.f32 "
        "{%0,%1,%2,%3},{%4,%5,%6,%7},{%8,%9},{%0,%1,%2,%3};"
        : "+f"(d[0]), "+f"(d[1]), "+f"(d[2]), "+f"(d[3])
        : "r"(a[0]), "r"(a[1]), "r"(a[2]), "r"(a[3]), "r"(b[0]), "r"(b[1]));
}
__device__ __forceinline__ uint32_t pack_bf2(__nv_bfloat16 a, __nv_bfloat16 b) {
    uint16_t ua = __bfloat16_as_ushort(a), ub = __bfloat16_as_ushort(b);
    return (uint32_t)ua | ((uint32_t)ub << 16);
}

// ---------------------------------------------------------------------------
// Trig table (fp64 freqs to match JAX fp32 pow exactly)
// ---------------------------------------------------------------------------
__global__ void trig_kernel(const int* __restrict__ pos_ids) {
    int s = blockIdx.x;
    int i = threadIdx.x;
    double freq = 40.0 * pow(10000.0, -((double)(2*i)) / 128.0);
    float ang = (float)pos_ids[s] * (float)freq;
    g_cos[s*64 + i] = (float)cos((double)ang);
    g_sin[s*64 + i] = (float)sin((double)ang);
}

// ---------------------------------------------------------------------------
// elementwise fp32 -> split bf16 (hi, lo)
// ---------------------------------------------------------------------------
__global__ void cvt_split(const float* __restrict__ X,
                          __nv_bfloat16* __restrict__ H,
                          __nv_bfloat16* __restrict__ L) {
    size_t i = ((size_t)blockIdx.x * 256 + threadIdx.x) * 4;
    float4 v = *(const float4*)(X + i);
    __nv_bfloat16 h0 = __float2bfloat16(v.x), h1 = __float2bfloat16(v.y);
    __nv_bfloat16 h2 = __float2bfloat16(v.z), h3 = __float2bfloat16(v.w);
    __nv_bfloat16 hl[4] = {h0, h1, h2, h3};
    __nv_bfloat16 ll[4] = {
        __float2bfloat16(v.x - __bfloat162float(h0)),
        __float2bfloat16(v.y - __bfloat162float(h1)),
        __float2bfloat16(v.z - __bfloat162float(h2)),
        __float2bfloat16(v.w - __bfloat162float(h3))};
    *(uint2*)(H + i) = *(uint2*)hl;
    *(uint2*)(L + i) = *(uint2*)ll;
}

// ---------------------------------------------------------------------------
// Weight transpose + split-bf16 convert: W[K][N] -> Thi/Tlo [N][K]
// ---------------------------------------------------------------------------
__global__ void transpose_cvt(const float* __restrict__ W,
                              __nv_bfloat16* __restrict__ Thi,
                              __nv_bfloat16* __restrict__ Tlo, int K, int N) {
    __shared__ float ts[32][33];
    int k0 = blockIdx.y * 32, n0 = blockIdx.x * 32;
    int tx = threadIdx.x & 31, ty = threadIdx.x >> 5;  // 32x8
#pragma unroll
    for (int i = 0; i < 4; i++)
        ts[ty + 8*i][tx] = W[(size_t)(k0 + ty + 8*i)*N + n0 + tx];
    __syncthreads();
#pragma unroll
    for (int i = 0; i < 4; i++) {
        int n = ty + 8*i;
        float v = ts[tx][n];
        __nv_bfloat16 hi = __float2bfloat16(v);
        __nv_bfloat16 lo = __float2bfloat16(v - __bfloat162float(hi));
        size_t o = (size_t)(n0 + n)*K + k0 + tx;
        Thi[o] = hi; Tlo[o] = lo;
    }
}

// ---------------------------------------------------------------------------
// Split-precision bf16 GEMM via mma.sync (HMMA) — unchanged from round 3.
// ---------------------------------------------------------------------------
#define GEMM_SMEM (2*32768)   // 64 KB

__global__ void __launch_bounds__(256)
mma_gemm(const __nv_bfloat16* __restrict__ Ahi, const __nv_bfloat16* __restrict__ Alo,
         const __nv_bfloat16* __restrict__ Bhi, const __nv_bfloat16* __restrict__ Blo,
         float* __restrict__ C, int M, int N, int K) {
    extern __shared__ char sm[];
    uint32_t sb = smem_u32(sm);
    const int tid = threadIdx.x, lane = tid & 31, wid = tid >> 5;
    const int row0 = blockIdx.y * 128, col0 = blockIdx.x * 128;
    const int wm = (wid >> 2) * 64, wn = (wid & 3) * 32;
    const int cps = K >> 6;      // chunks per section
    const int NC = 3 * cps;

    float acc[4][4][4];
#pragma unroll
    for (int mi = 0; mi < 4; mi++)
#pragma unroll
        for (int ni = 0; ni < 4; ni++)
#pragma unroll
            for (int r = 0; r < 4; r++) acc[mi][ni][r] = 0.f;

    auto load_chunk = [&](int c, int buf) {
        int cc = c, sec = 0;
        if (cc >= cps) { sec = 1; cc -= cps; }
        if (cc >= cps) { sec = 2; cc -= cps; }
        const __nv_bfloat16* gA = ((sec == 2) ? Alo : Ahi) + (size_t)row0 * K + cc * 64;
        const __nv_bfloat16* gB = ((sec == 1) ? Blo : Bhi) + (size_t)col0 * K + cc * 64;
        uint32_t base = sb + (uint32_t)buf * 32768;
#pragma unroll
        for (int i = 0; i < 4; i++) {
            int idx = tid + i * 256;
            int r = idx >> 3, s = idx & 7;
            cp16(base + SWZ((uint32_t)(r * 128 + s * 16)), gA + (size_t)r * K + s * 8);
        }
#pragma unroll
        for (int i = 0; i < 4; i++) {
            int idx = tid + i * 256;
            int r = idx >> 3, s = idx & 7;
            cp16(base + 16384 + SWZ((uint32_t)(r * 128 + s * 16)), gB + (size_t)r * K + s * 8);
        }
    };

    load_chunk(0, 0);
    cp_commit();

    for (int c = 0; c < NC; c++) {
        if (c + 1 < NC) load_chunk(c + 1, (c + 1) & 1);
        cp_commit();
        cp_wait1();
        __syncthreads();

        uint32_t sA = sb + (uint32_t)(c & 1) * 32768;
        uint32_t sB = sA + 16384;
        uint32_t Breg[4][4];
#pragma unroll
        for (int kk = 0; kk < 4; kk++) {
            if ((kk & 1) == 0) {
                int kh = kk >> 1;
#pragma unroll
                for (int ni = 0; ni < 4; ni++) {
                    uint32_t addr = sB + SWZ((uint32_t)((wn + ni*8 + (lane & 7)) * 128
                                                        + kh*64 + (lane >> 3) * 16));
                    ldsm_x4(Breg[ni], addr);
                }
            }
            uint32_t Areg[4][4];
#pragma unroll
            for (int mi = 0; mi < 4; mi++) {
                uint32_t addr = sA + SWZ((uint32_t)((wm + mi*16 + (lane & 15)) * 128
                                                    + kk*32 + (lane >> 4) * 16));
                ldsm_x4(Areg[mi], addr);
            }
#pragma unroll
            for (int mi = 0; mi < 4; mi++)
#pragma unroll
                for (int ni = 0; ni < 4; ni++)
                    mma16816(acc[mi][ni], Areg[mi], &Breg[ni][2 * (kk & 1)]);
        }
        __syncthreads();
    }

#pragma unroll
    for (int mi = 0; mi < 4; mi++) {
        int r0 = row0 + wm + mi * 16 + (lane >> 2);
#pragma unroll
        for (int ni = 0; ni < 4; ni++) {
            int cc = col0 + wn + ni * 8 + (lane & 3) * 2;
            *(float2*)(C + (size_t)r0 * N + cc)       = make_float2(acc[mi][ni][0], acc[mi][ni][1]);
            *(float2*)(C + (size_t)(r0 + 8) * N + cc) = make_float2(acc[mi][ni][2], acc[mi][ni][3]);
        }
    }
}

// ---------------------------------------------------------------------------
// LayerNorm -> kvc split bf16 ; RoPE(kv[512:640]) -> g_kpe (fp32)
// ---------------------------------------------------------------------------
__global__ void ln_rope_kv_kernel(const float* __restrict__ kvns) {
    int row = blockIdx.x;
    int tid = threadIdx.x;
    const float* x = g_kv + (size_t)row * KVCOLS;
    __shared__ float red[256];

    float v0 = x[tid], v1 = x[tid + 256];
    red[tid] = v0 + v1;
    __syncthreads();
#pragma unroll
    for (int off = 128; off > 0; off >>= 1) {
        if (tid < off) red[tid] += red[tid + off];
        __syncthreads();
    }
    float mean = red[0] * (1.f / 512.f);
    __syncthreads();
    float d0 = v0 - mean, d1 = v1 - mean;
    red[tid] = d0*d0 + d1*d1;
    __syncthreads();
#pragma unroll
    for (int off = 128; off > 0; off >>= 1) {
        if (tid < off) red[tid] += red[tid + off];
        __syncthreads();
    }
    float inv = rsqrtf(red[0] * (1.f / 512.f) + 1e-5f);
    size_t o = (size_t)row * KVR;
    float r0 = d0 * inv * kvns[tid];
    float r1 = d1 * inv * kvns[tid + 256];
    __nv_bfloat16 h0 = __float2bfloat16(r0), h1 = __float2bfloat16(r1);
    g_kvcH[o + tid]       = h0;
    g_kvcH[o + tid + 256] = h1;
    g_kvcL[o + tid]       = __float2bfloat16(r0 - __bfloat162float(h0));
    g_kvcL[o + tid + 256] = __float2bfloat16(r1 - __bfloat162float(h1));

    if (tid < 64) {
        int s = row & (SS_ - 1);
        float c = g_cos[s*64 + tid], sn = g_sin[s*64 + tid];
        float xr = x[KVR + 2*tid], xi = x[KVR + 2*tid + 1];
        g_kpe[(size_t)row*HD + 2*tid]     = xr*c - xi*sn;
        g_kpe[(size_t)row*HD + 2*tid + 1] = xr*sn + xi*c;
    }
}

// ---------------------------------------------------------------------------
// RoPE q_pe + split q -> g_qH/g_qL. grid=ROWS, block=1024 (4 elems/thread)
// ---------------------------------------------------------------------------
__global__ void rope_q_split() {
    int row = blockIdx.x, t = threadIdx.x;
    int c4 = t * 4;
    float4 v = *(const float4*)(g_q + (size_t)row*QCOLS + c4);
    int d = c4 & 255;
    if (d >= 128) {
        int i0 = (d - 128) >> 1;
        int s = row & (SS_ - 1);
        float c0 = g_cos[s*64 + i0],     s0 = g_sin[s*64 + i0];
        float c1 = g_cos[s*64 + i0 + 1], s1 = g_sin[s*64 + i0 + 1];
        float xr = v.x, xi = v.y;
        v.x = xr*c0 - xi*s0; v.y = xr*s0 + xi*c0;
        xr = v.z; xi = v.w;
        v.z = xr*c1 - xi*s1; v.w = xr*s1 + xi*c1;
    }
    __nv_bfloat16 h0 = __float2bfloat16(v.x), h1 = __float2bfloat16(v.y);
    __nv_bfloat16 h2 = __float2bfloat16(v.z), h3 = __float2bfloat16(v.w);
    __nv_bfloat16 hl[4] = {h0, h1, h2, h3};
    __nv_bfloat16 ll[4] = {
        __float2bfloat16(v.x - __bfloat162float(h0)),
        __float2bfloat16(v.y - __bfloat162float(h1)),
        __float2bfloat16(v.z - __bfloat162float(h2)),
        __float2bfloat16(v.w - __bfloat162float(h3))};
    size_t o = (size_t)row*QCOLS + c4;
    *(uint2*)(g_qH + o) = *(uint2*)hl;
    *(uint2*)(g_qL + o) = *(uint2*)ll;
}

// Assemble split K [b][hk][s][256] = concat(k_nope, k_pe)
__global__ void assemble_k_split() {
    size_t idx = (size_t)blockIdx.x * 256 + threadIdx.x;
    int d = (int)(idx & 255);
    size_t t = idx >> 8;
    int s  = (int)(t & (SS_ - 1));
    int hk = (int)((t >> 11) & (KVH - 1));
    int b  = (int)(t >> 14);
    size_t rowbs = (size_t)b*SS_ + s;
    float val;
    if (d < 128) val = g_kvb[rowbs*KVBCOLS + hk*256 + d];
    else         val = g_kpe[rowbs*HD + (d - 128)];
    __nv_bfloat16 hi = __float2bfloat16(val);
    g_kH[idx] = hi;
    g_kL[idx] = __float2bfloat16(val - __bfloat162float(hi));
}

__global__ void assemble_v_split() {
    size_t idx = (size_t)blockIdx.x * 256 + threadIdx.x;
    int c = (int)(idx & 127);
    size_t t = idx >> 7;
    int s  = (int)(t & (SS_ - 1));
    int hk = (int)((t >> 11) & (KVH - 1));
    int b  = (int)(t >> 14);
    float val = g_kvb[((size_t)b*SS_ + s)*KVBCOLS + hk*256 + 128 + c];
    __nv_bfloat16 hi = __float2bfloat16(val);
    g_vH[idx] = hi;
    g_vL[idx] = __float2bfloat16(val - __bfloat162float(hi));
}

// ---------------------------------------------------------------------------
// Tensor-core flash attention, split-bf16 (3-term) for QK^T and PV.
// CTA: 128 q-rows, 8 warps (16 rows each), K-tiles of 32.
// ---------------------------------------------------------------------------
#define FA_QH_OFF 0
#define FA_QL_OFF 67584
#define FA_KH_OFF 135168
#define FA_KL_OFF 152064
#define FA_VH_OFF 168960
#define FA_VL_OFF 177664
#define FA_SMEM   186368
#define QSTB 528   // 264 bf16 row stride (mod 128 = 16 -> conflict-free ldsm)
#define VSTB 272   // 136 bf16 row stride

__global__ void __launch_bounds__(256) fa_kernel() {
    const int tid = threadIdx.x, lane = tid & 31, wid = tid >> 5;
    const int b = blockIdx.x >> 4, h = blockIdx.x & 15, hk = h >> 1;
    const int qt = 15 - (int)blockIdx.y;   // big tiles first
    extern __shared__ char sm[];
    uint32_t sb = smem_u32(sm);

    // Q load (128 rows x 256, hi+lo)
    {
        const __nv_bfloat16* qh = g_qH + ((size_t)(b*SS_ + qt*128))*QCOLS + h*256;
        const __nv_bfloat16* ql = g_qL + ((size_t)(b*SS_ + qt*128))*QCOLS + h*256;
#pragma unroll
        for (int i = 0; i < 16; i++) {
            int idx = tid + i*256, r = idx >> 5, c = idx & 31;
            cp16(sb + FA_QH_OFF + r*QSTB + c*16, qh + (size_t)r*QCOLS + c*8);
            cp16(sb + FA_QL_OFF + r*QSTB + c*16, ql + (size_t)r*QCOLS + c*8);
        }
        cp_commit();
    }

    const int wm = wid * 16;
    float mrow0 = -1e30f, mrow1 = -1e30f;
    float lrow0 = 0.f, lrow1 = 0.f;
    float o[16][4];
#pragma unroll
    for (int nf = 0; nf < 16; nf++)
#pragma unroll
        for (int e = 0; e < 4; e++) o[nf][e] = 0.f;

    const size_t kbase = (size_t)(b*KVH + hk) * SS_;
    const int NKT = 4*qt + 4;
    const float scale = 0.08838834764831845f;

    for (int kt = 0; kt < NKT; kt++) {
        if (kt) __syncthreads();   // previous tile fully consumed
        {
            const __nv_bfloat16* khp = g_kH + (kbase + kt*32)*256;
            const __nv_bfloat16* klp = g_kL + (kbase + kt*32)*256;
#pragma unroll
            for (int i = 0; i < 4; i++) {
                int idx = tid + i*256, r = idx >> 5, c = idx & 31;
                cp16(sb + FA_KH_OFF + r*QSTB + c*16, khp + (size_t)r*256 + c*8);
                cp16(sb + FA_KL_OFF + r*QSTB + c*16, klp + (size_t)r*256 + c*8);
            }
            const __nv_bfloat16* vhp = g_vH + (kbase + kt*32)*128;
            const __nv_bfloat16* vlp = g_vL + (kbase + kt*32)*128;
#pragma unroll
            for (int i = 0; i < 2; i++) {
                int idx = tid + i*256, r = idx >> 4, c = idx & 15;
                cp16(sb + FA_VH_OFF + r*VSTB + c*16, vhp + (size_t)r*128 + c*8);
                cp16(sb + FA_VL_OFF + r*VSTB + c*16, vlp + (size_t)r*128 + c*8);
            }
            cp_commit();
            cp_wait0();
            __syncthreads();
        }

        // ---- S = Q K^T (16x32 per warp, 3 split terms) ----
        float s4[4][4];
#pragma unroll
        for (int f = 0; f < 4; f++)
#pragma unroll
            for (int e = 0; e < 4; e++) s4[f][e] = 0.f;

#pragma unroll
        for (int kc = 0; kc < 16; kc++) {
            uint32_t ah[4], al[4];
            uint32_t aaddr = sb + FA_QH_OFF + (uint32_t)(wm + (lane & 15))*QSTB
                             + (uint32_t)(kc*16 + (lane >> 4)*8)*2;
            ldsm_x4(ah, aaddr);
            ldsm_x4(al, aaddr + (FA_QL_OFF - FA_QH_OFF));
#pragma unroll
            for (int nb = 0; nb < 2; nb++) {
                uint32_t baddr = sb + FA_KH_OFF
                    + (uint32_t)(nb*16 + (lane >> 4)*8 + (lane & 7))*QSTB
                    + (uint32_t)(kc*16 + ((lane >> 3) & 1)*8)*2;
                uint32_t bh[4], bl[4];
                ldsm_x4(bh, baddr);
                ldsm_x4(bl, baddr + (FA_KL_OFF - FA_KH_OFF));
                mma16816(s4[2*nb],   ah, bh); mma16816(s4[2*nb+1], ah, bh+2);
                mma16816(s4[2*nb],   ah, bl); mma16816(s4[2*nb+1], ah, bl+2);
                mma16816(s4[2*nb],   al, bh); mma16816(s4[2*nb+1], al, bh+2);
            }
        }

        // ---- scale + causal mask ----
        if (kt >= 4*qt) {
            int grow0 = qt*128 + wm + (lane >> 2);
#pragma unroll
            for (int f = 0; f < 4; f++)
#pragma unroll
                for (int e = 0; e < 4; e++) {
                    int col = kt*32 + f*8 + (lane & 3)*2 + (e & 1);
                    int row = grow0 + (e >> 1)*8;
                    float v = s4[f][e] * scale;
                    s4[f][e] = (col > row) ? -1e9f : v;
                }
        } else {
#pragma unroll
            for (int f = 0; f < 4; f++)
#pragma unroll
                for (int e = 0; e < 4; e++) s4[f][e] *= scale;
        }

        // ---- online softmax ----
        float rm0 = -1e30f, rm1 = -1e30f;
#pragma unroll
        for (int f = 0; f < 4; f++) {
            rm0 = fmaxf(rm0, fmaxf(s4[f][0], s4[f][1]));
            rm1 = fmaxf(rm1, fmaxf(s4[f][2], s4[f][3]));
        }
        rm0 = fmaxf(rm0, __shfl_xor_sync(0xffffffffu, rm0, 1));
        rm0 = fmaxf(rm0, __shfl_xor_sync(0xffffffffu, rm0, 2));
        rm1 = fmaxf(rm1, __shfl_xor_sync(0xffffffffu, rm1, 1));
        rm1 = fmaxf(rm1, __shfl_xor_sync(0xffffffffu, rm1, 2));
        float mn0 = fmaxf(mrow0, rm0), mn1 = fmaxf(mrow1, rm1);
        float al0 = __expf(mrow0 - mn0), al1 = __expf(mrow1 - mn1);
        float rs0 = 0.f, rs1 = 0.f;
#pragma unroll
        for (int f = 0; f < 4; f++) {
            s4[f][0] = __expf(s4[f][0] - mn0); rs0 += s4[f][0];
            s4[f][1] = __expf(s4[f][1] - mn0); rs0 += s4[f][1];
            s4[f][2] = __expf(s4[f][2] - mn1); rs1 += s4[f][2];
            s4[f][3] = __expf(s4[f][3] - mn1); rs1 += s4[f][3];
        }
        rs0 += __shfl_xor_sync(0xffffffffu, rs0, 1);
        rs0 += __shfl_xor_sync(0xffffffffu, rs0, 2);
        rs1 += __shfl_xor_sync(0xffffffffu, rs1, 1);
        rs1 += __shfl_xor_sync(0xffffffffu, rs1, 2);
        lrow0 = lrow0*al0 + rs0; mrow0 = mn0;
        lrow1 = lrow1*al1 + rs1; mrow1 = mn1;

#pragma unroll
        for (int nf = 0; nf < 16; nf++) {
            o[nf][0] *= al0; o[nf][1] *= al0;
            o[nf][2] *= al1; o[nf][3] *= al1;
        }

        // ---- P fragments (hi/lo) ----
        uint32_t ph[2][4], pl[2][4];
#pragma unroll
        for (int c = 0; c < 2; c++) {
#pragma unroll
            for (int g = 0; g < 2; g++) {
                float p0 = s4[2*c+g][0], p1 = s4[2*c+g][1];
                float p2 = s4[2*c+g][2], p3 = s4[2*c+g][3];
                __nv_bfloat16 h0 = __float2bfloat16(p0), h1 = __float2bfloat16(p1);
                __nv_bfloat16 h2 = __float2bfloat16(p2), h3 = __float2bfloat16(p3);
                ph[c][2*g]   = pack_bf2(h0, h1);
                ph[c][2*g+1] = pack_bf2(h2, h3);
                pl[c][2*g]   = pack_bf2(__float2bfloat16(p0 - __bfloat162float(h0)),
                                        __float2bfloat16(p1 - __bfloat162float(h1)));
                pl[c][2*g+1] = pack_bf2(__float2bfloat16(p2 - __bfloat162float(h2)),
                                        __float2bfloat16(p3 - __bfloat162float(h3)));
            }
        }

        // ---- O += P V (3 split terms) ----
#pragma unroll
        for (int c = 0; c < 2; c++) {
#pragma unroll
            for (int nb = 0; nb < 8; nb++) {
                uint32_t vaddr = sb + FA_VH_OFF
                    + (uint32_t)(c*16 + ((lane >> 3) & 1)*8 + (lane & 7))*VSTB
                    + (uint32_t)(nb*16 + (lane >> 4)*8)*2;
                uint32_t bh[4], bl[4];
                ldsm_x4_t(bh, vaddr);
                ldsm_x4_t(bl, vaddr + (FA_VL_OFF - FA_VH_OFF));
                mma16816(o[2*nb],   ph[c], bh); mma16816(o[2*nb+1], ph[c], bh+2);
                mma16816(o[2*nb],   ph[c], bl); mma16816(o[2*nb+1], ph[c], bl+2);
                mma16816(o[2*nb],   pl[c], bh); mma16816(o[2*nb+1], pl[c], bh+2);
            }
        }
    }

    // ---- epilogue: normalize, stage in SMEM, write split-bf16 ----
    __syncthreads();
    float inv0 = 1.f / lrow0, inv1 = 1.f / lrow1;
    float* st = (float*)sm;   // reuse (128 x 132 floats = 67584 B)
#pragma unroll
    for (int nf = 0; nf < 16; nf++) {
        int c0 = nf*8 + (lane & 3)*2;
        int r0 = wm + (lane >> 2);
        *(float2*)&st[r0*132 + c0]       = make_float2(o[nf][0]*inv0, o[nf][1]*inv0);
        *(float2*)&st[(r0 + 8)*132 + c0] = make_float2(o[nf][2]*inv1, o[nf][3]*inv1);
    }
    __syncthreads();
#pragma unroll
    for (int i = 0; i < 32; i++) {
        int idx = tid + i*256, r = idx >> 6, c = (idx & 63)*2;
        float f0 = st[r*132 + c], f1 = st[r*132 + c + 1];
        size_t off = ((size_t)(b*SS_ + qt*128 + r))*(HH*HD) + h*128 + c;
        __nv_bfloat16 h0 = __float2bfloat16(f0), h1 = __float2bfloat16(f1);
        *(uint32_t*)(g_attnH + off) = pack_bf2(h0, h1);
        *(uint32_t*)(g_attnL + off) = pack_bf2(__float2bfloat16(f0 - __bfloat162float(h0)),
                                               __float2bfloat16(f1 - __bfloat162float(h1)));
    }
}

// ---------------------------------------------------------------------------
extern "C" void kernel_launch(void* const* d_in, const int* in_sizes, int n_in,
                              void* d_out, int out_size) {
    const float* x     = (const float*)d_in[0];
    const float* wq    = (const float*)d_in[1];
    const float* wkv_a = (const float*)d_in[2];
    const float* kvns  = (const float*)d_in[3];
    const float* wkv_b = (const float*)d_in[4];
    const float* wo    = (const float*)d_in[5];
    const int*   pos   = (const int*)d_in[7];
    float* out = (float*)d_out;

    float *q, *kv, *kvb;
    cudaGetSymbolAddress((void**)&q,   g_q);
    cudaGetSymbolAddress((void**)&kv,  g_kv);
    cudaGetSymbolAddress((void**)&kvb, g_kvb);
    __nv_bfloat16 *xH,*xL,*kvcH,*kvcL,*attnH,*attnL;
    cudaGetSymbolAddress((void**)&xH,    g_xH);    cudaGetSymbolAddress((void**)&xL,    g_xL);
    cudaGetSymbolAddress((void**)&kvcH,  g_kvcH);  cudaGetSymbolAddress((void**)&kvcL,  g_kvcL);
    cudaGetSymbolAddress((void**)&attnH, g_attnH); cudaGetSymbolAddress((void**)&attnL, g_attnL);
    __nv_bfloat16 *wqh,*wql,*wah,*wal,*wbh,*wbl,*woh,*wol;
    cudaGetSymbolAddress((void**)&wqh, g_wqT_hi); cudaGetSymbolAddress((void**)&wql, g_wqT_lo);
    cudaGetSymbolAddress((void**)&wah, g_waT_hi); cudaGetSymbolAddress((void**)&wal, g_waT_lo);
    cudaGetSymbolAddress((void**)&wbh, g_wbT_hi); cudaGetSymbolAddress((void**)&wbl, g_wbT_lo);
    cudaGetSymbolAddress((void**)&woh, g_woT_hi); cudaGetSymbolAddress((void**)&wol, g_woT_lo);

    cudaFuncSetAttribute(mma_gemm, cudaFuncAttributeMaxDynamicSharedMemorySize, GEMM_SMEM);
    cudaFuncSetAttribute(fa_kernel, cudaFuncAttributeMaxDynamicSharedMemorySize, FA_SMEM);

    trig_kernel<<<SS_, 64>>>(pos);

    // weight transpose + split
    transpose_cvt<<<dim3(QCOLS/32,  DD/32),  256>>>(wq,    wqh, wql, DD,  QCOLS);
    transpose_cvt<<<dim3(KVCOLS/32, DD/32),  256>>>(wkv_a, wah, wal, DD,  KVCOLS);
    transpose_cvt<<<dim3(KVBCOLS/32,KVR/32), 256>>>(wkv_b, wbh, wbl, KVR, KVBCOLS);
    transpose_cvt<<<dim3(DD/32, (HH*HD)/32), 256>>>(wo,    woh, wol, HH*HD, DD);

    // x -> split bf16
    cvt_split<<<((size_t)ROWS*DD)/1024, 256>>>(x, xH, xL);

    // q = x @ wq
    mma_gemm<<<dim3(QCOLS/128, ROWS/128), 256, GEMM_SMEM>>>(xH, xL, wqh, wql, q, ROWS, QCOLS, DD);
    // kv = x @ wkv_a
    mma_gemm<<<dim3(KVCOLS/128, ROWS/128), 256, GEMM_SMEM>>>(xH, xL, wah, wal, kv, ROWS, KVCOLS, DD);
    // layernorm (-> kvc split) + k_pe rope
    ln_rope_kv_kernel<<<ROWS, 256>>>(kvns);
    // kvb = kv_c @ wkv_b
    mma_gemm<<<dim3(KVBCOLS/128, ROWS/128), 256, GEMM_SMEM>>>(kvcH, kvcL, wbh, wbl, kvb, ROWS, KVBCOLS, KVR);
    // rope q_pe + split q
    rope_q_split<<<ROWS, 1024>>>();
    // assemble split K/V head-major
    assemble_k_split<<<(BB*KVH*SS_*256)/256, 256>>>();
    assemble_v_split<<<(BB*KVH*SS_*128)/256, 256>>>();
    // tensor-core flash attention (writes attn split directly)
    fa_kernel<<<dim3(BB*HH, SS_/128), 256, FA_SMEM>>>();
    // out = attn @ wo
    mma_gemm<<<dim3(DD/128, ROWS/128), 256, GEMM_SMEM>>>(attnH, attnL, woh, wol, out, ROWS, DD, HH*HD);
}

// round 7
// speedup vs baseline: 3.3393x; 1.0076x over previous
#include <cuda_runtime.h>
#include <cuda_bf16.h>
#include <math.h>
#include <cstdint>

// Problem constants
#define BB 2
#define SS_ 2048
#define DD 2048
#define HH 16
#define KVH 8
#define HD 128
#define KVR 512
#define ROWS (BB*SS_)          // 4096
#define QCOLS (HH*2*HD)        // 4096
#define KVCOLS (KVR+HD)        // 640
#define KVBCOLS (KVH*2*HD)     // 2048

// fp32 scratch
__device__ float g_kv  [(size_t)ROWS*KVCOLS];
__device__ float g_cos [SS_*64];
__device__ float g_sin [SS_*64];

// split-bf16 activations
__device__ __nv_bfloat16 g_xH   [(size_t)ROWS*DD];
__device__ __nv_bfloat16 g_xL   [(size_t)ROWS*DD];
__device__ __nv_bfloat16 g_kvcH [(size_t)ROWS*KVR];
__device__ __nv_bfloat16 g_kvcL [(size_t)ROWS*KVR];
__device__ __nv_bfloat16 g_attnH[(size_t)ROWS*(HH*HD)];
__device__ __nv_bfloat16 g_attnL[(size_t)ROWS*(HH*HD)];
__device__ __nv_bfloat16 g_qH   [(size_t)ROWS*QCOLS];
__device__ __nv_bfloat16 g_qL   [(size_t)ROWS*QCOLS];
__device__ __nv_bfloat16 g_kH   [(size_t)BB*KVH*SS_*256];
__device__ __nv_bfloat16 g_kL   [(size_t)BB*KVH*SS_*256];
__device__ __nv_bfloat16 g_vH   [(size_t)BB*KVH*SS_*128];
__device__ __nv_bfloat16 g_vL   [(size_t)BB*KVH*SS_*128];

// transposed split-bf16 weights  WT[n][k]
__device__ __nv_bfloat16 g_wqT_hi[(size_t)QCOLS*DD];
__device__ __nv_bfloat16 g_wqT_lo[(size_t)QCOLS*DD];
__device__ __nv_bfloat16 g_waT_hi[(size_t)KVCOLS*DD];
__device__ __nv_bfloat16 g_waT_lo[(size_t)KVCOLS*DD];
__device__ __nv_bfloat16 g_wbT_hi[(size_t)KVBCOLS*KVR];
__device__ __nv_bfloat16 g_wbT_lo[(size_t)KVBCOLS*KVR];
__device__ __nv_bfloat16 g_woT_hi[(size_t)DD*(HH*HD)];
__device__ __nv_bfloat16 g_woT_lo[(size_t)DD*(HH*HD)];

// ---------------------------------------------------------------------------
// helpers
// ---------------------------------------------------------------------------
__device__ __forceinline__ uint32_t smem_u32(const void* p) {
    uint32_t a;
    asm("{ .reg .u64 t; cvta.to.shared.u64 t, %1; cvt.u32.u64 %0, t; }"
        : "=r"(a) : "l"(p));
    return a;
}
#define SWZ(o) ((o) ^ (((o) >> 3) & 0x70))

__device__ __forceinline__ void cp16(uint32_t dst, const void* src) {
    asm volatile("cp.async.cg.shared.global [%0], [%1], 16;" :: "r"(dst), "l"(src));
}
__device__ __forceinline__ void cp_commit() {
    asm volatile("cp.async.commit_group;" ::: "memory");
}
__device__ __forceinline__ void cp_wait1() {
    asm volatile("cp.async.wait_group 1;" ::: "memory");
}
__device__ __forceinline__ void cp_wait2() {
    asm volatile("cp.async.wait_group 2;" ::: "memory");
}
__device__ __forceinline__ void ldsm_x4(uint32_t (&r)[4], uint32_t addr) {
    asm volatile("ldmatrix.sync.aligned.m8n8.x4.shared.b16 {%0,%1,%2,%3}, [%4];"
                 : "=r"(r[0]), "=r"(r[1]), "=r"(r[2]), "=r"(r[3]) : "r"(addr));
}
__device__ __forceinline__ void ldsm_x4_t(uint32_t (&r)[4], uint32_t addr) {
    asm volatile("ldmatrix.sync.aligned.m8n8.x4.trans.shared.b16 {%0,%1,%2,%3}, [%4];"
                 : "=r"(r[0]), "=r"(r[1]), "=r"(r[2]), "=r"(r[3]) : "r"(addr));
}
__device__ __forceinline__ void mma16816(float* d, const uint32_t* a, const uint32_t* b) {
    asm volatile(
        "mma.sync.aligned.m16n8k16.row.col.f32.bf16.bf16.f32 "
        "{%0,%1,%2,%3},{%4,%5,%6,%7},{%8,%9},{%0,%1,%2,%3};"
        : "+f"(d[0]), "+f"(d[1]), "+f"(d[2]), "+f"(d[3])
        : "r"(a[0]), "r"(a[1]), "r"(a[2]), "r"(a[3]), "r"(b[0]), "r"(b[1]));
}
__device__ __forceinline__ uint32_t pack_bf2(__nv_bfloat16 a, __nv_bfloat16 b) {
    uint16_t ua = __bfloat16_as_ushort(a), ub = __bfloat16_as_ushort(b);
    return (uint32_t)ua | ((uint32_t)ub << 16);
}
__device__ __forceinline__ void split_pair(float f0, float f1, uint32_t& hi, uint32_t& lo) {
    __nv_bfloat16 h0 = __float2bfloat16(f0), h1 = __float2bfloat16(f1);
    hi = pack_bf2(h0, h1);
    lo = pack_bf2(__float2bfloat16(f0 - __bfloat162float(h0)),
                  __float2bfloat16(f1 - __bfloat162float(h1)));
}

// ---------------------------------------------------------------------------
// Trig table (fp64 freqs to match JAX fp32 pow exactly)
// ---------------------------------------------------------------------------
__global__ void trig_kernel(const int* __restrict__ pos_ids) {
    int s = blockIdx.x;
    int i = threadIdx.x;
    double freq = 40.0 * pow(10000.0, -((double)(2*i)) / 128.0);
    float ang = (float)pos_ids[s] * (float)freq;
    g_cos[s*64 + i] = (float)cos((double)ang);
    g_sin[s*64 + i] = (float)sin((double)ang);
}

// ---------------------------------------------------------------------------
// elementwise fp32 -> split bf16 (hi, lo)
// ---------------------------------------------------------------------------
__global__ void cvt_split(const float* __restrict__ X,
                          __nv_bfloat16* __restrict__ H,
                          __nv_bfloat16* __restrict__ L) {
    size_t i = ((size_t)blockIdx.x * 256 + threadIdx.x) * 4;
    float4 v = *(const float4*)(X + i);
    uint32_t h0, l0, h1, l1;
    split_pair(v.x, v.y, h0, l0);
    split_pair(v.z, v.w, h1, l1);
    *(uint2*)(H + i) = make_uint2(h0, h1);
    *(uint2*)(L + i) = make_uint2(l0, l1);
}

// ---------------------------------------------------------------------------
// Weight transpose + split-bf16 convert: W[K][N] -> Thi/Tlo [N][K]
// ---------------------------------------------------------------------------
__global__ void transpose_cvt(const float* __restrict__ W,
                              __nv_bfloat16* __restrict__ Thi,
                              __nv_bfloat16* __restrict__ Tlo, int K, int N) {
    __shared__ float ts[32][33];
    int k0 = blockIdx.y * 32, n0 = blockIdx.x * 32;
    int tx = threadIdx.x & 31, ty = threadIdx.x >> 5;  // 32x8
#pragma unroll
    for (int i = 0; i < 4; i++)
        ts[ty + 8*i][tx] = W[(size_t)(k0 + ty + 8*i)*N + n0 + tx];
    __syncthreads();
#pragma unroll
    for (int i = 0; i < 4; i++) {
        int n = ty + 8*i;
        float v = ts[tx][n];
        __nv_bfloat16 hi = __float2bfloat16(v);
        __nv_bfloat16 lo = __float2bfloat16(v - __bfloat162float(hi));
        size_t o = (size_t)(n0 + n)*K + k0 + tx;
        Thi[o] = hi; Tlo[o] = lo;
    }
}

// ---------------------------------------------------------------------------
// Split-precision bf16 GEMM via mma.sync, 3-stage cp.async pipeline.
// MODE 0: C fp32.  MODE 1: rope(q_pe) + split -> OH/OL (qH/qL).
// MODE 2: scatter split k_nope -> OH/OL, v -> O2H/O2L (head-major).
// ---------------------------------------------------------------------------
#define GEMM_SMEM (3*32768)   // 96 KB

template<int MODE>
__global__ void __launch_bounds__(256)
mma_gemm_t(const __nv_bfloat16* __restrict__ Ahi, const __nv_bfloat16* __restrict__ Alo,
           const __nv_bfloat16* __restrict__ Bhi, const __nv_bfloat16* __restrict__ Blo,
           float* __restrict__ C,
           __nv_bfloat16* __restrict__ OH, __nv_bfloat16* __restrict__ OL,
           __nv_bfloat16* __restrict__ O2H, __nv_bfloat16* __restrict__ O2L,
           int M, int N, int K) {
    extern __shared__ char sm[];
    uint32_t sb = smem_u32(sm);
    const int tid = threadIdx.x, lane = tid & 31, wid = tid >> 5;
    const int row0 = blockIdx.y * 128, col0 = blockIdx.x * 128;
    const int wm = (wid >> 2) * 64, wn = (wid & 3) * 32;
    const int cps = K >> 6;
    const int NC = 3 * cps;

    float acc[4][4][4];
#pragma unroll
    for (int mi = 0; mi < 4; mi++)
#pragma unroll
        for (int ni = 0; ni < 4; ni++)
#pragma unroll
            for (int r = 0; r < 4; r++) acc[mi][ni][r] = 0.f;

    auto load_chunk = [&](int c, int buf) {
        int cc = c, sec = 0;
        if (cc >= cps) { sec = 1; cc -= cps; }
        if (cc >= cps) { sec = 2; cc -= cps; }
        const __nv_bfloat16* gA = ((sec == 2) ? Alo : Ahi) + (size_t)row0 * K + cc * 64;
        const __nv_bfloat16* gB = ((sec == 1) ? Blo : Bhi) + (size_t)col0 * K + cc * 64;
        uint32_t base = sb + (uint32_t)buf * 32768;
#pragma unroll
        for (int i = 0; i < 4; i++) {
            int idx = tid + i * 256;
            int r = idx >> 3, s = idx & 7;
            cp16(base + SWZ((uint32_t)(r * 128 + s * 16)), gA + (size_t)r * K + s * 8);
        }
#pragma unroll
        for (int i = 0; i < 4; i++) {
            int idx = tid + i * 256;
            int r = idx >> 3, s = idx & 7;
            cp16(base + 16384 + SWZ((uint32_t)(r * 128 + s * 16)), gB + (size_t)r * K + s * 8);
        }
    };

    load_chunk(0, 0); cp_commit();
    load_chunk(1, 1); cp_commit();

    for (int c = 0; c < NC; c++) {
        if (c + 2 < NC) {
            int b3 = (c + 2) % 3;
            load_chunk(c + 2, b3);
        }
        cp_commit();
        cp_wait2();
        __syncthreads();

        uint32_t sA = sb + (uint32_t)(c % 3) * 32768;
        uint32_t sB = sA + 16384;
        uint32_t Breg[4][4];
#pragma unroll
        for (int kk = 0; kk < 4; kk++) {
            if ((kk & 1) == 0) {
                int kh = kk >> 1;
#pragma unroll
                for (int ni = 0; ni < 4; ni++) {
                    uint32_t addr = sB + SWZ((uint32_t)((wn + ni*8 + (lane & 7)) * 128
                                                        + kh*64 + (lane >> 3) * 16));
                    ldsm_x4(Breg[ni], addr);
                }
            }
            uint32_t Areg[4][4];
#pragma unroll
            for (int mi = 0; mi < 4; mi++) {
                uint32_t addr = sA + SWZ((uint32_t)((wm + mi*16 + (lane & 15)) * 128
                                                    + kk*32 + (lane >> 4) * 16));
                ldsm_x4(Areg[mi], addr);
            }
#pragma unroll
            for (int mi = 0; mi < 4; mi++)
#pragma unroll
                for (int ni = 0; ni < 4; ni++)
                    mma16816(acc[mi][ni], Areg[mi], &Breg[ni][2 * (kk & 1)]);
        }
        __syncthreads();
    }

    // epilogue
#pragma unroll
    for (int mi = 0; mi < 4; mi++) {
        int r0 = row0 + wm + mi * 16 + (lane >> 2);
#pragma unroll
        for (int ni = 0; ni < 4; ni++) {
            int cc = col0 + wn + ni * 8 + (lane & 3) * 2;
            float a0 = acc[mi][ni][0], a1 = acc[mi][ni][1];
            float a2 = acc[mi][ni][2], a3 = acc[mi][ni][3];
            if (MODE == 0) {
                *(float2*)(C + (size_t)r0 * N + cc)       = make_float2(a0, a1);
                *(float2*)(C + (size_t)(r0 + 8) * N + cc) = make_float2(a2, a3);
            } else if (MODE == 1) {
                int d = cc & 255;
                if (d >= 128) {
                    int i = (d - 128) >> 1;
                    int s0 = r0 & (SS_-1), s1 = (r0 + 8) & (SS_-1);
                    float c0 = g_cos[s0*64 + i], sn0 = g_sin[s0*64 + i];
                    float c1 = g_cos[s1*64 + i], sn1 = g_sin[s1*64 + i];
                    float xr = a0, xi = a1;
                    a0 = xr*c0 - xi*sn0; a1 = xr*sn0 + xi*c0;
                    xr = a2; xi = a3;
                    a2 = xr*c1 - xi*sn1; a3 = xr*sn1 + xi*c1;
                }
                uint32_t h0, l0, h1, l1;
                split_pair(a0, a1, h0, l0);
                split_pair(a2, a3, h1, l1);
                size_t o0 = (size_t)r0 * N + cc, o1 = (size_t)(r0 + 8) * N + cc;
                *(uint32_t*)(OH + o0) = h0; *(uint32_t*)(OL + o0) = l0;
                *(uint32_t*)(OH + o1) = h1; *(uint32_t*)(OL + o1) = l1;
            } else {
                int hk = cc >> 8, d = cc & 255;
                uint32_t h0, l0, h1, l1;
                split_pair(a0, a1, h0, l0);
                split_pair(a2, a3, h1, l1);
                int b0 = r0 >> 11, s0 = r0 & (SS_-1);
                int b1 = (r0+8) >> 11, s1 = (r0+8) & (SS_-1);
                if (d < 128) {
                    size_t o0 = ((size_t)(b0*KVH + hk)*SS_ + s0)*256 + d;
                    size_t o1 = ((size_t)(b1*KVH + hk)*SS_ + s1)*256 + d;
                    *(uint32_t*)(OH + o0) = h0; *(uint32_t*)(OL + o0) = l0;
                    *(uint32_t*)(OH + o1) = h1; *(uint32_t*)(OL + o1) = l1;
                } else {
                    size_t o0 = ((size_t)(b0*KVH + hk)*SS_ + s0)*128 + (d - 128);
                    size_t o1 = ((size_t)(b1*KVH + hk)*SS_ + s1)*128 + (d - 128);
                    *(uint32_t*)(O2H + o0) = h0; *(uint32_t*)(O2L + o0) = l0;
                    *(uint32_t*)(O2H + o1) = h1; *(uint32_t*)(O2L + o1) = l1;
                }
            }
        }
    }
}

// ---------------------------------------------------------------------------
// LayerNorm -> kvc split ; RoPE(k_pe) -> split, replicated into g_kH/g_kL
// ---------------------------------------------------------------------------
__global__ void ln_rope_kv_kernel(const float* __restrict__ kvns) {
    int row = blockIdx.x;
    int tid = threadIdx.x;
    const float* x = g_kv + (size_t)row * KVCOLS;
    __shared__ float red[256];

    float v0 = x[tid], v1 = x[tid + 256];
    red[tid] = v0 + v1;
    __syncthreads();
#pragma unroll
    for (int off = 128; off > 0; off >>= 1) {
        if (tid < off) red[tid] += red[tid + off];
        __syncthreads();
    }
    float mean = red[0] * (1.f / 512.f);
    __syncthreads();
    float d0 = v0 - mean, d1 = v1 - mean;
    red[tid] = d0*d0 + d1*d1;
    __syncthreads();
#pragma unroll
    for (int off = 128; off > 0; off >>= 1) {
        if (tid < off) red[tid] += red[tid + off];
        __syncthreads();
    }
    float inv = rsqrtf(red[0] * (1.f / 512.f) + 1e-5f);
    size_t o = (size_t)row * KVR;
    float r0 = d0 * inv * kvns[tid];
    float r1 = d1 * inv * kvns[tid + 256];
    __nv_bfloat16 h0 = __float2bfloat16(r0), h1 = __float2bfloat16(r1);
    g_kvcH[o + tid]       = h0;
    g_kvcH[o + tid + 256] = h1;
    g_kvcL[o + tid]       = __float2bfloat16(r0 - __bfloat162float(h0));
    g_kvcL[o + tid + 256] = __float2bfloat16(r1 - __bfloat162float(h1));

    if (tid < 64) {
        int s = row & (SS_ - 1);
        int b = row >> 11;
        float c = g_cos[s*64 + tid], sn = g_sin[s*64 + tid];
        float xr = x[KVR + 2*tid], xi = x[KVR + 2*tid + 1];
        float k0 = xr*c - xi*sn, k1 = xr*sn + xi*c;
        uint32_t hh, ll;
        split_pair(k0, k1, hh, ll);
#pragma unroll
        for (int hk = 0; hk < KVH; hk++) {
            size_t base = ((size_t)(b*KVH + hk)*SS_ + s)*256 + 128 + 2*tid;
            *(uint32_t*)(g_kH + base) = hh;
            *(uint32_t*)(g_kL + base) = ll;
        }
    }
}

// ---------------------------------------------------------------------------
// Tensor-core flash attention, split-bf16, software-pipelined loads.
// CTA: 128 q-rows, 8 warps, K-tiles of 32. K double-buffered, V overlapped.
// ---------------------------------------------------------------------------
#define FA_QH_OFF 0
#define FA_QL_OFF 67584
#define FA_K0_OFF 135168           // two K stages of 33792 (hi 16896 + lo 16896)
#define FA_KSTG   33792
#define FA_V_OFF  202752           // hi 8704 + lo 8704
#define FA_SMEM   220160
#define QSTB 528
#define VSTB 272

__global__ void __launch_bounds__(256) fa_kernel() {
    const int tid = threadIdx.x, lane = tid & 31, wid = tid >> 5;
    const int b = blockIdx.x >> 4, h = blockIdx.x & 15, hk = h >> 1;
    const int qt = 15 - (int)blockIdx.y;   // big tiles first
    extern __shared__ char sm[];
    uint32_t sb = smem_u32(sm);

    const size_t kbase = (size_t)(b*KVH + hk) * SS_;
    const int NKT = 4*qt + 4;

    auto loadK = [&](int kt, int buf) {
        uint32_t kb = sb + FA_K0_OFF + (uint32_t)buf * FA_KSTG;
        const __nv_bfloat16* khp = g_kH + (kbase + kt*32)*256;
        const __nv_bfloat16* klp = g_kL + (kbase + kt*32)*256;
#pragma unroll
        for (int i = 0; i < 4; i++) {
            int idx = tid + i*256, r = idx >> 5, c = idx & 31;
            cp16(kb + r*QSTB + c*16,         khp + (size_t)r*256 + c*8);
            cp16(kb + 16896 + r*QSTB + c*16, klp + (size_t)r*256 + c*8);
        }
    };
    auto loadV = [&](int kt) {
        const __nv_bfloat16* vhp = g_vH + (kbase + kt*32)*128;
        const __nv_bfloat16* vlp = g_vL + (kbase + kt*32)*128;
#pragma unroll
        for (int i = 0; i < 2; i++) {
            int idx = tid + i*256, r = idx >> 4, c = idx & 15;
            cp16(sb + FA_V_OFF + r*VSTB + c*16,        vhp + (size_t)r*128 + c*8);
            cp16(sb + FA_V_OFF + 8704 + r*VSTB + c*16, vlp + (size_t)r*128 + c*8);
        }
    };

    // prologue: Q, K0, V0 (three commit groups)
    {
        const __nv_bfloat16* qh = g_qH + ((size_t)(b*SS_ + qt*128))*QCOLS + h*256;
        const __nv_bfloat16* ql = g_qL + ((size_t)(b*SS_ + qt*128))*QCOLS + h*256;
#pragma unroll
        for (int i = 0; i < 16; i++) {
            int idx = tid + i*256, r = idx >> 5, c = idx & 31;
            cp16(sb + FA_QH_OFF + r*QSTB + c*16, qh + (size_t)r*QCOLS + c*8);
            cp16(sb + FA_QL_OFF + r*QSTB + c*16, ql + (size_t)r*QCOLS + c*8);
        }
        cp_commit();
    }
    loadK(0, 0); cp_commit();
    loadV(0);    cp_commit();

    const int wm = wid * 16;
    float mrow0 = -1e30f, mrow1 = -1e30f;
    float lrow0 = 0.f, lrow1 = 0.f;
    float o[16][4];
#pragma unroll
    for (int nf = 0; nf < 16; nf++)
#pragma unroll
        for (int e = 0; e < 4; e++) o[nf][e] = 0.f;

    const float scale = 0.08838834764831845f;

    for (int kt = 0; kt < NKT; kt++) {
        // K(kt) (+Q on first iter) ready; V(kt) may still be in flight
        cp_wait1();
        __syncthreads();
        if (kt + 1 < NKT) loadK(kt + 1, (kt + 1) & 1);
        cp_commit();

        uint32_t kbuf = sb + FA_K0_OFF + (uint32_t)(kt & 1) * FA_KSTG;

        // ---- S = Q K^T (3 split terms) ----
        float s4[4][4];
#pragma unroll
        for (int f = 0; f < 4; f++)
#pragma unroll
            for (int e = 0; e < 4; e++) s4[f][e] = 0.f;

#pragma unroll
        for (int kc = 0; kc < 16; kc++) {
            uint32_t ah[4], al[4];
            uint32_t aaddr = sb + FA_QH_OFF + (uint32_t)(wm + (lane & 15))*QSTB
                             + (uint32_t)(kc*16 + (lane >> 4)*8)*2;
            ldsm_x4(ah, aaddr);
            ldsm_x4(al, aaddr + (FA_QL_OFF - FA_QH_OFF));
#pragma unroll
            for (int nb = 0; nb < 2; nb++) {
                uint32_t baddr = kbuf
                    + (uint32_t)(nb*16 + (lane >> 4)*8 + (lane & 7))*QSTB
                    + (uint32_t)(kc*16 + ((lane >> 3) & 1)*8)*2;
                uint32_t bh[4], bl[4];
                ldsm_x4(bh, baddr);
                ldsm_x4(bl, baddr + 16896);
                mma16816(s4[2*nb],   ah, bh); mma16816(s4[2*nb+1], ah, bh+2);
                mma16816(s4[2*nb],   ah, bl); mma16816(s4[2*nb+1], ah, bl+2);
                mma16816(s4[2*nb],   al, bh); mma16816(s4[2*nb+1], al, bh+2);
            }
        }

        // ---- scale + causal mask ----
        if (kt >= 4*qt) {
            int grow0 = qt*128 + wm + (lane >> 2);
#pragma unroll
            for (int f = 0; f < 4; f++)
#pragma unroll
                for (int e = 0; e < 4; e++) {
                    int col = kt*32 + f*8 + (lane & 3)*2 + (e & 1);
                    int row = grow0 + (e >> 1)*8;
                    float v = s4[f][e] * scale;
                    s4[f][e] = (col > row) ? -1e9f : v;
                }
        } else {
#pragma unroll
            for (int f = 0; f < 4; f++)
#pragma unroll
                for (int e = 0; e < 4; e++) s4[f][e] *= scale;
        }

        // ---- online softmax ----
        float rm0 = -1e30f, rm1 = -1e30f;
#pragma unroll
        for (int f = 0; f < 4; f++) {
            rm0 = fmaxf(rm0, fmaxf(s4[f][0], s4[f][1]));
            rm1 = fmaxf(rm1, fmaxf(s4[f][2], s4[f][3]));
        }
        rm0 = fmaxf(rm0, __shfl_xor_sync(0xffffffffu, rm0, 1));
        rm0 = fmaxf(rm0, __shfl_xor_sync(0xffffffffu, rm0, 2));
        rm1 = fmaxf(rm1, __shfl_xor_sync(0xffffffffu, rm1, 1));
        rm1 = fmaxf(rm1, __shfl_xor_sync(0xffffffffu, rm1, 2));
        float mn0 = fmaxf(mrow0, rm0), mn1 = fmaxf(mrow1, rm1);
        float al0 = __expf(mrow0 - mn0), al1 = __expf(mrow1 - mn1);
        float rs0 = 0.f, rs1 = 0.f;
#pragma unroll
        for (int f = 0; f < 4; f++) {
            s4[f][0] = __expf(s4[f][0] - mn0); rs0 += s4[f][0];
            s4[f][1] = __expf(s4[f][1] - mn0); rs0 += s4[f][1];
            s4[f][2] = __expf(s4[f][2] - mn1); rs1 += s4[f][2];
            s4[f][3] = __expf(s4[f][3] - mn1); rs1 += s4[f][3];
        }
        rs0 += __shfl_xor_sync(0xffffffffu, rs0, 1);
        rs0 += __shfl_xor_sync(0xffffffffu, rs0, 2);
        rs1 += __shfl_xor_sync(0xffffffffu, rs1, 1);
        rs1 += __shfl_xor_sync(0xffffffffu, rs1, 2);
        lrow0 = lrow0*al0 + rs0; mrow0 = mn0;
        lrow1 = lrow1*al1 + rs1; mrow1 = mn1;

#pragma unroll
        for (int nf = 0; nf < 16; nf++) {
            o[nf][0] *= al0; o[nf][1] *= al0;
            o[nf][2] *= al1; o[nf][3] *= al1;
        }

        // ---- P fragments (hi/lo) ----
        uint32_t ph[2][4], pl[2][4];
#pragma unroll
        for (int c = 0; c < 2; c++) {
#pragma unroll
            for (int g = 0; g < 2; g++) {
                split_pair(s4[2*c+g][0], s4[2*c+g][1], ph[c][2*g],   pl[c][2*g]);
                split_pair(s4[2*c+g][2], s4[2*c+g][3], ph[c][2*g+1], pl[c][2*g+1]);
            }
        }

        // V(kt) ready; K(kt+1) may still be in flight
        cp_wait1();
        __syncthreads();

        // ---- O += P V (3 split terms) ----
#pragma unroll
        for (int c = 0; c < 2; c++) {
#pragma unroll
            for (int nb = 0; nb < 8; nb++) {
                uint32_t vaddr = sb + FA_V_OFF
                    + (uint32_t)(c*16 + ((lane >> 3) & 1)*8 + (lane & 7))*VSTB
                    + (uint32_t)(nb*16 + (lane >> 4)*8)*2;
                uint32_t bh[4], bl[4];
                ldsm_x4_t(bh, vaddr);
                ldsm_x4_t(bl, vaddr + 8704);
                mma16816(o[2*nb],   ph[c], bh); mma16816(o[2*nb+1], ph[c], bh+2);
                mma16816(o[2*nb],   ph[c], bl); mma16816(o[2*nb+1], ph[c], bl+2);
                mma16816(o[2*nb],   pl[c], bh); mma16816(o[2*nb+1], pl[c], bh+2);
            }
        }

        __syncthreads();                 // all warps done reading V buffer
        if (kt + 1 < NKT) loadV(kt + 1);
        cp_commit();
    }

    // ---- epilogue: normalize, stage in SMEM, write split-bf16 ----
    __syncthreads();
    float inv0 = 1.f / lrow0, inv1 = 1.f / lrow1;
    float* st = (float*)sm;   // reuse Q area (128 x 132 floats = 67584 B)
#pragma unroll
    for (int nf = 0; nf < 16; nf++) {
        int c0 = nf*8 + (lane & 3)*2;
        int r0 = wm + (lane >> 2);
        *(float2*)&st[r0*132 + c0]       = make_float2(o[nf][0]*inv0, o[nf][1]*inv0);
        *(float2*)&st[(r0 + 8)*132 + c0] = make_float2(o[nf][2]*inv1, o[nf][3]*inv1);
    }
    __syncthreads();
#pragma unroll
    for (int i = 0; i < 32; i++) {
        int idx = tid + i*256, r = idx >> 6, c = (idx & 63)*2;
        float f0 = st[r*132 + c], f1 = st[r*132 + c + 1];
        size_t off = ((size_t)(b*SS_ + qt*128 + r))*(HH*HD) + h*128 + c;
        uint32_t hh, ll;
        split_pair(f0, f1, hh, ll);
        *(uint32_t*)(g_attnH + off) = hh;
        *(uint32_t*)(g_attnL + off) = ll;
    }
}

// ---------------------------------------------------------------------------
extern "C" void kernel_launch(void* const* d_in, const int* in_sizes, int n_in,
                              void* d_out, int out_size) {
    const float* x     = (const float*)d_in[0];
    const float* wq    = (const float*)d_in[1];
    const float* wkv_a = (const float*)d_in[2];
    const float* kvns  = (const float*)d_in[3];
    const float* wkv_b = (const float*)d_in[4];
    const float* wo    = (const float*)d_in[5];
    const int*   pos   = (const int*)d_in[7];
    float* out = (float*)d_out;

    float *kv;
    cudaGetSymbolAddress((void**)&kv, g_kv);
    __nv_bfloat16 *xH,*xL,*kvcH,*kvcL,*attnH,*attnL,*qH,*qL,*kH,*kL,*vH,*vL;
    cudaGetSymbolAddress((void**)&xH,    g_xH);    cudaGetSymbolAddress((void**)&xL,    g_xL);
    cudaGetSymbolAddress((void**)&kvcH,  g_kvcH);  cudaGetSymbolAddress((void**)&kvcL,  g_kvcL);
    cudaGetSymbolAddress((void**)&attnH, g_attnH); cudaGetSymbolAddress((void**)&attnL, g_attnL);
    cudaGetSymbolAddress((void**)&qH,    g_qH);    cudaGetSymbolAddress((void**)&qL,    g_qL);
    cudaGetSymbolAddress((void**)&kH,    g_kH);    cudaGetSymbolAddress((void**)&kL,    g_kL);
    cudaGetSymbolAddress((void**)&vH,    g_vH);    cudaGetSymbolAddress((void**)&vL,    g_vL);
    __nv_bfloat16 *wqh,*wql,*wah,*wal,*wbh,*wbl,*woh,*wol;
    cudaGetSymbolAddress((void**)&wqh, g_wqT_hi); cudaGetSymbolAddress((void**)&wql, g_wqT_lo);
    cudaGetSymbolAddress((void**)&wah, g_waT_hi); cudaGetSymbolAddress((void**)&wal, g_waT_lo);
    cudaGetSymbolAddress((void**)&wbh, g_wbT_hi); cudaGetSymbolAddress((void**)&wbl, g_wbT_lo);
    cudaGetSymbolAddress((void**)&woh, g_woT_hi); cudaGetSymbolAddress((void**)&wol, g_woT_lo);

    cudaFuncSetAttribute(mma_gemm_t<0>, cudaFuncAttributeMaxDynamicSharedMemorySize, GEMM_SMEM);
    cudaFuncSetAttribute(mma_gemm_t<1>, cudaFuncAttributeMaxDynamicSharedMemorySize, GEMM_SMEM);
    cudaFuncSetAttribute(mma_gemm_t<2>, cudaFuncAttributeMaxDynamicSharedMemorySize, GEMM_SMEM);
    cudaFuncSetAttribute(fa_kernel, cudaFuncAttributeMaxDynamicSharedMemorySize, FA_SMEM);

    trig_kernel<<<SS_, 64>>>(pos);

    // weight transpose + split
    transpose_cvt<<<dim3(QCOLS/32,  DD/32),  256>>>(wq,    wqh, wql, DD,  QCOLS);
    transpose_cvt<<<dim3(KVCOLS/32, DD/32),  256>>>(wkv_a, wah, wal, DD,  KVCOLS);
    transpose_cvt<<<dim3(KVBCOLS/32,KVR/32), 256>>>(wkv_b, wbh, wbl, KVR, KVBCOLS);
    transpose_cvt<<<dim3(DD/32, (HH*HD)/32), 256>>>(wo,    woh, wol, HH*HD, DD);

    // x -> split bf16
    cvt_split<<<((size_t)ROWS*DD)/1024, 256>>>(x, xH, xL);

    // q = rope(x @ wq) -> qH/qL (fused epilogue)
    mma_gemm_t<1><<<dim3(QCOLS/128, ROWS/128), 256, GEMM_SMEM>>>(
        xH, xL, wqh, wql, nullptr, qH, qL, nullptr, nullptr, ROWS, QCOLS, DD);
    // kv = x @ wkv_a (fp32, feeds layernorm)
    mma_gemm_t<0><<<dim3(KVCOLS/128, ROWS/128), 256, GEMM_SMEM>>>(
        xH, xL, wah, wal, kv, nullptr, nullptr, nullptr, nullptr, ROWS, KVCOLS, DD);
    // layernorm -> kvc split ; roped k_pe -> g_kH/g_kL (replicated)
    ln_rope_kv_kernel<<<ROWS, 256>>>(kvns);
    // kvb = kv_c @ wkv_b -> scatter split k_nope/v head-major (fused epilogue)
    mma_gemm_t<2><<<dim3(KVBCOLS/128, ROWS/128), 256, GEMM_SMEM>>>(
        kvcH, kvcL, wbh, wbl, nullptr, kH, kL, vH, vL, ROWS, KVBCOLS, KVR);
    // tensor-core flash attention (writes attn split directly)
    fa_kernel<<<dim3(BB*HH, SS_/128), 256, FA_SMEM>>>();
    // out = attn @ wo
    mma_gemm_t<0><<<dim3(DD/128, ROWS/128), 256, GEMM_SMEM>>>(
        attnH, attnL, woh, wol, out, nullptr, nullptr, nullptr, nullptr, ROWS, DD, HH*HD);
}

// round 8
// speedup vs baseline: 4.7931x; 1.4353x over previous
#include <cuda_runtime.h>
#include <cuda_fp16.h>
#include <math.h>
#include <cstdint>

// Problem constants
#define BB 2
#define SS_ 2048
#define DD 2048
#define HH 16
#define KVH 8
#define HD 128
#define KVR 512
#define ROWS (BB*SS_)          // 4096
#define QCOLS (HH*2*HD)        // 4096
#define KVCOLS (KVR+HD)        // 640
#define NQA (QCOLS+KVCOLS)     // 4736
#define KVBCOLS (KVH*2*HD)     // 2048

// fp32 scratch
__device__ float g_kv  [(size_t)ROWS*KVCOLS];
__device__ float g_cos [SS_*64];
__device__ float g_sin [SS_*64];

// fp16 activations: A-side single, B-side split
__device__ __half g_xH   [(size_t)ROWS*DD];
__device__ __half g_kvcH [(size_t)ROWS*KVR];
__device__ __half g_attnH[(size_t)ROWS*(HH*HD)];
__device__ __half g_qH   [(size_t)ROWS*QCOLS];
__device__ __half g_qL   [(size_t)ROWS*QCOLS];
__device__ __half g_kH   [(size_t)BB*KVH*SS_*256];
__device__ __half g_kL   [(size_t)BB*KVH*SS_*256];
__device__ __half g_vH   [(size_t)BB*KVH*SS_*128];
__device__ __half g_vL   [(size_t)BB*KVH*SS_*128];

// transposed split-fp16 weights  WT[n][k]
__device__ __half g_wqaT_hi[(size_t)NQA*DD];      // wq (n<4096) ++ wkv_a (n>=4096)
__device__ __half g_wqaT_lo[(size_t)NQA*DD];
__device__ __half g_wbT_hi[(size_t)KVBCOLS*KVR];
__device__ __half g_wbT_lo[(size_t)KVBCOLS*KVR];
__device__ __half g_woT_hi[(size_t)DD*(HH*HD)];
__device__ __half g_woT_lo[(size_t)DD*(HH*HD)];

// ---------------------------------------------------------------------------
// helpers
// ---------------------------------------------------------------------------
__device__ __forceinline__ uint32_t smem_u32(const void* p) {
    uint32_t a;
    asm("{ .reg .u64 t; cvta.to.shared.u64 t, %1; cvt.u32.u64 %0, t; }"
        : "=r"(a) : "l"(p));
    return a;
}
#define SWZ(o) ((o) ^ (((o) >> 3) & 0x70))

__device__ __forceinline__ void cp16(uint32_t dst, const void* src) {
    asm volatile("cp.async.cg.shared.global [%0], [%1], 16;" :: "r"(dst), "l"(src));
}
__device__ __forceinline__ void cp_commit() {
    asm volatile("cp.async.commit_group;" ::: "memory");
}
__device__ __forceinline__ void cp_wait1() {
    asm volatile("cp.async.wait_group 1;" ::: "memory");
}
__device__ __forceinline__ void cp_wait2() {
    asm volatile("cp.async.wait_group 2;" ::: "memory");
}
__device__ __forceinline__ void ldsm_x4(uint32_t (&r)[4], uint32_t addr) {
    asm volatile("ldmatrix.sync.aligned.m8n8.x4.shared.b16 {%0,%1,%2,%3}, [%4];"
                 : "=r"(r[0]), "=r"(r[1]), "=r"(r[2]), "=r"(r[3]) : "r"(addr));
}
__device__ __forceinline__ void ldsm_x4_t(uint32_t (&r)[4], uint32_t addr) {
    asm volatile("ldmatrix.sync.aligned.m8n8.x4.trans.shared.b16 {%0,%1,%2,%3}, [%4];"
                 : "=r"(r[0]), "=r"(r[1]), "=r"(r[2]), "=r"(r[3]) : "r"(addr));
}
__device__ __forceinline__ void mma16816(float* d, const uint32_t* a, const uint32_t* b) {
    asm volatile(
        "mma.sync.aligned.m16n8k16.row.col.f32.f16.f16.f32 "
        "{%0,%1,%2,%3},{%4,%5,%6,%7},{%8,%9},{%0,%1,%2,%3};"
        : "+f"(d[0]), "+f"(d[1]), "+f"(d[2]), "+f"(d[3])
        : "r"(a[0]), "r"(a[1]), "r"(a[2]), "r"(a[3]), "r"(b[0]), "r"(b[1]));
}
__device__ __forceinline__ uint32_t pack_h2(__half a, __half b) {
    return (uint32_t)__half_as_ushort(a) | ((uint32_t)__half_as_ushort(b) << 16);
}
__device__ __forceinline__ uint32_t pack_single(float f0, float f1) {
    return pack_h2(__float2half_rn(f0), __float2half_rn(f1));
}
__device__ __forceinline__ void split_pair(float f0, float f1, uint32_t& hi, uint32_t& lo) {
    __half h0 = __float2half_rn(f0), h1 = __float2half_rn(f1);
    hi = pack_h2(h0, h1);
    lo = pack_h2(__float2half_rn(f0 - __half2float(h0)),
                 __float2half_rn(f1 - __half2float(h1)));
}

// ---------------------------------------------------------------------------
// Trig table (fp64 freqs to match JAX fp32 pow exactly)
// ---------------------------------------------------------------------------
__global__ void trig_kernel(const int* __restrict__ pos_ids) {
    int s = blockIdx.x;
    int i = threadIdx.x;
    double freq = 40.0 * pow(10000.0, -((double)(2*i)) / 128.0);
    float ang = (float)pos_ids[s] * (float)freq;
    g_cos[s*64 + i] = (float)cos((double)ang);
    g_sin[s*64 + i] = (float)sin((double)ang);
}

// ---------------------------------------------------------------------------
// elementwise fp32 -> single fp16
// ---------------------------------------------------------------------------
__global__ void cvt_half(const float* __restrict__ X, __half* __restrict__ H) {
    size_t i = ((size_t)blockIdx.x * 256 + threadIdx.x) * 4;
    float4 v = *(const float4*)(X + i);
    *(uint2*)(H + i) = make_uint2(pack_single(v.x, v.y), pack_single(v.z, v.w));
}

// ---------------------------------------------------------------------------
// Weight transpose + split-fp16 convert: W[K][N] -> Thi/Tlo [N][K]
// ---------------------------------------------------------------------------
__global__ void transpose_cvt(const float* __restrict__ W,
                              __half* __restrict__ Thi,
                              __half* __restrict__ Tlo, int K, int N) {
    __shared__ float ts[32][33];
    int k0 = blockIdx.y * 32, n0 = blockIdx.x * 32;
    int tx = threadIdx.x & 31, ty = threadIdx.x >> 5;  // 32x8
#pragma unroll
    for (int i = 0; i < 4; i++)
        ts[ty + 8*i][tx] = W[(size_t)(k0 + ty + 8*i)*N + n0 + tx];
    __syncthreads();
#pragma unroll
    for (int i = 0; i < 4; i++) {
        int n = ty + 8*i;
        float v = ts[tx][n];
        __half hi = __float2half_rn(v);
        __half lo = __float2half_rn(v - __half2float(hi));
        size_t o = (size_t)(n0 + n)*K + k0 + tx;
        Thi[o] = hi; Tlo[o] = lo;
    }
}

// ---------------------------------------------------------------------------
// 2-term split GEMM: C = A(fp16 single) @ [Bhi + Blo]^T, 3-stage cp.async.
// MODE 0: C fp32.
// MODE 1: N=NQA; cc<QCOLS: rope(q_pe)+split -> qH/qL; else fp32 -> g_kv.
// MODE 2: scatter split k_nope -> OH/OL, v -> O2H/O2L (head-major).
// ---------------------------------------------------------------------------
#define GEMM_SMEM (3*32768)   // 96 KB

template<int MODE>
__global__ void __launch_bounds__(256)
mma_gemm_t(const __half* __restrict__ A,
           const __half* __restrict__ Bhi, const __half* __restrict__ Blo,
           float* __restrict__ C,
           __half* __restrict__ OH, __half* __restrict__ OL,
           __half* __restrict__ O2H, __half* __restrict__ O2L,
           int M, int N, int K) {
    extern __shared__ char sm[];
    uint32_t sb = smem_u32(sm);
    const int tid = threadIdx.x, lane = tid & 31, wid = tid >> 5;
    const int row0 = blockIdx.y * 128, col0 = blockIdx.x * 128;
    const int wm = (wid >> 2) * 64, wn = (wid & 3) * 32;
    const int cps = K >> 6;
    const int NC = 2 * cps;

    float acc[4][4][4];
#pragma unroll
    for (int mi = 0; mi < 4; mi++)
#pragma unroll
        for (int ni = 0; ni < 4; ni++)
#pragma unroll
            for (int r = 0; r < 4; r++) acc[mi][ni][r] = 0.f;

    auto load_chunk = [&](int c, int buf) {
        int sec = (c >= cps);
        int cc = c - sec * cps;
        const __half* gA = A + (size_t)row0 * K + cc * 64;
        const __half* gB = (sec ? Blo : Bhi) + (size_t)col0 * K + cc * 64;
        uint32_t base = sb + (uint32_t)buf * 32768;
#pragma unroll
        for (int i = 0; i < 4; i++) {
            int idx = tid + i * 256;
            int r = idx >> 3, s = idx & 7;
            cp16(base + SWZ((uint32_t)(r * 128 + s * 16)), gA + (size_t)r * K + s * 8);
        }
#pragma unroll
        for (int i = 0; i < 4; i++) {
            int idx = tid + i * 256;
            int r = idx >> 3, s = idx & 7;
            cp16(base + 16384 + SWZ((uint32_t)(r * 128 + s * 16)), gB + (size_t)r * K + s * 8);
        }
    };

    load_chunk(0, 0); cp_commit();
    load_chunk(1, 1); cp_commit();

    for (int c = 0; c < NC; c++) {
        if (c + 2 < NC) load_chunk(c + 2, (c + 2) % 3);
        cp_commit();
        cp_wait2();
        __syncthreads();

        uint32_t sA = sb + (uint32_t)(c % 3) * 32768;
        uint32_t sB = sA + 16384;
        uint32_t Breg[4][4];
#pragma unroll
        for (int kk = 0; kk < 4; kk++) {
            if ((kk & 1) == 0) {
                int kh = kk >> 1;
#pragma unroll
                for (int ni = 0; ni < 4; ni++) {
                    uint32_t addr = sB + SWZ((uint32_t)((wn + ni*8 + (lane & 7)) * 128
                                                        + kh*64 + (lane >> 3) * 16));
                    ldsm_x4(Breg[ni], addr);
                }
            }
            uint32_t Areg[4][4];
#pragma unroll
            for (int mi = 0; mi < 4; mi++) {
                uint32_t addr = sA + SWZ((uint32_t)((wm + mi*16 + (lane & 15)) * 128
                                                    + kk*32 + (lane >> 4) * 16));
                ldsm_x4(Areg[mi], addr);
            }
#pragma unroll
            for (int mi = 0; mi < 4; mi++)
#pragma unroll
                for (int ni = 0; ni < 4; ni++)
                    mma16816(acc[mi][ni], Areg[mi], &Breg[ni][2 * (kk & 1)]);
        }
        __syncthreads();
    }

    // epilogue
#pragma unroll
    for (int mi = 0; mi < 4; mi++) {
        int r0 = row0 + wm + mi * 16 + (lane >> 2);
#pragma unroll
        for (int ni = 0; ni < 4; ni++) {
            int cc = col0 + wn + ni * 8 + (lane & 3) * 2;
            float a0 = acc[mi][ni][0], a1 = acc[mi][ni][1];
            float a2 = acc[mi][ni][2], a3 = acc[mi][ni][3];
            if (MODE == 0) {
                *(float2*)(C + (size_t)r0 * N + cc)       = make_float2(a0, a1);
                *(float2*)(C + (size_t)(r0 + 8) * N + cc) = make_float2(a2, a3);
            } else if (MODE == 1) {
                if (cc < QCOLS) {
                    int d = cc & 255;
                    if (d >= 128) {
                        int i = (d - 128) >> 1;
                        int s0 = r0 & (SS_-1), s1 = (r0 + 8) & (SS_-1);
                        float c0 = g_cos[s0*64 + i], sn0 = g_sin[s0*64 + i];
                        float c1 = g_cos[s1*64 + i], sn1 = g_sin[s1*64 + i];
                        float xr = a0, xi = a1;
                        a0 = xr*c0 - xi*sn0; a1 = xr*sn0 + xi*c0;
                        xr = a2; xi = a3;
                        a2 = xr*c1 - xi*sn1; a3 = xr*sn1 + xi*c1;
                    }
                    uint32_t h0, l0, h1, l1;
                    split_pair(a0, a1, h0, l0);
                    split_pair(a2, a3, h1, l1);
                    size_t o0 = (size_t)r0 * QCOLS + cc, o1 = (size_t)(r0 + 8) * QCOLS + cc;
                    *(uint32_t*)(OH + o0) = h0; *(uint32_t*)(OL + o0) = l0;
                    *(uint32_t*)(OH + o1) = h1; *(uint32_t*)(OL + o1) = l1;
                } else {
                    int kc = cc - QCOLS;
                    *(float2*)(C + (size_t)r0 * KVCOLS + kc)       = make_float2(a0, a1);
                    *(float2*)(C + (size_t)(r0 + 8) * KVCOLS + kc) = make_float2(a2, a3);
                }
            } else {
                int hk = cc >> 8, d = cc & 255;
                uint32_t h0, l0, h1, l1;
                split_pair(a0, a1, h0, l0);
                split_pair(a2, a3, h1, l1);
                int b0 = r0 >> 11, s0 = r0 & (SS_-1);
                int b1 = (r0+8) >> 11, s1 = (r0+8) & (SS_-1);
                if (d < 128) {
                    size_t o0 = ((size_t)(b0*KVH + hk)*SS_ + s0)*256 + d;
                    size_t o1 = ((size_t)(b1*KVH + hk)*SS_ + s1)*256 + d;
                    *(uint32_t*)(OH + o0) = h0; *(uint32_t*)(OL + o0) = l0;
                    *(uint32_t*)(OH + o1) = h1; *(uint32_t*)(OL + o1) = l1;
                } else {
                    size_t o0 = ((size_t)(b0*KVH + hk)*SS_ + s0)*128 + (d - 128);
                    size_t o1 = ((size_t)(b1*KVH + hk)*SS_ + s1)*128 + (d - 128);
                    *(uint32_t*)(O2H + o0) = h0; *(uint32_t*)(O2L + o0) = l0;
                    *(uint32_t*)(O2H + o1) = h1; *(uint32_t*)(O2L + o1) = l1;
                }
            }
        }
    }
}

// ---------------------------------------------------------------------------
// LayerNorm -> kvc single fp16 ; RoPE(k_pe) -> split fp16 replicated into g_kH/L
// ---------------------------------------------------------------------------
__global__ void ln_rope_kv_kernel(const float* __restrict__ kvns) {
    int row = blockIdx.x;
    int tid = threadIdx.x;
    const float* x = g_kv + (size_t)row * KVCOLS;
    __shared__ float red[256];

    float v0 = x[tid], v1 = x[tid + 256];
    red[tid] = v0 + v1;
    __syncthreads();
#pragma unroll
    for (int off = 128; off > 0; off >>= 1) {
        if (tid < off) red[tid] += red[tid + off];
        __syncthreads();
    }
    float mean = red[0] * (1.f / 512.f);
    __syncthreads();
    float d0 = v0 - mean, d1 = v1 - mean;
    red[tid] = d0*d0 + d1*d1;
    __syncthreads();
#pragma unroll
    for (int off = 128; off > 0; off >>= 1) {
        if (tid < off) red[tid] += red[tid + off];
        __syncthreads();
    }
    float inv = rsqrtf(red[0] * (1.f / 512.f) + 1e-5f);
    size_t o = (size_t)row * KVR;
    g_kvcH[o + tid]       = __float2half_rn(d0 * inv * kvns[tid]);
    g_kvcH[o + tid + 256] = __float2half_rn(d1 * inv * kvns[tid + 256]);

    if (tid < 64) {
        int s = row & (SS_ - 1);
        int b = row >> 11;
        float c = g_cos[s*64 + tid], sn = g_sin[s*64 + tid];
        float xr = x[KVR + 2*tid], xi = x[KVR + 2*tid + 1];
        float k0 = xr*c - xi*sn, k1 = xr*sn + xi*c;
        uint32_t hh, ll;
        split_pair(k0, k1, hh, ll);
#pragma unroll
        for (int hk = 0; hk < KVH; hk++) {
            size_t base = ((size_t)(b*KVH + hk)*SS_ + s)*256 + 128 + 2*tid;
            *(uint32_t*)(g_kH + base) = hh;
            *(uint32_t*)(g_kL + base) = ll;
        }
    }
}

// ---------------------------------------------------------------------------
// Tensor-core flash attention (fp16): S = 3-term split (Q,K split),
// PV = 2-term (P single, V split). K double-buffered, V overlapped.
// ---------------------------------------------------------------------------
#define FA_QH_OFF 0
#define FA_QL_OFF 67584
#define FA_K0_OFF 135168           // two K stages of 33792 (hi 16896 + lo 16896)
#define FA_KSTG   33792
#define FA_V_OFF  202752           // hi 8704 + lo 8704
#define FA_SMEM   220160
#define QSTB 528
#define VSTB 272

__global__ void __launch_bounds__(256) fa_kernel() {
    const int tid = threadIdx.x, lane = tid & 31, wid = tid >> 5;
    const int b = blockIdx.x >> 4, h = blockIdx.x & 15, hk = h >> 1;
    const int qt = 15 - (int)blockIdx.y;   // big tiles first
    extern __shared__ char sm[];
    uint32_t sb = smem_u32(sm);

    const size_t kbase = (size_t)(b*KVH + hk) * SS_;
    const int NKT = 4*qt + 4;

    auto loadK = [&](int kt, int buf) {
        uint32_t kb = sb + FA_K0_OFF + (uint32_t)buf * FA_KSTG;
        const __half* khp = g_kH + (kbase + kt*32)*256;
        const __half* klp = g_kL + (kbase + kt*32)*256;
#pragma unroll
        for (int i = 0; i < 4; i++) {
            int idx = tid + i*256, r = idx >> 5, c = idx & 31;
            cp16(kb + r*QSTB + c*16,         khp + (size_t)r*256 + c*8);
            cp16(kb + 16896 + r*QSTB + c*16, klp + (size_t)r*256 + c*8);
        }
    };
    auto loadV = [&](int kt) {
        const __half* vhp = g_vH + (kbase + kt*32)*128;
        const __half* vlp = g_vL + (kbase + kt*32)*128;
#pragma unroll
        for (int i = 0; i < 2; i++) {
            int idx = tid + i*256, r = idx >> 4, c = idx & 15;
            cp16(sb + FA_V_OFF + r*VSTB + c*16,        vhp + (size_t)r*128 + c*8);
            cp16(sb + FA_V_OFF + 8704 + r*VSTB + c*16, vlp + (size_t)r*128 + c*8);
        }
    };

    // prologue: Q, K0, V0 (three commit groups)
    {
        const __half* qh = g_qH + ((size_t)(b*SS_ + qt*128))*QCOLS + h*256;
        const __half* ql = g_qL + ((size_t)(b*SS_ + qt*128))*QCOLS + h*256;
#pragma unroll
        for (int i = 0; i < 16; i++) {
            int idx = tid + i*256, r = idx >> 5, c = idx & 31;
            cp16(sb + FA_QH_OFF + r*QSTB + c*16, qh + (size_t)r*QCOLS + c*8);
            cp16(sb + FA_QL_OFF + r*QSTB + c*16, ql + (size_t)r*QCOLS + c*8);
        }
        cp_commit();
    }
    loadK(0, 0); cp_commit();
    loadV(0);    cp_commit();

    const int wm = wid * 16;
    float mrow0 = -1e30f, mrow1 = -1e30f;
    float lrow0 = 0.f, lrow1 = 0.f;
    float o[16][4];
#pragma unroll
    for (int nf = 0; nf < 16; nf++)
#pragma unroll
        for (int e = 0; e < 4; e++) o[nf][e] = 0.f;

    const float scale = 0.08838834764831845f;

    for (int kt = 0; kt < NKT; kt++) {
        cp_wait1();
        __syncthreads();
        if (kt + 1 < NKT) loadK(kt + 1, (kt + 1) & 1);
        cp_commit();

        uint32_t kbuf = sb + FA_K0_OFF + (uint32_t)(kt & 1) * FA_KSTG;

        // ---- S = Q K^T (3 split terms) ----
        float s4[4][4];
#pragma unroll
        for (int f = 0; f < 4; f++)
#pragma unroll
            for (int e = 0; e < 4; e++) s4[f][e] = 0.f;

#pragma unroll
        for (int kc = 0; kc < 16; kc++) {
            uint32_t ah[4], al[4];
            uint32_t aaddr = sb + FA_QH_OFF + (uint32_t)(wm + (lane & 15))*QSTB
                             + (uint32_t)(kc*16 + (lane >> 4)*8)*2;
            ldsm_x4(ah, aaddr);
            ldsm_x4(al, aaddr + (FA_QL_OFF - FA_QH_OFF));
#pragma unroll
            for (int nb = 0; nb < 2; nb++) {
                uint32_t baddr = kbuf
                    + (uint32_t)(nb*16 + (lane >> 4)*8 + (lane & 7))*QSTB
                    + (uint32_t)(kc*16 + ((lane >> 3) & 1)*8)*2;
                uint32_t bh[4], bl[4];
                ldsm_x4(bh, baddr);
                ldsm_x4(bl, baddr + 16896);
                mma16816(s4[2*nb],   ah, bh); mma16816(s4[2*nb+1], ah, bh+2);
                mma16816(s4[2*nb],   ah, bl); mma16816(s4[2*nb+1], ah, bl+2);
                mma16816(s4[2*nb],   al, bh); mma16816(s4[2*nb+1], al, bh+2);
            }
        }

        // ---- scale + causal mask ----
        if (kt >= 4*qt) {
            int grow0 = qt*128 + wm + (lane >> 2);
#pragma unroll
            for (int f = 0; f < 4; f++)
#pragma unroll
                for (int e = 0; e < 4; e++) {
                    int col = kt*32 + f*8 + (lane & 3)*2 + (e & 1);
                    int row = grow0 + (e >> 1)*8;
                    float v = s4[f][e] * scale;
                    s4[f][e] = (col > row) ? -1e9f : v;
                }
        } else {
#pragma unroll
            for (int f = 0; f < 4; f++)
#pragma unroll
                for (int e = 0; e < 4; e++) s4[f][e] *= scale;
        }

        // ---- online softmax ----
        float rm0 = -1e30f, rm1 = -1e30f;
#pragma unroll
        for (int f = 0; f < 4; f++) {
            rm0 = fmaxf(rm0, fmaxf(s4[f][0], s4[f][1]));
            rm1 = fmaxf(rm1, fmaxf(s4[f][2], s4[f][3]));
        }
        rm0 = fmaxf(rm0, __shfl_xor_sync(0xffffffffu, rm0, 1));
        rm0 = fmaxf(rm0, __shfl_xor_sync(0xffffffffu, rm0, 2));
        rm1 = fmaxf(rm1, __shfl_xor_sync(0xffffffffu, rm1, 1));
        rm1 = fmaxf(rm1, __shfl_xor_sync(0xffffffffu, rm1, 2));
        float mn0 = fmaxf(mrow0, rm0), mn1 = fmaxf(mrow1, rm1);
        float al0 = __expf(mrow0 - mn0), al1 = __expf(mrow1 - mn1);
        float rs0 = 0.f, rs1 = 0.f;
#pragma unroll
        for (int f = 0; f < 4; f++) {
            s4[f][0] = __expf(s4[f][0] - mn0); rs0 += s4[f][0];
            s4[f][1] = __expf(s4[f][1] - mn0); rs0 += s4[f][1];
            s4[f][2] = __expf(s4[f][2] - mn1); rs1 += s4[f][2];
            s4[f][3] = __expf(s4[f][3] - mn1); rs1 += s4[f][3];
        }
        rs0 += __shfl_xor_sync(0xffffffffu, rs0, 1);
        rs0 += __shfl_xor_sync(0xffffffffu, rs0, 2);
        rs1 += __shfl_xor_sync(0xffffffffu, rs1, 1);
        rs1 += __shfl_xor_sync(0xffffffffu, rs1, 2);
        lrow0 = lrow0*al0 + rs0; mrow0 = mn0;
        lrow1 = lrow1*al1 + rs1; mrow1 = mn1;

#pragma unroll
        for (int nf = 0; nf < 16; nf++) {
            o[nf][0] *= al0; o[nf][1] *= al0;
            o[nf][2] *= al1; o[nf][3] *= al1;
        }

        // ---- P fragments (single fp16) ----
        uint32_t ph[2][4];
#pragma unroll
        for (int c = 0; c < 2; c++) {
#pragma unroll
            for (int g = 0; g < 2; g++) {
                ph[c][2*g]   = pack_single(s4[2*c+g][0], s4[2*c+g][1]);
                ph[c][2*g+1] = pack_single(s4[2*c+g][2], s4[2*c+g][3]);
            }
        }

        // V(kt) ready; K(kt+1) may still be in flight
        cp_wait1();
        __syncthreads();

        // ---- O += P V (2 split terms: Ph*Vh + Ph*Vl) ----
#pragma unroll
        for (int c = 0; c < 2; c++) {
#pragma unroll
            for (int nb = 0; nb < 8; nb++) {
                uint32_t vaddr = sb + FA_V_OFF
                    + (uint32_t)(c*16 + ((lane >> 3) & 1)*8 + (lane & 7))*VSTB
                    + (uint32_t)(nb*16 + (lane >> 4)*8)*2;
                uint32_t bh[4], bl[4];
                ldsm_x4_t(bh, vaddr);
                ldsm_x4_t(bl, vaddr + 8704);
                mma16816(o[2*nb],   ph[c], bh); mma16816(o[2*nb+1], ph[c], bh+2);
                mma16816(o[2*nb],   ph[c], bl); mma16816(o[2*nb+1], ph[c], bl+2);
            }
        }

        __syncthreads();                 // all warps done reading V buffer
        if (kt + 1 < NKT) loadV(kt + 1);
        cp_commit();
    }

    // ---- epilogue: normalize, stage in SMEM, write single fp16 ----
    __syncthreads();
    float inv0 = 1.f / lrow0, inv1 = 1.f / lrow1;
    float* st = (float*)sm;   // reuse Q area (128 x 132 floats)
#pragma unroll
    for (int nf = 0; nf < 16; nf++) {
        int c0 = nf*8 + (lane & 3)*2;
        int r0 = wm + (lane >> 2);
        *(float2*)&st[r0*132 + c0]       = make_float2(o[nf][0]*inv0, o[nf][1]*inv0);
        *(float2*)&st[(r0 + 8)*132 + c0] = make_float2(o[nf][2]*inv1, o[nf][3]*inv1);
    }
    __syncthreads();
#pragma unroll
    for (int i = 0; i < 32; i++) {
        int idx = tid + i*256, r = idx >> 6, c = (idx & 63)*2;
        float f0 = st[r*132 + c], f1 = st[r*132 + c + 1];
        size_t off = ((size_t)(b*SS_ + qt*128 + r))*(HH*HD) + h*128 + c;
        *(uint32_t*)(g_attnH + off) = pack_single(f0, f1);
    }
}

// ---------------------------------------------------------------------------
extern "C" void kernel_launch(void* const* d_in, const int* in_sizes, int n_in,
                              void* d_out, int out_size) {
    const float* x     = (const float*)d_in[0];
    const float* wq    = (const float*)d_in[1];
    const float* wkv_a = (const float*)d_in[2];
    const float* kvns  = (const float*)d_in[3];
    const float* wkv_b = (const float*)d_in[4];
    const float* wo    = (const float*)d_in[5];
    const int*   pos   = (const int*)d_in[7];
    float* out = (float*)d_out;

    float *kv;
    cudaGetSymbolAddress((void**)&kv, g_kv);
    __half *xH,*kvcH,*attnH,*qH,*qL,*kH,*kL,*vH,*vL;
    cudaGetSymbolAddress((void**)&xH,    g_xH);
    cudaGetSymbolAddress((void**)&kvcH,  g_kvcH);
    cudaGetSymbolAddress((void**)&attnH, g_attnH);
    cudaGetSymbolAddress((void**)&qH,    g_qH);    cudaGetSymbolAddress((void**)&qL, g_qL);
    cudaGetSymbolAddress((void**)&kH,    g_kH);    cudaGetSymbolAddress((void**)&kL, g_kL);
    cudaGetSymbolAddress((void**)&vH,    g_vH);    cudaGetSymbolAddress((void**)&vL, g_vL);
    __half *wqah,*wqal,*wbh,*wbl,*woh,*wol;
    cudaGetSymbolAddress((void**)&wqah, g_wqaT_hi); cudaGetSymbolAddress((void**)&wqal, g_wqaT_lo);
    cudaGetSymbolAddress((void**)&wbh,  g_wbT_hi);  cudaGetSymbolAddress((void**)&wbl,  g_wbT_lo);
    cudaGetSymbolAddress((void**)&woh,  g_woT_hi);  cudaGetSymbolAddress((void**)&wol,  g_woT_lo);

    cudaFuncSetAttribute(mma_gemm_t<0>, cudaFuncAttributeMaxDynamicSharedMemorySize, GEMM_SMEM);
    cudaFuncSetAttribute(mma_gemm_t<1>, cudaFuncAttributeMaxDynamicSharedMemorySize, GEMM_SMEM);
    cudaFuncSetAttribute(mma_gemm_t<2>, cudaFuncAttributeMaxDynamicSharedMemorySize, GEMM_SMEM);
    cudaFuncSetAttribute(fa_kernel, cudaFuncAttributeMaxDynamicSharedMemorySize, FA_SMEM);

    trig_kernel<<<SS_, 64>>>(pos);

    // weight transpose + split (wq and wkv_a share one WT buffer)
    transpose_cvt<<<dim3(QCOLS/32,  DD/32),  256>>>(wq,    wqah, wqal, DD, QCOLS);
    transpose_cvt<<<dim3(KVCOLS/32, DD/32),  256>>>(wkv_a, wqah + (size_t)QCOLS*DD,
                                                            wqal + (size_t)QCOLS*DD, DD, KVCOLS);
    transpose_cvt<<<dim3(KVBCOLS/32,KVR/32), 256>>>(wkv_b, wbh, wbl, KVR, KVBCOLS);
    transpose_cvt<<<dim3(DD/32, (HH*HD)/32), 256>>>(wo,    woh, wol, HH*HD, DD);

    // x -> single fp16
    cvt_half<<<((size_t)ROWS*DD)/1024, 256>>>(x, xH);

    // [q | kv] = x @ [wq | wkv_a]  (fused; rope+split q, fp32 kv)
    mma_gemm_t<1><<<dim3(NQA/128, ROWS/128), 256, GEMM_SMEM>>>(
        xH, wqah, wqal, kv, qH, qL, nullptr, nullptr, ROWS, NQA, DD);
    // layernorm -> kvc fp16 ; roped k_pe -> g_kH/g_kL (replicated)
    ln_rope_kv_kernel<<<ROWS, 256>>>(kvns);
    // kvb = kv_c @ wkv_b -> scatter split k_nope/v head-major
    mma_gemm_t<2><<<dim3(KVBCOLS/128, ROWS/128), 256, GEMM_SMEM>>>(
        kvcH, wbh, wbl, nullptr, kH, kL, vH, vL, ROWS, KVBCOLS, KVR);
    // flash attention (fp16 tensor cores)
    fa_kernel<<<dim3(BB*HH, SS_/128), 256, FA_SMEM>>>();
    // out = attn @ wo
    mma_gemm_t<0><<<dim3(DD/128, ROWS/128), 256, GEMM_SMEM>>>(
        attnH, woh, wol, out, nullptr, nullptr, nullptr, nullptr, ROWS, DD, HH*HD);
}

// round 9
// speedup vs baseline: 6.5668x; 1.3701x over previous
#include <cuda_runtime.h>
#include <cuda_fp16.h>
#include <math.h>
#include <cstdint>

// Problem constants
#define BB 2
#define SS_ 2048
#define DD 2048
#define HH 16
#define KVH 8
#define HD 128
#define KVR 512
#define ROWS (BB*SS_)          // 4096
#define QCOLS (HH*2*HD)        // 4096
#define KVCOLS (KVR+HD)        // 640
#define NQA (QCOLS+KVCOLS)     // 4736
#define KVBCOLS (KVH*2*HD)     // 2048

// fp32 scratch
__device__ float g_kv  [(size_t)ROWS*KVCOLS];
__device__ float g_cos [SS_*64];
__device__ float g_sin [SS_*64];

// fp16 activations
__device__ __half g_xH   [(size_t)ROWS*DD];
__device__ __half g_kvcH [(size_t)ROWS*KVR];
__device__ __half g_attnH[(size_t)ROWS*(HH*HD)];
__device__ __half g_qH   [(size_t)ROWS*QCOLS];
__device__ __half g_qL   [(size_t)ROWS*QCOLS];
__device__ __half g_kH   [(size_t)BB*KVH*SS_*256];
__device__ __half g_kL   [(size_t)BB*KVH*SS_*256];
__device__ __half g_vH   [(size_t)BB*KVH*SS_*128];
__device__ __half g_vL   [(size_t)BB*KVH*SS_*128];

// transposed fp16 weights  WT[n][k]
__device__ __half g_wqaT_hi[(size_t)NQA*DD];      // wq ++ wkv_a (single fp16)
__device__ __half g_wbT_hi[(size_t)KVBCOLS*KVR];  // split
__device__ __half g_wbT_lo[(size_t)KVBCOLS*KVR];
__device__ __half g_woT_hi[(size_t)DD*(HH*HD)];   // single fp16

// ---------------------------------------------------------------------------
// helpers
// ---------------------------------------------------------------------------
__device__ __forceinline__ uint32_t smem_u32(const void* p) {
    uint32_t a;
    asm("{ .reg .u64 t; cvta.to.shared.u64 t, %1; cvt.u32.u64 %0, t; }"
        : "=r"(a) : "l"(p));
    return a;
}
#define SWZ(o) ((o) ^ (((o) >> 3) & 0x70))

__device__ __forceinline__ void cp16(uint32_t dst, const void* src) {
    asm volatile("cp.async.cg.shared.global [%0], [%1], 16;" :: "r"(dst), "l"(src));
}
__device__ __forceinline__ void cp_commit() {
    asm volatile("cp.async.commit_group;" ::: "memory");
}
__device__ __forceinline__ void cp_wait1() {
    asm volatile("cp.async.wait_group 1;" ::: "memory");
}
__device__ __forceinline__ void cp_wait2() {
    asm volatile("cp.async.wait_group 2;" ::: "memory");
}
__device__ __forceinline__ void ldsm_x4(uint32_t (&r)[4], uint32_t addr) {
    asm volatile("ldmatrix.sync.aligned.m8n8.x4.shared.b16 {%0,%1,%2,%3}, [%4];"
                 : "=r"(r[0]), "=r"(r[1]), "=r"(r[2]), "=r"(r[3]) : "r"(addr));
}
__device__ __forceinline__ void ldsm_x4_t(uint32_t (&r)[4], uint32_t addr) {
    asm volatile("ldmatrix.sync.aligned.m8n8.x4.trans.shared.b16 {%0,%1,%2,%3}, [%4];"
                 : "=r"(r[0]), "=r"(r[1]), "=r"(r[2]), "=r"(r[3]) : "r"(addr));
}
__device__ __forceinline__ void mma16816(float* d, const uint32_t* a, const uint32_t* b) {
    asm volatile(
        "mma.sync.aligned.m16n8k16.row.col.f32.f16.f16.f32 "
        "{%0,%1,%2,%3},{%4,%5,%6,%7},{%8,%9},{%0,%1,%2,%3};"
        : "+f"(d[0]), "+f"(d[1]), "+f"(d[2]), "+f"(d[3])
        : "r"(a[0]), "r"(a[1]), "r"(a[2]), "r"(a[3]), "r"(b[0]), "r"(b[1]));
}
__device__ __forceinline__ uint32_t pack_h2(__half a, __half b) {
    return (uint32_t)__half_as_ushort(a) | ((uint32_t)__half_as_ushort(b) << 16);
}
__device__ __forceinline__ uint32_t pack_single(float f0, float f1) {
    return pack_h2(__float2half_rn(f0), __float2half_rn(f1));
}
__device__ __forceinline__ void split_pair(float f0, float f1, uint32_t& hi, uint32_t& lo) {
    __half h0 = __float2half_rn(f0), h1 = __float2half_rn(f1);
    hi = pack_h2(h0, h1);
    lo = pack_h2(__float2half_rn(f0 - __half2float(h0)),
                 __float2half_rn(f1 - __half2float(h1)));
}

// ---------------------------------------------------------------------------
// Trig table (fp64 freqs to match JAX fp32 pow exactly)
// ---------------------------------------------------------------------------
__global__ void trig_kernel(const int* __restrict__ pos_ids) {
    int s = blockIdx.x;
    int i = threadIdx.x;
    double freq = 40.0 * pow(10000.0, -((double)(2*i)) / 128.0);
    float ang = (float)pos_ids[s] * (float)freq;
    g_cos[s*64 + i] = (float)cos((double)ang);
    g_sin[s*64 + i] = (float)sin((double)ang);
}

// ---------------------------------------------------------------------------
// elementwise fp32 -> single fp16
// ---------------------------------------------------------------------------
__global__ void cvt_half(const float* __restrict__ X, __half* __restrict__ H) {
    size_t i = ((size_t)blockIdx.x * 256 + threadIdx.x) * 4;
    float4 v = *(const float4*)(X + i);
    *(uint2*)(H + i) = make_uint2(pack_single(v.x, v.y), pack_single(v.z, v.w));
}

// ---------------------------------------------------------------------------
// Weight transpose: W[K][N] -> Thi[N][K] single fp16 (Tlo optional)
// ---------------------------------------------------------------------------
__global__ void transpose_cvt(const float* __restrict__ W,
                              __half* __restrict__ Thi,
                              __half* __restrict__ Tlo, int K, int N) {
    __shared__ float ts[32][33];
    int k0 = blockIdx.y * 32, n0 = blockIdx.x * 32;
    int tx = threadIdx.x & 31, ty = threadIdx.x >> 5;  // 32x8
#pragma unroll
    for (int i = 0; i < 4; i++)
        ts[ty + 8*i][tx] = W[(size_t)(k0 + ty + 8*i)*N + n0 + tx];
    __syncthreads();
#pragma unroll
    for (int i = 0; i < 4; i++) {
        int n = ty + 8*i;
        float v = ts[tx][n];
        __half hi = __float2half_rn(v);
        size_t o = (size_t)(n0 + n)*K + k0 + tx;
        Thi[o] = hi;
        if (Tlo) Tlo[o] = __float2half_rn(v - __half2float(hi));
    }
}

// ---------------------------------------------------------------------------
// fp16 GEMM, TERMS in {1,2} B-side terms, 3-stage cp.async pipeline.
// MODE 0: C fp32.
// MODE 1: N=NQA; cc<QCOLS: rope(q_pe)+split -> qH/qL; else fp32 -> g_kv.
// MODE 2: scatter split k_nope -> OH/OL, v -> O2H/O2L (head-major).
// ---------------------------------------------------------------------------
#define GEMM_SMEM (3*32768)   // 96 KB

template<int MODE, int TERMS>
__global__ void __launch_bounds__(256)
mma_gemm_t(const __half* __restrict__ A,
           const __half* __restrict__ Bhi, const __half* __restrict__ Blo,
           float* __restrict__ C,
           __half* __restrict__ OH, __half* __restrict__ OL,
           __half* __restrict__ O2H, __half* __restrict__ O2L,
           int M, int N, int K) {
    extern __shared__ char sm[];
    uint32_t sb = smem_u32(sm);
    const int tid = threadIdx.x, lane = tid & 31, wid = tid >> 5;
    const int row0 = blockIdx.y * 128, col0 = blockIdx.x * 128;
    const int wm = (wid >> 2) * 64, wn = (wid & 3) * 32;
    const int cps = K >> 6;
    const int NC = TERMS * cps;

    float acc[4][4][4];
#pragma unroll
    for (int mi = 0; mi < 4; mi++)
#pragma unroll
        for (int ni = 0; ni < 4; ni++)
#pragma unroll
            for (int r = 0; r < 4; r++) acc[mi][ni][r] = 0.f;

    auto load_chunk = [&](int c, int buf) {
        int sec = (TERMS == 2) ? (c >= cps) : 0;
        int cc = c - sec * cps;
        const __half* gA = A + (size_t)row0 * K + cc * 64;
        const __half* gB = (sec ? Blo : Bhi) + (size_t)col0 * K + cc * 64;
        uint32_t base = sb + (uint32_t)buf * 32768;
#pragma unroll
        for (int i = 0; i < 4; i++) {
            int idx = tid + i * 256;
            int r = idx >> 3, s = idx & 7;
            cp16(base + SWZ((uint32_t)(r * 128 + s * 16)), gA + (size_t)r * K + s * 8);
        }
#pragma unroll
        for (int i = 0; i < 4; i++) {
            int idx = tid + i * 256;
            int r = idx >> 3, s = idx & 7;
            cp16(base + 16384 + SWZ((uint32_t)(r * 128 + s * 16)), gB + (size_t)r * K + s * 8);
        }
    };

    load_chunk(0, 0); cp_commit();
    if (NC > 1) load_chunk(1, 1);
    cp_commit();

    for (int c = 0; c < NC; c++) {
        if (c + 2 < NC) load_chunk(c + 2, (c + 2) % 3);
        cp_commit();
        cp_wait2();
        __syncthreads();

        uint32_t sA = sb + (uint32_t)(c % 3) * 32768;
        uint32_t sB = sA + 16384;
        uint32_t Breg[4][4];
#pragma unroll
        for (int kk = 0; kk < 4; kk++) {
            if ((kk & 1) == 0) {
                int kh = kk >> 1;
#pragma unroll
                for (int ni = 0; ni < 4; ni++) {
                    uint32_t addr = sB + SWZ((uint32_t)((wn + ni*8 + (lane & 7)) * 128
                                                        + kh*64 + (lane >> 3) * 16));
                    ldsm_x4(Breg[ni], addr);
                }
            }
            uint32_t Areg[4][4];
#pragma unroll
            for (int mi = 0; mi < 4; mi++) {
                uint32_t addr = sA + SWZ((uint32_t)((wm + mi*16 + (lane & 15)) * 128
                                                    + kk*32 + (lane >> 4) * 16));
                ldsm_x4(Areg[mi], addr);
            }
#pragma unroll
            for (int mi = 0; mi < 4; mi++)
#pragma unroll
                for (int ni = 0; ni < 4; ni++)
                    mma16816(acc[mi][ni], Areg[mi], &Breg[ni][2 * (kk & 1)]);
        }
        __syncthreads();
    }

    // epilogue
#pragma unroll
    for (int mi = 0; mi < 4; mi++) {
        int r0 = row0 + wm + mi * 16 + (lane >> 2);
#pragma unroll
        for (int ni = 0; ni < 4; ni++) {
            int cc = col0 + wn + ni * 8 + (lane & 3) * 2;
            float a0 = acc[mi][ni][0], a1 = acc[mi][ni][1];
            float a2 = acc[mi][ni][2], a3 = acc[mi][ni][3];
            if (MODE == 0) {
                *(float2*)(C + (size_t)r0 * N + cc)       = make_float2(a0, a1);
                *(float2*)(C + (size_t)(r0 + 8) * N + cc) = make_float2(a2, a3);
            } else if (MODE == 1) {
                if (cc < QCOLS) {
                    int d = cc & 255;
                    if (d >= 128) {
                        int i = (d - 128) >> 1;
                        int s0 = r0 & (SS_-1), s1 = (r0 + 8) & (SS_-1);
                        float c0 = g_cos[s0*64 + i], sn0 = g_sin[s0*64 + i];
                        float c1 = g_cos[s1*64 + i], sn1 = g_sin[s1*64 + i];
                        float xr = a0, xi = a1;
                        a0 = xr*c0 - xi*sn0; a1 = xr*sn0 + xi*c0;
                        xr = a2; xi = a3;
                        a2 = xr*c1 - xi*sn1; a3 = xr*sn1 + xi*c1;
                    }
                    uint32_t h0, l0, h1, l1;
                    split_pair(a0, a1, h0, l0);
                    split_pair(a2, a3, h1, l1);
                    size_t o0 = (size_t)r0 * QCOLS + cc, o1 = (size_t)(r0 + 8) * QCOLS + cc;
                    *(uint32_t*)(OH + o0) = h0; *(uint32_t*)(OL + o0) = l0;
                    *(uint32_t*)(OH + o1) = h1; *(uint32_t*)(OL + o1) = l1;
                } else {
                    int kc = cc - QCOLS;
                    *(float2*)(C + (size_t)r0 * KVCOLS + kc)       = make_float2(a0, a1);
                    *(float2*)(C + (size_t)(r0 + 8) * KVCOLS + kc) = make_float2(a2, a3);
                }
            } else {
                int hk = cc >> 8, d = cc & 255;
                uint32_t h0, l0, h1, l1;
                split_pair(a0, a1, h0, l0);
                split_pair(a2, a3, h1, l1);
                int b0 = r0 >> 11, s0 = r0 & (SS_-1);
                int b1 = (r0+8) >> 11, s1 = (r0+8) & (SS_-1);
                if (d < 128) {
                    size_t o0 = ((size_t)(b0*KVH + hk)*SS_ + s0)*256 + d;
                    size_t o1 = ((size_t)(b1*KVH + hk)*SS_ + s1)*256 + d;
                    *(uint32_t*)(OH + o0) = h0; *(uint32_t*)(OL + o0) = l0;
                    *(uint32_t*)(OH + o1) = h1; *(uint32_t*)(OL + o1) = l1;
                } else {
                    size_t o0 = ((size_t)(b0*KVH + hk)*SS_ + s0)*128 + (d - 128);
                    size_t o1 = ((size_t)(b1*KVH + hk)*SS_ + s1)*128 + (d - 128);
                    *(uint32_t*)(O2H + o0) = h0; *(uint32_t*)(O2L + o0) = l0;
                    *(uint32_t*)(O2H + o1) = h1; *(uint32_t*)(O2L + o1) = l1;
                }
            }
        }
    }
}

// ---------------------------------------------------------------------------
// LayerNorm -> kvc single fp16 ; RoPE(k_pe) -> split fp16 replicated into g_kH/L
// ---------------------------------------------------------------------------
__global__ void ln_rope_kv_kernel(const float* __restrict__ kvns) {
    int row = blockIdx.x;
    int tid = threadIdx.x;
    const float* x = g_kv + (size_t)row * KVCOLS;
    __shared__ float red[256];

    float v0 = x[tid], v1 = x[tid + 256];
    red[tid] = v0 + v1;
    __syncthreads();
#pragma unroll
    for (int off = 128; off > 0; off >>= 1) {
        if (tid < off) red[tid] += red[tid + off];
        __syncthreads();
    }
    float mean = red[0] * (1.f / 512.f);
    __syncthreads();
    float d0 = v0 - mean, d1 = v1 - mean;
    red[tid] = d0*d0 + d1*d1;
    __syncthreads();
#pragma unroll
    for (int off = 128; off > 0; off >>= 1) {
        if (tid < off) red[tid] += red[tid + off];
        __syncthreads();
    }
    float inv = rsqrtf(red[0] * (1.f / 512.f) + 1e-5f);
    size_t o = (size_t)row * KVR;
    g_kvcH[o + tid]       = __float2half_rn(d0 * inv * kvns[tid]);
    g_kvcH[o + tid + 256] = __float2half_rn(d1 * inv * kvns[tid + 256]);

    if (tid < 64) {
        int s = row & (SS_ - 1);
        int b = row >> 11;
        float c = g_cos[s*64 + tid], sn = g_sin[s*64 + tid];
        float xr = x[KVR + 2*tid], xi = x[KVR + 2*tid + 1];
        float k0 = xr*c - xi*sn, k1 = xr*sn + xi*c;
        uint32_t hh, ll;
        split_pair(k0, k1, hh, ll);
#pragma unroll
        for (int hk = 0; hk < KVH; hk++) {
            size_t base = ((size_t)(b*KVH + hk)*SS_ + s)*256 + 128 + 2*tid;
            *(uint32_t*)(g_kH + base) = hh;
            *(uint32_t*)(g_kL + base) = ll;
        }
    }
}

// ---------------------------------------------------------------------------
// Tensor-core flash attention (fp16): S = 3-term split (Q,K split),
// PV = 2-term (P single, V split). K double-buffered, V overlapped.
// ---------------------------------------------------------------------------
#define FA_QH_OFF 0
#define FA_QL_OFF 67584
#define FA_K0_OFF 135168           // two K stages of 33792 (hi 16896 + lo 16896)
#define FA_KSTG   33792
#define FA_V_OFF  202752           // hi 8704 + lo 8704
#define FA_SMEM   220160
#define QSTB 528
#define VSTB 272

__global__ void __launch_bounds__(256) fa_kernel() {
    const int tid = threadIdx.x, lane = tid & 31, wid = tid >> 5;
    const int b = blockIdx.x >> 4, h = blockIdx.x & 15, hk = h >> 1;
    const int qt = 15 - (int)blockIdx.y;   // big tiles first
    extern __shared__ char sm[];
    uint32_t sb = smem_u32(sm);

    const size_t kbase = (size_t)(b*KVH + hk) * SS_;
    const int NKT = 4*qt + 4;

    auto loadK = [&](int kt, int buf) {
        uint32_t kb = sb + FA_K0_OFF + (uint32_t)buf * FA_KSTG;
        const __half* khp = g_kH + (kbase + kt*32)*256;
        const __half* klp = g_kL + (kbase + kt*32)*256;
#pragma unroll
        for (int i = 0; i < 4; i++) {
            int idx = tid + i*256, r = idx >> 5, c = idx & 31;
            cp16(kb + r*QSTB + c*16,         khp + (size_t)r*256 + c*8);
            cp16(kb + 16896 + r*QSTB + c*16, klp + (size_t)r*256 + c*8);
        }
    };
    auto loadV = [&](int kt) {
        const __half* vhp = g_vH + (kbase + kt*32)*128;
        const __half* vlp = g_vL + (kbase + kt*32)*128;
#pragma unroll
        for (int i = 0; i < 2; i++) {
            int idx = tid + i*256, r = idx >> 4, c = idx & 15;
            cp16(sb + FA_V_OFF + r*VSTB + c*16,        vhp + (size_t)r*128 + c*8);
            cp16(sb + FA_V_OFF + 8704 + r*VSTB + c*16, vlp + (size_t)r*128 + c*8);
        }
    };

    // prologue: Q, K0, V0 (three commit groups)
    {
        const __half* qh = g_qH + ((size_t)(b*SS_ + qt*128))*QCOLS + h*256;
        const __half* ql = g_qL + ((size_t)(b*SS_ + qt*128))*QCOLS + h*256;
#pragma unroll
        for (int i = 0; i < 16; i++) {
            int idx = tid + i*256, r = idx >> 5, c = idx & 31;
            cp16(sb + FA_QH_OFF + r*QSTB + c*16, qh + (size_t)r*QCOLS + c*8);
            cp16(sb + FA_QL_OFF + r*QSTB + c*16, ql + (size_t)r*QCOLS + c*8);
        }
        cp_commit();
    }
    loadK(0, 0); cp_commit();
    loadV(0);    cp_commit();

    const int wm = wid * 16;
    float mrow0 = -1e30f, mrow1 = -1e30f;
    float lrow0 = 0.f, lrow1 = 0.f;
    float o[16][4];
#pragma unroll
    for (int nf = 0; nf < 16; nf++)
#pragma unroll
        for (int e = 0; e < 4; e++) o[nf][e] = 0.f;

    const float scale = 0.08838834764831845f;

    for (int kt = 0; kt < NKT; kt++) {
        cp_wait1();
        __syncthreads();
        if (kt + 1 < NKT) loadK(kt + 1, (kt + 1) & 1);
        cp_commit();

        uint32_t kbuf = sb + FA_K0_OFF + (uint32_t)(kt & 1) * FA_KSTG;

        // ---- S = Q K^T (3 split terms) ----
        float s4[4][4];
#pragma unroll
        for (int f = 0; f < 4; f++)
#pragma unroll
            for (int e = 0; e < 4; e++) s4[f][e] = 0.f;

#pragma unroll
        for (int kc = 0; kc < 16; kc++) {
            uint32_t ah[4], al[4];
            uint32_t aaddr = sb + FA_QH_OFF + (uint32_t)(wm + (lane & 15))*QSTB
                             + (uint32_t)(kc*16 + (lane >> 4)*8)*2;
            ldsm_x4(ah, aaddr);
            ldsm_x4(al, aaddr + (FA_QL_OFF - FA_QH_OFF));
#pragma unroll
            for (int nb = 0; nb < 2; nb++) {
                uint32_t baddr = kbuf
                    + (uint32_t)(nb*16 + (lane >> 4)*8 + (lane & 7))*QSTB
                    + (uint32_t)(kc*16 + ((lane >> 3) & 1)*8)*2;
                uint32_t bh[4], bl[4];
                ldsm_x4(bh, baddr);
                ldsm_x4(bl, baddr + 16896);
                mma16816(s4[2*nb],   ah, bh); mma16816(s4[2*nb+1], ah, bh+2);
                mma16816(s4[2*nb],   ah, bl); mma16816(s4[2*nb+1], ah, bl+2);
                mma16816(s4[2*nb],   al, bh); mma16816(s4[2*nb+1], al, bh+2);
            }
        }

        // ---- scale + causal mask ----
        if (kt >= 4*qt) {
            int grow0 = qt*128 + wm + (lane >> 2);
#pragma unroll
            for (int f = 0; f < 4; f++)
#pragma unroll
                for (int e = 0; e < 4; e++) {
                    int col = kt*32 + f*8 + (lane & 3)*2 + (e & 1);
                    int row = grow0 + (e >> 1)*8;
                    float v = s4[f][e] * scale;
                    s4[f][e] = (col > row) ? -1e9f : v;
                }
        } else {
#pragma unroll
            for (int f = 0; f < 4; f++)
#pragma unroll
                for (int e = 0; e < 4; e++) s4[f][e] *= scale;
        }

        // ---- online softmax ----
        float rm0 = -1e30f, rm1 = -1e30f;
#pragma unroll
        for (int f = 0; f < 4; f++) {
            rm0 = fmaxf(rm0, fmaxf(s4[f][0], s4[f][1]));
            rm1 = fmaxf(rm1, fmaxf(s4[f][2], s4[f][3]));
        }
        rm0 = fmaxf(rm0, __shfl_xor_sync(0xffffffffu, rm0, 1));
        rm0 = fmaxf(rm0, __shfl_xor_sync(0xffffffffu, rm0, 2));
        rm1 = fmaxf(rm1, __shfl_xor_sync(0xffffffffu, rm1, 1));
        rm1 = fmaxf(rm1, __shfl_xor_sync(0xffffffffu, rm1, 2));
        float mn0 = fmaxf(mrow0, rm0), mn1 = fmaxf(mrow1, rm1);
        float al0 = __expf(mrow0 - mn0), al1 = __expf(mrow1 - mn1);
        float rs0 = 0.f, rs1 = 0.f;
#pragma unroll
        for (int f = 0; f < 4; f++) {
            s4[f][0] = __expf(s4[f][0] - mn0); rs0 += s4[f][0];
            s4[f][1] = __expf(s4[f][1] - mn0); rs0 += s4[f][1];
            s4[f][2] = __expf(s4[f][2] - mn1); rs1 += s4[f][2];
            s4[f][3] = __expf(s4[f][3] - mn1); rs1 += s4[f][3];
        }
        rs0 += __shfl_xor_sync(0xffffffffu, rs0, 1);
        rs0 += __shfl_xor_sync(0xffffffffu, rs0, 2);
        rs1 += __shfl_xor_sync(0xffffffffu, rs1, 1);
        rs1 += __shfl_xor_sync(0xffffffffu, rs1, 2);
        lrow0 = lrow0*al0 + rs0; mrow0 = mn0;
        lrow1 = lrow1*al1 + rs1; mrow1 = mn1;

#pragma unroll
        for (int nf = 0; nf < 16; nf++) {
            o[nf][0] *= al0; o[nf][1] *= al0;
            o[nf][2] *= al1; o[nf][3] *= al1;
        }

        // ---- P fragments (single fp16) ----
        uint32_t ph[2][4];
#pragma unroll
        for (int c = 0; c < 2; c++) {
#pragma unroll
            for (int g = 0; g < 2; g++) {
                ph[c][2*g]   = pack_single(s4[2*c+g][0], s4[2*c+g][1]);
                ph[c][2*g+1] = pack_single(s4[2*c+g][2], s4[2*c+g][3]);
            }
        }

        // V(kt) ready; K(kt+1) may still be in flight
        cp_wait1();
        __syncthreads();

        // ---- O += P V (2 split terms: Ph*Vh + Ph*Vl) ----
#pragma unroll
        for (int c = 0; c < 2; c++) {
#pragma unroll
            for (int nb = 0; nb < 8; nb++) {
                uint32_t vaddr = sb + FA_V_OFF
                    + (uint32_t)(c*16 + ((lane >> 3) & 1)*8 + (lane & 7))*VSTB
                    + (uint32_t)(nb*16 + (lane >> 4)*8)*2;
                uint32_t bh[4], bl[4];
                ldsm_x4_t(bh, vaddr);
                ldsm_x4_t(bl, vaddr + 8704);
                mma16816(o[2*nb],   ph[c], bh); mma16816(o[2*nb+1], ph[c], bh+2);
                mma16816(o[2*nb],   ph[c], bl); mma16816(o[2*nb+1], ph[c], bl+2);
            }
        }

        __syncthreads();                 // all warps done reading V buffer
        if (kt + 1 < NKT) loadV(kt + 1);
        cp_commit();
    }

    // ---- epilogue: normalize, stage in SMEM, write single fp16 ----
    __syncthreads();
    float inv0 = 1.f / lrow0, inv1 = 1.f / lrow1;
    float* st = (float*)sm;   // reuse Q area (128 x 132 floats)
#pragma unroll
    for (int nf = 0; nf < 16; nf++) {
        int c0 = nf*8 + (lane & 3)*2;
        int r0 = wm + (lane >> 2);
        *(float2*)&st[r0*132 + c0]       = make_float2(o[nf][0]*inv0, o[nf][1]*inv0);
        *(float2*)&st[(r0 + 8)*132 + c0] = make_float2(o[nf][2]*inv1, o[nf][3]*inv1);
    }
    __syncthreads();
#pragma unroll
    for (int i = 0; i < 32; i++) {
        int idx = tid + i*256, r = idx >> 6, c = (idx & 63)*2;
        float f0 = st[r*132 + c], f1 = st[r*132 + c + 1];
        size_t off = ((size_t)(b*SS_ + qt*128 + r))*(HH*HD) + h*128 + c;
        *(uint32_t*)(g_attnH + off) = pack_single(f0, f1);
    }
}

// ---------------------------------------------------------------------------
extern "C" void kernel_launch(void* const* d_in, const int* in_sizes, int n_in,
                              void* d_out, int out_size) {
    const float* x     = (const float*)d_in[0];
    const float* wq    = (const float*)d_in[1];
    const float* wkv_a = (const float*)d_in[2];
    const float* kvns  = (const float*)d_in[3];
    const float* wkv_b = (const float*)d_in[4];
    const float* wo    = (const float*)d_in[5];
    const int*   pos   = (const int*)d_in[7];
    float* out = (float*)d_out;

    float *kv;
    cudaGetSymbolAddress((void**)&kv, g_kv);
    __half *xH,*kvcH,*attnH,*qH,*qL,*kH,*kL,*vH,*vL;
    cudaGetSymbolAddress((void**)&xH,    g_xH);
    cudaGetSymbolAddress((void**)&kvcH,  g_kvcH);
    cudaGetSymbolAddress((void**)&attnH, g_attnH);
    cudaGetSymbolAddress((void**)&qH,    g_qH);    cudaGetSymbolAddress((void**)&qL, g_qL);
    cudaGetSymbolAddress((void**)&kH,    g_kH);    cudaGetSymbolAddress((void**)&kL, g_kL);
    cudaGetSymbolAddress((void**)&vH,    g_vH);    cudaGetSymbolAddress((void**)&vL, g_vL);
    __half *wqah,*wbh,*wbl,*woh;
    cudaGetSymbolAddress((void**)&wqah, g_wqaT_hi);
    cudaGetSymbolAddress((void**)&wbh,  g_wbT_hi);  cudaGetSymbolAddress((void**)&wbl, g_wbT_lo);
    cudaGetSymbolAddress((void**)&woh,  g_woT_hi);

    cudaFuncSetAttribute((const void*)mma_gemm_t<0,1>, cudaFuncAttributeMaxDynamicSharedMemorySize, GEMM_SMEM);
    cudaFuncSetAttribute((const void*)mma_gemm_t<1,1>, cudaFuncAttributeMaxDynamicSharedMemorySize, GEMM_SMEM);
    cudaFuncSetAttribute((const void*)mma_gemm_t<2,2>, cudaFuncAttributeMaxDynamicSharedMemorySize, GEMM_SMEM);
    cudaFuncSetAttribute(fa_kernel, cudaFuncAttributeMaxDynamicSharedMemorySize, FA_SMEM);

    trig_kernel<<<SS_, 64>>>(pos);

    // weight transpose (wq/wkv_a and wo single fp16; wkv_b split)
    transpose_cvt<<<dim3(QCOLS/32,  DD/32),  256>>>(wq,    wqah, nullptr, DD, QCOLS);
    transpose_cvt<<<dim3(KVCOLS/32, DD/32),  256>>>(wkv_a, wqah + (size_t)QCOLS*DD,
                                                            nullptr, DD, KVCOLS);
    transpose_cvt<<<dim3(KVBCOLS/32,KVR/32), 256>>>(wkv_b, wbh, wbl, KVR, KVBCOLS);
    transpose_cvt<<<dim3(DD/32, (HH*HD)/32), 256>>>(wo,    woh, nullptr, HH*HD, DD);

    // x -> single fp16
    cvt_half<<<((size_t)ROWS*DD)/1024, 256>>>(x, xH);

    // [q | kv] = x @ [wq | wkv_a]  (1-term; rope+split q, fp32 kv)
    mma_gemm_t<1,1><<<dim3(NQA/128, ROWS/128), 256, GEMM_SMEM>>>(
        xH, wqah, nullptr, kv, qH, qL, nullptr, nullptr, ROWS, NQA, DD);
    // layernorm -> kvc fp16 ; roped k_pe -> g_kH/g_kL (replicated)
    ln_rope_kv_kernel<<<ROWS, 256>>>(kvns);
    // kvb = kv_c @ wkv_b (2-term) -> scatter split k_nope/v head-major
    mma_gemm_t<2,2><<<dim3(KVBCOLS/128, ROWS/128), 256, GEMM_SMEM>>>(
        kvcH, wbh, wbl, nullptr, kH, kL, vH, vL, ROWS, KVBCOLS, KVR);
    // flash attention (fp16 tensor cores)
    fa_kernel<<<dim3(BB*HH, SS_/128), 256, FA_SMEM>>>();
    // out = attn @ wo (1-term)
    mma_gemm_t<0,1><<<dim3(DD/128, ROWS/128), 256, GEMM_SMEM>>>(
        attnH, woh, nullptr, out, nullptr, nullptr, nullptr, nullptr, ROWS, DD, HH*HD);
}

// round 10
// speedup vs baseline: 7.3374x; 1.1173x over previous
#include <cuda_runtime.h>
#include <cuda_fp16.h>
#include <math.h>
#include <cstdint>

// Problem constants
#define BB 2
#define SS_ 2048
#define DD 2048
#define HH 16
#define KVH 8
#define HD 128
#define KVR 512
#define ROWS (BB*SS_)          // 4096
#define QCOLS (HH*2*HD)        // 4096
#define KVCOLS (KVR+HD)        // 640
#define NQA (QCOLS+KVCOLS)     // 4736
#define KVBCOLS (KVH*2*HD)     // 2048

// fp32 scratch
__device__ float g_kv  [(size_t)ROWS*KVCOLS];
__device__ float g_cos [SS_*64];
__device__ float g_sin [SS_*64];

// fp16 activations
__device__ __half g_xH   [(size_t)ROWS*DD];
__device__ __half g_kvcH [(size_t)ROWS*KVR];
__device__ __half g_attnH[(size_t)ROWS*(HH*HD)];
__device__ __half g_qH   [(size_t)ROWS*QCOLS];          // single fp16
__device__ __half g_kH   [(size_t)BB*KVH*SS_*256];      // split
__device__ __half g_kL   [(size_t)BB*KVH*SS_*256];
__device__ __half g_vH   [(size_t)BB*KVH*SS_*128];      // single fp16

// transposed fp16 weights  WT[n][k]
__device__ __half g_wqaT_hi[(size_t)NQA*DD];      // wq ++ wkv_a (single fp16)
__device__ __half g_wbT_hi[(size_t)KVBCOLS*KVR];  // split
__device__ __half g_wbT_lo[(size_t)KVBCOLS*KVR];
__device__ __half g_woT_hi[(size_t)DD*(HH*HD)];   // single fp16

// ---------------------------------------------------------------------------
// helpers
// ---------------------------------------------------------------------------
__device__ __forceinline__ uint32_t smem_u32(const void* p) {
    uint32_t a;
    asm("{ .reg .u64 t; cvta.to.shared.u64 t, %1; cvt.u32.u64 %0, t; }"
        : "=r"(a) : "l"(p));
    return a;
}
#define SWZ(o) ((o) ^ (((o) >> 3) & 0x70))

__device__ __forceinline__ void cp16(uint32_t dst, const void* src) {
    asm volatile("cp.async.cg.shared.global [%0], [%1], 16;" :: "r"(dst), "l"(src));
}
__device__ __forceinline__ void cp_commit() {
    asm volatile("cp.async.commit_group;" ::: "memory");
}
__device__ __forceinline__ void cp_wait1() {
    asm volatile("cp.async.wait_group 1;" ::: "memory");
}
__device__ __forceinline__ void cp_wait2() {
    asm volatile("cp.async.wait_group 2;" ::: "memory");
}
__device__ __forceinline__ void ldsm_x4(uint32_t (&r)[4], uint32_t addr) {
    asm volatile("ldmatrix.sync.aligned.m8n8.x4.shared.b16 {%0,%1,%2,%3}, [%4];"
                 : "=r"(r[0]), "=r"(r[1]), "=r"(r[2]), "=r"(r[3]) : "r"(addr));
}
__device__ __forceinline__ void ldsm_x4_t(uint32_t (&r)[4], uint32_t addr) {
    asm volatile("ldmatrix.sync.aligned.m8n8.x4.trans.shared.b16 {%0,%1,%2,%3}, [%4];"
                 : "=r"(r[0]), "=r"(r[1]), "=r"(r[2]), "=r"(r[3]) : "r"(addr));
}
__device__ __forceinline__ void mma16816(float* d, const uint32_t* a, const uint32_t* b) {
    asm volatile(
        "mma.sync.aligned.m16n8k16.row.col.f32.f16.f16.f32 "
        "{%0,%1,%2,%3},{%4,%5,%6,%7},{%8,%9},{%0,%1,%2,%3};"
        : "+f"(d[0]), "+f"(d[1]), "+f"(d[2]), "+f"(d[3])
        : "r"(a[0]), "r"(a[1]), "r"(a[2]), "r"(a[3]), "r"(b[0]), "r"(b[1]));
}
__device__ __forceinline__ uint32_t pack_h2(__half a, __half b) {
    return (uint32_t)__half_as_ushort(a) | ((uint32_t)__half_as_ushort(b) << 16);
}
__device__ __forceinline__ uint32_t pack_single(float f0, float f1) {
    return pack_h2(__float2half_rn(f0), __float2half_rn(f1));
}
__device__ __forceinline__ void split_pair(float f0, float f1, uint32_t& hi, uint32_t& lo) {
    __half h0 = __float2half_rn(f0), h1 = __float2half_rn(f1);
    hi = pack_h2(h0, h1);
    lo = pack_h2(__float2half_rn(f0 - __half2float(h0)),
                 __float2half_rn(f1 - __half2float(h1)));
}

// ---------------------------------------------------------------------------
// Trig table (fp64 freqs to match JAX fp32 pow exactly)
// ---------------------------------------------------------------------------
__global__ void trig_kernel(const int* __restrict__ pos_ids) {
    int s = blockIdx.x;
    int i = threadIdx.x;
    double freq = 40.0 * pow(10000.0, -((double)(2*i)) / 128.0);
    float ang = (float)pos_ids[s] * (float)freq;
    g_cos[s*64 + i] = (float)cos((double)ang);
    g_sin[s*64 + i] = (float)sin((double)ang);
}

// ---------------------------------------------------------------------------
// elementwise fp32 -> single fp16
// ---------------------------------------------------------------------------
__global__ void cvt_half(const float* __restrict__ X, __half* __restrict__ H) {
    size_t i = ((size_t)blockIdx.x * 256 + threadIdx.x) * 4;
    float4 v = *(const float4*)(X + i);
    *(uint2*)(H + i) = make_uint2(pack_single(v.x, v.y), pack_single(v.z, v.w));
}

// ---------------------------------------------------------------------------
// Weight transpose: W[K][N] -> Thi[N][K] single fp16 (Tlo optional)
// ---------------------------------------------------------------------------
__global__ void transpose_cvt(const float* __restrict__ W,
                              __half* __restrict__ Thi,
                              __half* __restrict__ Tlo, int K, int N) {
    __shared__ float ts[32][33];
    int k0 = blockIdx.y * 32, n0 = blockIdx.x * 32;
    int tx = threadIdx.x & 31, ty = threadIdx.x >> 5;  // 32x8
#pragma unroll
    for (int i = 0; i < 4; i++)
        ts[ty + 8*i][tx] = W[(size_t)(k0 + ty + 8*i)*N + n0 + tx];
    __syncthreads();
#pragma unroll
    for (int i = 0; i < 4; i++) {
        int n = ty + 8*i;
        float v = ts[tx][n];
        __half hi = __float2half_rn(v);
        size_t o = (size_t)(n0 + n)*K + k0 + tx;
        Thi[o] = hi;
        if (Tlo) Tlo[o] = __float2half_rn(v - __half2float(hi));
    }
}

// ---------------------------------------------------------------------------
// fp16 GEMM, TERMS in {1,2} B-side terms, 3-stage cp.async pipeline.
// MODE 0: C fp32.
// MODE 1: N=NQA; cc<QCOLS: rope(q_pe) -> qH single; else fp32 -> g_kv.
// MODE 2: scatter split k_nope -> OH/OL, single v -> O2H (head-major).
// ---------------------------------------------------------------------------
#define GEMM_SMEM (3*32768)   // 96 KB

template<int MODE, int TERMS>
__global__ void __launch_bounds__(256)
mma_gemm_t(const __half* __restrict__ A,
           const __half* __restrict__ Bhi, const __half* __restrict__ Blo,
           float* __restrict__ C,
           __half* __restrict__ OH, __half* __restrict__ OL,
           __half* __restrict__ O2H,
           int M, int N, int K) {
    extern __shared__ char sm[];
    uint32_t sb = smem_u32(sm);
    const int tid = threadIdx.x, lane = tid & 31, wid = tid >> 5;
    const int row0 = blockIdx.y * 128, col0 = blockIdx.x * 128;
    const int wm = (wid >> 2) * 64, wn = (wid & 3) * 32;
    const int cps = K >> 6;
    const int NC = TERMS * cps;

    float acc[4][4][4];
#pragma unroll
    for (int mi = 0; mi < 4; mi++)
#pragma unroll
        for (int ni = 0; ni < 4; ni++)
#pragma unroll
            for (int r = 0; r < 4; r++) acc[mi][ni][r] = 0.f;

    auto load_chunk = [&](int c, int buf) {
        int sec = (TERMS == 2) ? (c >= cps) : 0;
        int cc = c - sec * cps;
        const __half* gA = A + (size_t)row0 * K + cc * 64;
        const __half* gB = (sec ? Blo : Bhi) + (size_t)col0 * K + cc * 64;
        uint32_t base = sb + (uint32_t)buf * 32768;
#pragma unroll
        for (int i = 0; i < 4; i++) {
            int idx = tid + i * 256;
            int r = idx >> 3, s = idx & 7;
            cp16(base + SWZ((uint32_t)(r * 128 + s * 16)), gA + (size_t)r * K + s * 8);
        }
#pragma unroll
        for (int i = 0; i < 4; i++) {
            int idx = tid + i * 256;
            int r = idx >> 3, s = idx & 7;
            cp16(base + 16384 + SWZ((uint32_t)(r * 128 + s * 16)), gB + (size_t)r * K + s * 8);
        }
    };

    load_chunk(0, 0); cp_commit();
    if (NC > 1) load_chunk(1, 1);
    cp_commit();

    for (int c = 0; c < NC; c++) {
        if (c + 2 < NC) load_chunk(c + 2, (c + 2) % 3);
        cp_commit();
        cp_wait2();
        __syncthreads();

        uint32_t sA = sb + (uint32_t)(c % 3) * 32768;
        uint32_t sB = sA + 16384;
        uint32_t Breg[4][4];
#pragma unroll
        for (int kk = 0; kk < 4; kk++) {
            if ((kk & 1) == 0) {
                int kh = kk >> 1;
#pragma unroll
                for (int ni = 0; ni < 4; ni++) {
                    uint32_t addr = sB + SWZ((uint32_t)((wn + ni*8 + (lane & 7)) * 128
                                                        + kh*64 + (lane >> 3) * 16));
                    ldsm_x4(Breg[ni], addr);
                }
            }
            uint32_t Areg[4][4];
#pragma unroll
            for (int mi = 0; mi < 4; mi++) {
                uint32_t addr = sA + SWZ((uint32_t)((wm + mi*16 + (lane & 15)) * 128
                                                    + kk*32 + (lane >> 4) * 16));
                ldsm_x4(Areg[mi], addr);
            }
#pragma unroll
            for (int mi = 0; mi < 4; mi++)
#pragma unroll
                for (int ni = 0; ni < 4; ni++)
                    mma16816(acc[mi][ni], Areg[mi], &Breg[ni][2 * (kk & 1)]);
        }
        __syncthreads();
    }

    // epilogue
#pragma unroll
    for (int mi = 0; mi < 4; mi++) {
        int r0 = row0 + wm + mi * 16 + (lane >> 2);
#pragma unroll
        for (int ni = 0; ni < 4; ni++) {
            int cc = col0 + wn + ni * 8 + (lane & 3) * 2;
            float a0 = acc[mi][ni][0], a1 = acc[mi][ni][1];
            float a2 = acc[mi][ni][2], a3 = acc[mi][ni][3];
            if (MODE == 0) {
                *(float2*)(C + (size_t)r0 * N + cc)       = make_float2(a0, a1);
                *(float2*)(C + (size_t)(r0 + 8) * N + cc) = make_float2(a2, a3);
            } else if (MODE == 1) {
                if (cc < QCOLS) {
                    int d = cc & 255;
                    if (d >= 128) {
                        int i = (d - 128) >> 1;
                        int s0 = r0 & (SS_-1), s1 = (r0 + 8) & (SS_-1);
                        float c0 = g_cos[s0*64 + i], sn0 = g_sin[s0*64 + i];
                        float c1 = g_cos[s1*64 + i], sn1 = g_sin[s1*64 + i];
                        float xr = a0, xi = a1;
                        a0 = xr*c0 - xi*sn0; a1 = xr*sn0 + xi*c0;
                        xr = a2; xi = a3;
                        a2 = xr*c1 - xi*sn1; a3 = xr*sn1 + xi*c1;
                    }
                    size_t o0 = (size_t)r0 * QCOLS + cc, o1 = (size_t)(r0 + 8) * QCOLS + cc;
                    *(uint32_t*)(OH + o0) = pack_single(a0, a1);
                    *(uint32_t*)(OH + o1) = pack_single(a2, a3);
                } else {
                    int kc = cc - QCOLS;
                    *(float2*)(C + (size_t)r0 * KVCOLS + kc)       = make_float2(a0, a1);
                    *(float2*)(C + (size_t)(r0 + 8) * KVCOLS + kc) = make_float2(a2, a3);
                }
            } else {
                int hk = cc >> 8, d = cc & 255;
                int b0 = r0 >> 11, s0 = r0 & (SS_-1);
                int b1 = (r0+8) >> 11, s1 = (r0+8) & (SS_-1);
                if (d < 128) {
                    uint32_t h0, l0, h1, l1;
                    split_pair(a0, a1, h0, l0);
                    split_pair(a2, a3, h1, l1);
                    size_t o0 = ((size_t)(b0*KVH + hk)*SS_ + s0)*256 + d;
                    size_t o1 = ((size_t)(b1*KVH + hk)*SS_ + s1)*256 + d;
                    *(uint32_t*)(OH + o0) = h0; *(uint32_t*)(OL + o0) = l0;
                    *(uint32_t*)(OH + o1) = h1; *(uint32_t*)(OL + o1) = l1;
                } else {
                    size_t o0 = ((size_t)(b0*KVH + hk)*SS_ + s0)*128 + (d - 128);
                    size_t o1 = ((size_t)(b1*KVH + hk)*SS_ + s1)*128 + (d - 128);
                    *(uint32_t*)(O2H + o0) = pack_single(a0, a1);
                    *(uint32_t*)(O2H + o1) = pack_single(a2, a3);
                }
            }
        }
    }
}

// ---------------------------------------------------------------------------
// LayerNorm -> kvc single fp16 ; RoPE(k_pe) -> split fp16 replicated into g_kH/L
// ---------------------------------------------------------------------------
__global__ void ln_rope_kv_kernel(const float* __restrict__ kvns) {
    int row = blockIdx.x;
    int tid = threadIdx.x;
    const float* x = g_kv + (size_t)row * KVCOLS;
    __shared__ float red[256];

    float v0 = x[tid], v1 = x[tid + 256];
    red[tid] = v0 + v1;
    __syncthreads();
#pragma unroll
    for (int off = 128; off > 0; off >>= 1) {
        if (tid < off) red[tid] += red[tid + off];
        __syncthreads();
    }
    float mean = red[0] * (1.f / 512.f);
    __syncthreads();
    float d0 = v0 - mean, d1 = v1 - mean;
    red[tid] = d0*d0 + d1*d1;
    __syncthreads();
#pragma unroll
    for (int off = 128; off > 0; off >>= 1) {
        if (tid < off) red[tid] += red[tid + off];
        __syncthreads();
    }
    float inv = rsqrtf(red[0] * (1.f / 512.f) + 1e-5f);
    size_t o = (size_t)row * KVR;
    g_kvcH[o + tid]       = __float2half_rn(d0 * inv * kvns[tid]);
    g_kvcH[o + tid + 256] = __float2half_rn(d1 * inv * kvns[tid + 256]);

    if (tid < 64) {
        int s = row & (SS_ - 1);
        int b = row >> 11;
        float c = g_cos[s*64 + tid], sn = g_sin[s*64 + tid];
        float xr = x[KVR + 2*tid], xi = x[KVR + 2*tid + 1];
        float k0 = xr*c - xi*sn, k1 = xr*sn + xi*c;
        uint32_t hh, ll;
        split_pair(k0, k1, hh, ll);
#pragma unroll
        for (int hk = 0; hk < KVH; hk++) {
            size_t base = ((size_t)(b*KVH + hk)*SS_ + s)*256 + 128 + 2*tid;
            *(uint32_t*)(g_kH + base) = hh;
            *(uint32_t*)(g_kL + base) = ll;
        }
    }
}

// ---------------------------------------------------------------------------
// Tensor-core flash attention (fp16): S = 2-term (Q single, K split),
// PV = 1-term (P single, V single). K double-buffered, V overlapped.
// ---------------------------------------------------------------------------
#define FA_QH_OFF 0                // 128 x 528 = 67584
#define FA_K0_OFF 67584            // two K stages of 33792 (hi 16896 + lo 16896)
#define FA_KSTG   33792
#define FA_V_OFF  135168           // single 8704
#define FA_SMEM   143872
#define QSTB 528
#define VSTB 272

__global__ void __launch_bounds__(256) fa_kernel() {
    const int tid = threadIdx.x, lane = tid & 31, wid = tid >> 5;
    const int b = blockIdx.x >> 4, h = blockIdx.x & 15, hk = h >> 1;
    const int qt = 15 - (int)blockIdx.y;   // big tiles first
    extern __shared__ char sm[];
    uint32_t sb = smem_u32(sm);

    const size_t kbase = (size_t)(b*KVH + hk) * SS_;
    const int NKT = 4*qt + 4;

    auto loadK = [&](int kt, int buf) {
        uint32_t kb = sb + FA_K0_OFF + (uint32_t)buf * FA_KSTG;
        const __half* khp = g_kH + (kbase + kt*32)*256;
        const __half* klp = g_kL + (kbase + kt*32)*256;
#pragma unroll
        for (int i = 0; i < 4; i++) {
            int idx = tid + i*256, r = idx >> 5, c = idx & 31;
            cp16(kb + r*QSTB + c*16,         khp + (size_t)r*256 + c*8);
            cp16(kb + 16896 + r*QSTB + c*16, klp + (size_t)r*256 + c*8);
        }
    };
    auto loadV = [&](int kt) {
        const __half* vhp = g_vH + (kbase + kt*32)*128;
#pragma unroll
        for (int i = 0; i < 2; i++) {
            int idx = tid + i*256, r = idx >> 4, c = idx & 15;
            cp16(sb + FA_V_OFF + r*VSTB + c*16, vhp + (size_t)r*128 + c*8);
        }
    };

    // prologue: Q, K0, V0 (three commit groups)
    {
        const __half* qh = g_qH + ((size_t)(b*SS_ + qt*128))*QCOLS + h*256;
#pragma unroll
        for (int i = 0; i < 16; i++) {
            int idx = tid + i*256, r = idx >> 5, c = idx & 31;
            cp16(sb + FA_QH_OFF + r*QSTB + c*16, qh + (size_t)r*QCOLS + c*8);
        }
        cp_commit();
    }
    loadK(0, 0); cp_commit();
    loadV(0);    cp_commit();

    const int wm = wid * 16;
    float mrow0 = -1e30f, mrow1 = -1e30f;
    float lrow0 = 0.f, lrow1 = 0.f;
    float o[16][4];
#pragma unroll
    for (int nf = 0; nf < 16; nf++)
#pragma unroll
        for (int e = 0; e < 4; e++) o[nf][e] = 0.f;

    const float scale = 0.08838834764831845f;

    for (int kt = 0; kt < NKT; kt++) {
        cp_wait1();              // Q+K(kt) done; V(kt) may be in flight
        __syncthreads();
        if (kt + 1 < NKT) loadK(kt + 1, (kt + 1) & 1);
        cp_commit();

        uint32_t kbuf = sb + FA_K0_OFF + (uint32_t)(kt & 1) * FA_KSTG;

        // ---- S = Q K^T (2 terms: Qh*Kh + Qh*Kl) ----
        float s4[4][4];
#pragma unroll
        for (int f = 0; f < 4; f++)
#pragma unroll
            for (int e = 0; e < 4; e++) s4[f][e] = 0.f;

#pragma unroll
        for (int kc = 0; kc < 16; kc++) {
            uint32_t ah[4];
            uint32_t aaddr = sb + FA_QH_OFF + (uint32_t)(wm + (lane & 15))*QSTB
                             + (uint32_t)(kc*16 + (lane >> 4)*8)*2;
            ldsm_x4(ah, aaddr);
#pragma unroll
            for (int nb = 0; nb < 2; nb++) {
                uint32_t baddr = kbuf
                    + (uint32_t)(nb*16 + (lane >> 4)*8 + (lane & 7))*QSTB
                    + (uint32_t)(kc*16 + ((lane >> 3) & 1)*8)*2;
                uint32_t bh[4], bl[4];
                ldsm_x4(bh, baddr);
                ldsm_x4(bl, baddr + 16896);
                mma16816(s4[2*nb],   ah, bh); mma16816(s4[2*nb+1], ah, bh+2);
                mma16816(s4[2*nb],   ah, bl); mma16816(s4[2*nb+1], ah, bl+2);
            }
        }

        // ---- scale + causal mask ----
        if (kt >= 4*qt) {
            int grow0 = qt*128 + wm + (lane >> 2);
#pragma unroll
            for (int f = 0; f < 4; f++)
#pragma unroll
                for (int e = 0; e < 4; e++) {
                    int col = kt*32 + f*8 + (lane & 3)*2 + (e & 1);
                    int row = grow0 + (e >> 1)*8;
                    float v = s4[f][e] * scale;
                    s4[f][e] = (col > row) ? -1e9f : v;
                }
        } else {
#pragma unroll
            for (int f = 0; f < 4; f++)
#pragma unroll
                for (int e = 0; e < 4; e++) s4[f][e] *= scale;
        }

        // ---- online softmax ----
        float rm0 = -1e30f, rm1 = -1e30f;
#pragma unroll
        for (int f = 0; f < 4; f++) {
            rm0 = fmaxf(rm0, fmaxf(s4[f][0], s4[f][1]));
            rm1 = fmaxf(rm1, fmaxf(s4[f][2], s4[f][3]));
        }
        rm0 = fmaxf(rm0, __shfl_xor_sync(0xffffffffu, rm0, 1));
        rm0 = fmaxf(rm0, __shfl_xor_sync(0xffffffffu, rm0, 2));
        rm1 = fmaxf(rm1, __shfl_xor_sync(0xffffffffu, rm1, 1));
        rm1 = fmaxf(rm1, __shfl_xor_sync(0xffffffffu, rm1, 2));
        float mn0 = fmaxf(mrow0, rm0), mn1 = fmaxf(mrow1, rm1);
        float al0 = __expf(mrow0 - mn0), al1 = __expf(mrow1 - mn1);
        float rs0 = 0.f, rs1 = 0.f;
#pragma unroll
        for (int f = 0; f < 4; f++) {
            s4[f][0] = __expf(s4[f][0] - mn0); rs0 += s4[f][0];
            s4[f][1] = __expf(s4[f][1] - mn0); rs0 += s4[f][1];
            s4[f][2] = __expf(s4[f][2] - mn1); rs1 += s4[f][2];
            s4[f][3] = __expf(s4[f][3] - mn1); rs1 += s4[f][3];
        }
        rs0 += __shfl_xor_sync(0xffffffffu, rs0, 1);
        rs0 += __shfl_xor_sync(0xffffffffu, rs0, 2);
        rs1 += __shfl_xor_sync(0xffffffffu, rs1, 1);
        rs1 += __shfl_xor_sync(0xffffffffu, rs1, 2);
        lrow0 = lrow0*al0 + rs0; mrow0 = mn0;
        lrow1 = lrow1*al1 + rs1; mrow1 = mn1;

#pragma unroll
        for (int nf = 0; nf < 16; nf++) {
            o[nf][0] *= al0; o[nf][1] *= al0;
            o[nf][2] *= al1; o[nf][3] *= al1;
        }

        // ---- P fragments (single fp16) ----
        uint32_t ph[2][4];
#pragma unroll
        for (int c = 0; c < 2; c++) {
#pragma unroll
            for (int g = 0; g < 2; g++) {
                ph[c][2*g]   = pack_single(s4[2*c+g][0], s4[2*c+g][1]);
                ph[c][2*g+1] = pack_single(s4[2*c+g][2], s4[2*c+g][3]);
            }
        }

        // V(kt) ready; K(kt+1) may still be in flight
        cp_wait1();
        __syncthreads();

        // ---- O += P V (1 term) ----
#pragma unroll
        for (int c = 0; c < 2; c++) {
#pragma unroll
            for (int nb = 0; nb < 8; nb++) {
                uint32_t vaddr = sb + FA_V_OFF
                    + (uint32_t)(c*16 + ((lane >> 3) & 1)*8 + (lane & 7))*VSTB
                    + (uint32_t)(nb*16 + (lane >> 4)*8)*2;
                uint32_t bh[4];
                ldsm_x4_t(bh, vaddr);
                mma16816(o[2*nb],   ph[c], bh);
                mma16816(o[2*nb+1], ph[c], bh+2);
            }
        }

        __syncthreads();                 // all warps done reading V buffer
        if (kt + 1 < NKT) loadV(kt + 1);
        cp_commit();
    }

    // ---- epilogue: normalize, stage in SMEM, write single fp16 ----
    __syncthreads();
    float inv0 = 1.f / lrow0, inv1 = 1.f / lrow1;
    float* st = (float*)sm;   // reuse Q area (128 x 132 floats = 67584 B)
#pragma unroll
    for (int nf = 0; nf < 16; nf++) {
        int c0 = nf*8 + (lane & 3)*2;
        int r0 = wm + (lane >> 2);
        *(float2*)&st[r0*132 + c0]       = make_float2(o[nf][0]*inv0, o[nf][1]*inv0);
        *(float2*)&st[(r0 + 8)*132 + c0] = make_float2(o[nf][2]*inv1, o[nf][3]*inv1);
    }
    __syncthreads();
#pragma unroll
    for (int i = 0; i < 32; i++) {
        int idx = tid + i*256, r = idx >> 6, c = (idx & 63)*2;
        float f0 = st[r*132 + c], f1 = st[r*132 + c + 1];
        size_t off = ((size_t)(b*SS_ + qt*128 + r))*(HH*HD) + h*128 + c;
        *(uint32_t*)(g_attnH + off) = pack_single(f0, f1);
    }
}

// ---------------------------------------------------------------------------
extern "C" void kernel_launch(void* const* d_in, const int* in_sizes, int n_in,
                              void* d_out, int out_size) {
    const float* x     = (const float*)d_in[0];
    const float* wq    = (const float*)d_in[1];
    const float* wkv_a = (const float*)d_in[2];
    const float* kvns  = (const float*)d_in[3];
    const float* wkv_b = (const float*)d_in[4];
    const float* wo    = (const float*)d_in[5];
    const int*   pos   = (const int*)d_in[7];
    float* out = (float*)d_out;

    float *kv;
    cudaGetSymbolAddress((void**)&kv, g_kv);
    __half *xH,*kvcH,*attnH,*qH,*kH,*kL,*vH;
    cudaGetSymbolAddress((void**)&xH,    g_xH);
    cudaGetSymbolAddress((void**)&kvcH,  g_kvcH);
    cudaGetSymbolAddress((void**)&attnH, g_attnH);
    cudaGetSymbolAddress((void**)&qH,    g_qH);
    cudaGetSymbolAddress((void**)&kH,    g_kH);    cudaGetSymbolAddress((void**)&kL, g_kL);
    cudaGetSymbolAddress((void**)&vH,    g_vH);
    __half *wqah,*wbh,*wbl,*woh;
    cudaGetSymbolAddress((void**)&wqah, g_wqaT_hi);
    cudaGetSymbolAddress((void**)&wbh,  g_wbT_hi);  cudaGetSymbolAddress((void**)&wbl, g_wbT_lo);
    cudaGetSymbolAddress((void**)&woh,  g_woT_hi);

    cudaFuncSetAttribute((const void*)mma_gemm_t<0,1>, cudaFuncAttributeMaxDynamicSharedMemorySize, GEMM_SMEM);
    cudaFuncSetAttribute((const void*)mma_gemm_t<1,1>, cudaFuncAttributeMaxDynamicSharedMemorySize, GEMM_SMEM);
    cudaFuncSetAttribute((const void*)mma_gemm_t<2,2>, cudaFuncAttributeMaxDynamicSharedMemorySize, GEMM_SMEM);
    cudaFuncSetAttribute(fa_kernel, cudaFuncAttributeMaxDynamicSharedMemorySize, FA_SMEM);

    trig_kernel<<<SS_, 64>>>(pos);

    // weight transpose (wq/wkv_a and wo single fp16; wkv_b split)
    transpose_cvt<<<dim3(QCOLS/32,  DD/32),  256>>>(wq,    wqah, nullptr, DD, QCOLS);
    transpose_cvt<<<dim3(KVCOLS/32, DD/32),  256>>>(wkv_a, wqah + (size_t)QCOLS*DD,
                                                            nullptr, DD, KVCOLS);
    transpose_cvt<<<dim3(KVBCOLS/32,KVR/32), 256>>>(wkv_b, wbh, wbl, KVR, KVBCOLS);
    transpose_cvt<<<dim3(DD/32, (HH*HD)/32), 256>>>(wo,    woh, nullptr, HH*HD, DD);

    // x -> single fp16
    cvt_half<<<((size_t)ROWS*DD)/1024, 256>>>(x, xH);

    // [q | kv] = x @ [wq | wkv_a]  (1-term; rope q -> qH single, fp32 kv)
    mma_gemm_t<1,1><<<dim3(NQA/128, ROWS/128), 256, GEMM_SMEM>>>(
        xH, wqah, nullptr, kv, qH, nullptr, nullptr, ROWS, NQA, DD);
    // layernorm -> kvc fp16 ; roped k_pe -> g_kH/g_kL (replicated)
    ln_rope_kv_kernel<<<ROWS, 256>>>(kvns);
    // kvb = kv_c @ wkv_b (2-term) -> split k_nope, single v, head-major
    mma_gemm_t<2,2><<<dim3(KVBCOLS/128, ROWS/128), 256, GEMM_SMEM>>>(
        kvcH, wbh, wbl, nullptr, kH, kL, vH, ROWS, KVBCOLS, KVR);
    // flash attention (fp16 tensor cores)
    fa_kernel<<<dim3(BB*HH, SS_/128), 256, FA_SMEM>>>();
    // out = attn @ wo (1-term)
    mma_gemm_t<0,1><<<dim3(DD/128, ROWS/128), 256, GEMM_SMEM>>>(
        attnH, woh, nullptr, out, nullptr, nullptr, nullptr, ROWS, DD, HH*HD);
}

// round 12
// speedup vs baseline: 8.9257x; 1.2165x over previous
#include <cuda_runtime.h>
#include <cuda_fp16.h>
#include <math.h>
#include <cstdint>

// Problem constants
#define BB 2
#define SS_ 2048
#define DD 2048
#define HH 16
#define KVH 8
#define HD 128
#define KVR 512
#define ROWS (BB*SS_)          // 4096
#define QCOLS (HH*2*HD)        // 4096
#define KVCOLS (KVR+HD)        // 640
#define NQA (QCOLS+KVCOLS)     // 4736
#define KVBCOLS (KVH*2*HD)     // 2048

// fp32 scratch
__device__ float g_kv  [(size_t)ROWS*KVCOLS];
__device__ float g_cos [SS_*64];
__device__ float g_sin [SS_*64];

// fp16 activations (all single precision fp16 now except none split)
__device__ __half g_xH   [(size_t)ROWS*DD];
__device__ __half g_kvcH [(size_t)ROWS*KVR];
__device__ __half g_attnH[(size_t)ROWS*(HH*HD)];
__device__ __half g_qH   [(size_t)ROWS*QCOLS];
__device__ __half g_kH   [(size_t)BB*KVH*SS_*256];
__device__ __half g_vH   [(size_t)BB*KVH*SS_*128];

// transposed fp16 weights  WT[n][k] (all single fp16)
__device__ __half g_wqaT_hi[(size_t)NQA*DD];      // wq ++ wkv_a
__device__ __half g_wbT_hi[(size_t)KVBCOLS*KVR];
__device__ __half g_woT_hi[(size_t)DD*(HH*HD)];

// ---------------------------------------------------------------------------
// helpers
// ---------------------------------------------------------------------------
__device__ __forceinline__ uint32_t smem_u32(const void* p) {
    uint32_t a;
    asm("{ .reg .u64 t; cvta.to.shared.u64 t, %1; cvt.u32.u64 %0, t; }"
        : "=r"(a) : "l"(p));
    return a;
}
#define SWZ(o) ((o) ^ (((o) >> 3) & 0x70))

__device__ __forceinline__ void cp16(uint32_t dst, const void* src) {
    asm volatile("cp.async.cg.shared.global [%0], [%1], 16;" :: "r"(dst), "l"(src));
}
__device__ __forceinline__ void cp_commit() {
    asm volatile("cp.async.commit_group;" ::: "memory");
}
__device__ __forceinline__ void cp_wait1() {
    asm volatile("cp.async.wait_group 1;" ::: "memory");
}
__device__ __forceinline__ void cp_wait2() {
    asm volatile("cp.async.wait_group 2;" ::: "memory");
}
__device__ __forceinline__ void ldsm_x4(uint32_t (&r)[4], uint32_t addr) {
    asm volatile("ldmatrix.sync.aligned.m8n8.x4.shared.b16 {%0,%1,%2,%3}, [%4];"
                 : "=r"(r[0]), "=r"(r[1]), "=r"(r[2]), "=r"(r[3]) : "r"(addr));
}
__device__ __forceinline__ void ldsm_x4_t(uint32_t (&r)[4], uint32_t addr) {
    asm volatile("ldmatrix.sync.aligned.m8n8.x4.trans.shared.b16 {%0,%1,%2,%3}, [%4];"
                 : "=r"(r[0]), "=r"(r[1]), "=r"(r[2]), "=r"(r[3]) : "r"(addr));
}
__device__ __forceinline__ void mma16816(float* d, const uint32_t* a, const uint32_t* b) {
    asm volatile(
        "mma.sync.aligned.m16n8k16.row.col.f32.f16.f16.f32 "
        "{%0,%1,%2,%3},{%4,%5,%6,%7},{%8,%9},{%0,%1,%2,%3};"
        : "+f"(d[0]), "+f"(d[1]), "+f"(d[2]), "+f"(d[3])
        : "r"(a[0]), "r"(a[1]), "r"(a[2]), "r"(a[3]), "r"(b[0]), "r"(b[1]));
}
__device__ __forceinline__ uint32_t pack_h2(__half a, __half b) {
    return (uint32_t)__half_as_ushort(a) | ((uint32_t)__half_as_ushort(b) << 16);
}
__device__ __forceinline__ uint32_t pack_single(float f0, float f1) {
    return pack_h2(__float2half_rn(f0), __float2half_rn(f1));
}

// ---------------------------------------------------------------------------
// Trig table (fp64 freqs to match JAX fp32 pow exactly)
// ---------------------------------------------------------------------------
__global__ void trig_kernel(const int* __restrict__ pos_ids) {
    int s = blockIdx.x;
    int i = threadIdx.x;
    double freq = 40.0 * pow(10000.0, -((double)(2*i)) / 128.0);
    float ang = (float)pos_ids[s] * (float)freq;
    g_cos[s*64 + i] = (float)cos((double)ang);
    g_sin[s*64 + i] = (float)sin((double)ang);
}

// ---------------------------------------------------------------------------
// elementwise fp32 -> single fp16
// ---------------------------------------------------------------------------
__global__ void cvt_half(const float* __restrict__ X, __half* __restrict__ H) {
    size_t i = ((size_t)blockIdx.x * 256 + threadIdx.x) * 4;
    float4 v = *(const float4*)(X + i);
    *(uint2*)(H + i) = make_uint2(pack_single(v.x, v.y), pack_single(v.z, v.w));
}

// ---------------------------------------------------------------------------
// Weight transpose: W[K][N] -> T[N][K] single fp16
// ---------------------------------------------------------------------------
__global__ void transpose_cvt(const float* __restrict__ W,
                              __half* __restrict__ T, int K, int N) {
    __shared__ float ts[32][33];
    int k0 = blockIdx.y * 32, n0 = blockIdx.x * 32;
    int tx = threadIdx.x & 31, ty = threadIdx.x >> 5;  // 32x8
#pragma unroll
    for (int i = 0; i < 4; i++)
        ts[ty + 8*i][tx] = W[(size_t)(k0 + ty + 8*i)*N + n0 + tx];
    __syncthreads();
#pragma unroll
    for (int i = 0; i < 4; i++) {
        int n = ty + 8*i;
        T[(size_t)(n0 + n)*K + k0 + tx] = __float2half_rn(ts[tx][n]);
    }
}

// ---------------------------------------------------------------------------
// fp16 GEMM (1 term), 3-stage cp.async pipeline.
// MODE 0: C fp32.
// MODE 1: N=NQA; cc<QCOLS: rope(q_pe) -> qH; else fp32 -> g_kv.
// MODE 2: scatter k_nope -> OH, v -> O2H (head-major, single fp16).
// ---------------------------------------------------------------------------
#define GEMM_SMEM (3*32768)   // 96 KB

template<int MODE>
__global__ void __launch_bounds__(256)
mma_gemm_t(const __half* __restrict__ A,
           const __half* __restrict__ B,
           float* __restrict__ C,
           __half* __restrict__ OH, __half* __restrict__ O2H,
           int M, int N, int K) {
    extern __shared__ char sm[];
    uint32_t sb = smem_u32(sm);
    const int tid = threadIdx.x, lane = tid & 31, wid = tid >> 5;
    const int row0 = blockIdx.y * 128, col0 = blockIdx.x * 128;
    const int wm = (wid >> 2) * 64, wn = (wid & 3) * 32;
    const int NC = K >> 6;

    float acc[4][4][4];
#pragma unroll
    for (int mi = 0; mi < 4; mi++)
#pragma unroll
        for (int ni = 0; ni < 4; ni++)
#pragma unroll
            for (int r = 0; r < 4; r++) acc[mi][ni][r] = 0.f;

    auto load_chunk = [&](int cc, int buf) {
        const __half* gA = A + (size_t)row0 * K + cc * 64;
        const __half* gB = B + (size_t)col0 * K + cc * 64;
        uint32_t base = sb + (uint32_t)buf * 32768;
#pragma unroll
        for (int i = 0; i < 4; i++) {
            int idx = tid + i * 256;
            int r = idx >> 3, s = idx & 7;
            cp16(base + SWZ((uint32_t)(r * 128 + s * 16)), gA + (size_t)r * K + s * 8);
        }
#pragma unroll
        for (int i = 0; i < 4; i++) {
            int idx = tid + i * 256;
            int r = idx >> 3, s = idx & 7;
            cp16(base + 16384 + SWZ((uint32_t)(r * 128 + s * 16)), gB + (size_t)r * K + s * 8);
        }
    };

    load_chunk(0, 0); cp_commit();
    if (NC > 1) load_chunk(1, 1);
    cp_commit();

    for (int c = 0; c < NC; c++) {
        if (c + 2 < NC) load_chunk(c + 2, (c + 2) % 3);
        cp_commit();
        cp_wait2();
        __syncthreads();

        uint32_t sA = sb + (uint32_t)(c % 3) * 32768;
        uint32_t sB = sA + 16384;
        uint32_t Breg[4][4];
#pragma unroll
        for (int kk = 0; kk < 4; kk++) {
            if ((kk & 1) == 0) {
                int kh = kk >> 1;
#pragma unroll
                for (int ni = 0; ni < 4; ni++) {
                    uint32_t addr = sB + SWZ((uint32_t)((wn + ni*8 + (lane & 7)) * 128
                                                        + kh*64 + (lane >> 3) * 16));
                    ldsm_x4(Breg[ni], addr);
                }
            }
            uint32_t Areg[4][4];
#pragma unroll
            for (int mi = 0; mi < 4; mi++) {
                uint32_t addr = sA + SWZ((uint32_t)((wm + mi*16 + (lane & 15)) * 128
                                                    + kk*32 + (lane >> 4) * 16));
                ldsm_x4(Areg[mi], addr);
            }
#pragma unroll
            for (int mi = 0; mi < 4; mi++)
#pragma unroll
                for (int ni = 0; ni < 4; ni++)
                    mma16816(acc[mi][ni], Areg[mi], &Breg[ni][2 * (kk & 1)]);
        }
        __syncthreads();
    }

    // epilogue
#pragma unroll
    for (int mi = 0; mi < 4; mi++) {
        int r0 = row0 + wm + mi * 16 + (lane >> 2);
#pragma unroll
        for (int ni = 0; ni < 4; ni++) {
            int cc = col0 + wn + ni * 8 + (lane & 3) * 2;
            float a0 = acc[mi][ni][0], a1 = acc[mi][ni][1];
            float a2 = acc[mi][ni][2], a3 = acc[mi][ni][3];
            if (MODE == 0) {
                *(float2*)(C + (size_t)r0 * N + cc)       = make_float2(a0, a1);
                *(float2*)(C + (size_t)(r0 + 8) * N + cc) = make_float2(a2, a3);
            } else if (MODE == 1) {
                if (cc < QCOLS) {
                    int d = cc & 255;
                    if (d >= 128) {
                        int i = (d - 128) >> 1;
                        int s0 = r0 & (SS_-1), s1 = (r0 + 8) & (SS_-1);
                        float c0 = g_cos[s0*64 + i], sn0 = g_sin[s0*64 + i];
                        float c1 = g_cos[s1*64 + i], sn1 = g_sin[s1*64 + i];
                        float xr = a0, xi = a1;
                        a0 = xr*c0 - xi*sn0; a1 = xr*sn0 + xi*c0;
                        xr = a2; xi = a3;
                        a2 = xr*c1 - xi*sn1; a3 = xr*sn1 + xi*c1;
                    }
                    size_t o0 = (size_t)r0 * QCOLS + cc, o1 = (size_t)(r0 + 8) * QCOLS + cc;
                    *(uint32_t*)(OH + o0) = pack_single(a0, a1);
                    *(uint32_t*)(OH + o1) = pack_single(a2, a3);
                } else {
                    int kc = cc - QCOLS;
                    *(float2*)(C + (size_t)r0 * KVCOLS + kc)       = make_float2(a0, a1);
                    *(float2*)(C + (size_t)(r0 + 8) * KVCOLS + kc) = make_float2(a2, a3);
                }
            } else {
                int hk = cc >> 8, d = cc & 255;
                int b0 = r0 >> 11, s0 = r0 & (SS_-1);
                int b1 = (r0+8) >> 11, s1 = (r0+8) & (SS_-1);
                if (d < 128) {
                    size_t o0 = ((size_t)(b0*KVH + hk)*SS_ + s0)*256 + d;
                    size_t o1 = ((size_t)(b1*KVH + hk)*SS_ + s1)*256 + d;
                    *(uint32_t*)(OH + o0) = pack_single(a0, a1);
                    *(uint32_t*)(OH + o1) = pack_single(a2, a3);
                } else {
                    size_t o0 = ((size_t)(b0*KVH + hk)*SS_ + s0)*128 + (d - 128);
                    size_t o1 = ((size_t)(b1*KVH + hk)*SS_ + s1)*128 + (d - 128);
                    *(uint32_t*)(O2H + o0) = pack_single(a0, a1);
                    *(uint32_t*)(O2H + o1) = pack_single(a2, a3);
                }
            }
        }
    }
}

// ---------------------------------------------------------------------------
// LayerNorm -> kvc single fp16 ; RoPE(k_pe) -> single fp16 replicated into g_kH
// ---------------------------------------------------------------------------
__global__ void ln_rope_kv_kernel(const float* __restrict__ kvns) {
    int row = blockIdx.x;
    int tid = threadIdx.x;
    const float* x = g_kv + (size_t)row * KVCOLS;
    __shared__ float red[256];

    float v0 = x[tid], v1 = x[tid + 256];
    red[tid] = v0 + v1;
    __syncthreads();
#pragma unroll
    for (int off = 128; off > 0; off >>= 1) {
        if (tid < off) red[tid] += red[tid + off];
        __syncthreads();
    }
    float mean = red[0] * (1.f / 512.f);
    __syncthreads();
    float d0 = v0 - mean, d1 = v1 - mean;
    red[tid] = d0*d0 + d1*d1;
    __syncthreads();
#pragma unroll
    for (int off = 128; off > 0; off >>= 1) {
        if (tid < off) red[tid] += red[tid + off];
        __syncthreads();
    }
    float inv = rsqrtf(red[0] * (1.f / 512.f) + 1e-5f);
    size_t o = (size_t)row * KVR;
    g_kvcH[o + tid]       = __float2half_rn(d0 * inv * kvns[tid]);
    g_kvcH[o + tid + 256] = __float2half_rn(d1 * inv * kvns[tid + 256]);

    if (tid < 64) {
        int s = row & (SS_ - 1);
        int b = row >> 11;
        float c = g_cos[s*64 + tid], sn = g_sin[s*64 + tid];
        float xr = x[KVR + 2*tid], xi = x[KVR + 2*tid + 1];
        uint32_t hh = pack_single(xr*c - xi*sn, xr*sn + xi*c);
#pragma unroll
        for (int hk = 0; hk < KVH; hk++) {
            size_t base = ((size_t)(b*KVH + hk)*SS_ + s)*256 + 128 + 2*tid;
            *(uint32_t*)(g_kH + base) = hh;
        }
    }
}

// ---------------------------------------------------------------------------
// Tensor-core flash attention (fp16): S = 1 term, PV = 1 term.
// K double-buffered, V overlapped. SMEM 110 KB -> up to 2 CTAs/SM.
// ---------------------------------------------------------------------------
#define FA_QH_OFF 0                // 128 x 528 = 67584
#define FA_K0_OFF 67584            // two K stages of 16896
#define FA_KSTG   16896
#define FA_V_OFF  101376           // 8704
#define FA_SMEM   110080
#define QSTB 528
#define VSTB 272

__global__ void __launch_bounds__(256) fa_kernel() {
    const int tid = threadIdx.x, lane = tid & 31, wid = tid >> 5;
    const int b = blockIdx.x >> 4, h = blockIdx.x & 15, hk = h >> 1;
    const int qt = 15 - (int)blockIdx.y;   // big tiles first
    extern __shared__ char sm[];
    uint32_t sb = smem_u32(sm);

    const size_t kbase = (size_t)(b*KVH + hk) * SS_;
    const int NKT = 4*qt + 4;

    auto loadK = [&](int kt, int buf) {
        uint32_t kb = sb + FA_K0_OFF + (uint32_t)buf * FA_KSTG;
        const __half* khp = g_kH + (kbase + kt*32)*256;
#pragma unroll
        for (int i = 0; i < 4; i++) {
            int idx = tid + i*256, r = idx >> 5, c = idx & 31;
            cp16(kb + r*QSTB + c*16, khp + (size_t)r*256 + c*8);
        }
    };
    auto loadV = [&](int kt) {
        const __half* vhp = g_vH + (kbase + kt*32)*128;
#pragma unroll
        for (int i = 0; i < 2; i++) {
            int idx = tid + i*256, r = idx >> 4, c = idx & 15;
            cp16(sb + FA_V_OFF + r*VSTB + c*16, vhp + (size_t)r*128 + c*8);
        }
    };

    // prologue: Q, K0, V0 (three commit groups)
    {
        const __half* qh = g_qH + ((size_t)(b*SS_ + qt*128))*QCOLS + h*256;
#pragma unroll
        for (int i = 0; i < 16; i++) {
            int idx = tid + i*256, r = idx >> 5, c = idx & 31;
            cp16(sb + FA_QH_OFF + r*QSTB + c*16, qh + (size_t)r*QCOLS + c*8);
        }
        cp_commit();
    }
    loadK(0, 0); cp_commit();
    loadV(0);    cp_commit();

    const int wm = wid * 16;
    float mrow0 = -1e30f, mrow1 = -1e30f;
    float lrow0 = 0.f, lrow1 = 0.f;
    float o[16][4];
#pragma unroll
    for (int nf = 0; nf < 16; nf++)
#pragma unroll
        for (int e = 0; e < 4; e++) o[nf][e] = 0.f;

    const float scale = 0.08838834764831845f;

    for (int kt = 0; kt < NKT; kt++) {
        cp_wait1();              // Q+K(kt) done; V(kt) may be in flight
        __syncthreads();
        if (kt + 1 < NKT) loadK(kt + 1, (kt + 1) & 1);
        cp_commit();

        uint32_t kbuf = sb + FA_K0_OFF + (uint32_t)(kt & 1) * FA_KSTG;

        // ---- S = Q K^T (1 term) ----
        float s4[4][4];
#pragma unroll
        for (int f = 0; f < 4; f++)
#pragma unroll
            for (int e = 0; e < 4; e++) s4[f][e] = 0.f;

#pragma unroll
        for (int kc = 0; kc < 16; kc++) {
            uint32_t ah[4];
            uint32_t aaddr = sb + FA_QH_OFF + (uint32_t)(wm + (lane & 15))*QSTB
                             + (uint32_t)(kc*16 + (lane >> 4)*8)*2;
            ldsm_x4(ah, aaddr);
#pragma unroll
            for (int nb = 0; nb < 2; nb++) {
                uint32_t baddr = kbuf
                    + (uint32_t)(nb*16 + (lane >> 4)*8 + (lane & 7))*QSTB
                    + (uint32_t)(kc*16 + ((lane >> 3) & 1)*8)*2;
                uint32_t bh[4];
                ldsm_x4(bh, baddr);
                mma16816(s4[2*nb],   ah, bh);
                mma16816(s4[2*nb+1], ah, bh+2);
            }
        }

        // ---- scale + causal mask ----
        if (kt >= 4*qt) {
            int grow0 = qt*128 + wm + (lane >> 2);
#pragma unroll
            for (int f = 0; f < 4; f++)
#pragma unroll
                for (int e = 0; e < 4; e++) {
                    int col = kt*32 + f*8 + (lane & 3)*2 + (e & 1);
                    int row = grow0 + (e >> 1)*8;
                    float v = s4[f][e] * scale;
                    s4[f][e] = (col > row) ? -1e9f : v;
                }
        } else {
#pragma unroll
            for (int f = 0; f < 4; f++)
#pragma unroll
                for (int e = 0; e < 4; e++) s4[f][e] *= scale;
        }

        // ---- online softmax ----
        float rm0 = -1e30f, rm1 = -1e30f;
#pragma unroll
        for (int f = 0; f < 4; f++) {
            rm0 = fmaxf(rm0, fmaxf(s4[f][0], s4[f][1]));
            rm1 = fmaxf(rm1, fmaxf(s4[f][2], s4[f][3]));
        }
        rm0 = fmaxf(rm0, __shfl_xor_sync(0xffffffffu, rm0, 1));
        rm0 = fmaxf(rm0, __shfl_xor_sync(0xffffffffu, rm0, 2));
        rm1 = fmaxf(rm1, __shfl_xor_sync(0xffffffffu, rm1, 1));
        rm1 = fmaxf(rm1, __shfl_xor_sync(0xffffffffu, rm1, 2));
        float mn0 = fmaxf(mrow0, rm0), mn1 = fmaxf(mrow1, rm1);
        float al0 = __expf(mrow0 - mn0), al1 = __expf(mrow1 - mn1);
        float rs0 = 0.f, rs1 = 0.f;
#pragma unroll
        for (int f = 0; f < 4; f++) {
            s4[f][0] = __expf(s4[f][0] - mn0); rs0 += s4[f][0];
            s4[f][1] = __expf(s4[f][1] - mn0); rs0 += s4[f][1];
            s4[f][2] = __expf(s4[f][2] - mn1); rs1 += s4[f][2];
            s4[f][3] = __expf(s4[f][3] - mn1); rs1 += s4[f][3];
        }
        rs0 += __shfl_xor_sync(0xffffffffu, rs0, 1);
        rs0 += __shfl_xor_sync(0xffffffffu, rs0, 2);
        rs1 += __shfl_xor_sync(0xffffffffu, rs1, 1);
        rs1 += __shfl_xor_sync(0xffffffffu, rs1, 2);
        lrow0 = lrow0*al0 + rs0; mrow0 = mn0;
        lrow1 = lrow1*al1 + rs1; mrow1 = mn1;

#pragma unroll
        for (int nf = 0; nf < 16; nf++) {
            o[nf][0] *= al0; o[nf][1] *= al0;
            o[nf][2] *= al1; o[nf][3] *= al1;
        }

        // ---- P fragments (single fp16) ----
        uint32_t ph[2][4];
#pragma unroll
        for (int c = 0; c < 2; c++) {
#pragma unroll
            for (int g = 0; g < 2; g++) {
                ph[c][2*g]   = pack_single(s4[2*c+g][0], s4[2*c+g][1]);
                ph[c][2*g+1] = pack_single(s4[2*c+g][2], s4[2*c+g][3]);
            }
        }

        // V(kt) ready; K(kt+1) may still be in flight
        cp_wait1();
        __syncthreads();

        // ---- O += P V (1 term) ----
#pragma unroll
        for (int c = 0; c < 2; c++) {
#pragma unroll
            for (int nb = 0; nb < 8; nb++) {
                uint32_t vaddr = sb + FA_V_OFF
                    + (uint32_t)(c*16 + ((lane >> 3) & 1)*8 + (lane & 7))*VSTB
                    + (uint32_t)(nb*16 + (lane >> 4)*8)*2;
                uint32_t bh[4];
                ldsm_x4_t(bh, vaddr);
                mma16816(o[2*nb],   ph[c], bh);
                mma16816(o[2*nb+1], ph[c], bh+2);
            }
        }

        __syncthreads();                 // all warps done reading V buffer
        if (kt + 1 < NKT) loadV(kt + 1);
        cp_commit();
    }

    // ---- epilogue: normalize, stage in SMEM, write single fp16 ----
    __syncthreads();
    float inv0 = 1.f / lrow0, inv1 = 1.f / lrow1;
    float* st = (float*)sm;   // reuse Q area (128 x 132 floats = 67584 B)
#pragma unroll
    for (int nf = 0; nf < 16; nf++) {
        int c0 = nf*8 + (lane & 3)*2;
        int r0 = wm + (lane >> 2);
        *(float2*)&st[r0*132 + c0]       = make_float2(o[nf][0]*inv0, o[nf][1]*inv0);
        *(float2*)&st[(r0 + 8)*132 + c0] = make_float2(o[nf][2]*inv1, o[nf][3]*inv1);
    }
    __syncthreads();
#pragma unroll
    for (int i = 0; i < 32; i++) {
        int idx = tid + i*256, r = idx >> 6, c = (idx & 63)*2;
        float f0 = st[r*132 + c], f1 = st[r*132 + c + 1];
        size_t off = ((size_t)(b*SS_ + qt*128 + r))*(HH*HD) + h*128 + c;
        *(uint32_t*)(g_attnH + off) = pack_single(f0, f1);
    }
}

// ---------------------------------------------------------------------------
extern "C" void kernel_launch(void* const* d_in, const int* in_sizes, int n_in,
                              void* d_out, int out_size) {
    const float* x     = (const float*)d_in[0];
    const float* wq    = (const float*)d_in[1];
    const float* wkv_a = (const float*)d_in[2];
    const float* kvns  = (const float*)d_in[3];
    const float* wkv_b = (const float*)d_in[4];
    const float* wo    = (const float*)d_in[5];
    const int*   pos   = (const int*)d_in[7];
    float* out = (float*)d_out;

    float *kv;
    cudaGetSymbolAddress((void**)&kv, g_kv);
    __half *xH,*kvcH,*attnH,*qH,*kH,*vH;
    cudaGetSymbolAddress((void**)&xH,    g_xH);
    cudaGetSymbolAddress((void**)&kvcH,  g_kvcH);
    cudaGetSymbolAddress((void**)&attnH, g_attnH);
    cudaGetSymbolAddress((void**)&qH,    g_qH);
    cudaGetSymbolAddress((void**)&kH,    g_kH);
    cudaGetSymbolAddress((void**)&vH,    g_vH);
    __half *wqah,*wbh,*woh;
    cudaGetSymbolAddress((void**)&wqah, g_wqaT_hi);
    cudaGetSymbolAddress((void**)&wbh,  g_wbT_hi);
    cudaGetSymbolAddress((void**)&woh,  g_woT_hi);

    cudaFuncSetAttribute((const void*)mma_gemm_t<0>, cudaFuncAttributeMaxDynamicSharedMemorySize, GEMM_SMEM);
    cudaFuncSetAttribute((const void*)mma_gemm_t<1>, cudaFuncAttributeMaxDynamicSharedMemorySize, GEMM_SMEM);
    cudaFuncSetAttribute((const void*)mma_gemm_t<2>, cudaFuncAttributeMaxDynamicSharedMemorySize, GEMM_SMEM);
    cudaFuncSetAttribute(fa_kernel, cudaFuncAttributeMaxDynamicSharedMemorySize, FA_SMEM);

    trig_kernel<<<SS_, 64>>>(pos);

    // weight transpose (all single fp16)
    transpose_cvt<<<dim3(QCOLS/32,  DD/32),  256>>>(wq,    wqah, DD, QCOLS);
    transpose_cvt<<<dim3(KVCOLS/32, DD/32),  256>>>(wkv_a, wqah + (size_t)QCOLS*DD, DD, KVCOLS);
    transpose_cvt<<<dim3(KVBCOLS/32,KVR/32), 256>>>(wkv_b, wbh, KVR, KVBCOLS);
    transpose_cvt<<<dim3(DD/32, (HH*HD)/32), 256>>>(wo,    woh, HH*HD, DD);

    // x -> single fp16
    cvt_half<<<((size_t)ROWS*DD)/1024, 256>>>(x, xH);

    // [q | kv] = x @ [wq | wkv_a]  (rope q -> qH, fp32 kv)
    mma_gemm_t<1><<<dim3(NQA/128, ROWS/128), 256, GEMM_SMEM>>>(
        xH, wqah, kv, qH, nullptr, ROWS, NQA, DD);
    // layernorm -> kvc fp16 ; roped k_pe -> g_kH (replicated)
    ln_rope_kv_kernel<<<ROWS, 256>>>(kvns);
    // kvb = kv_c @ wkv_b -> k_nope/v head-major (single fp16)
    mma_gemm_t<2><<<dim3(KVBCOLS/128, ROWS/128), 256, GEMM_SMEM>>>(
        kvcH, wbh, nullptr, kH, vH, ROWS, KVBCOLS, KVR);
    // flash attention (fp16 tensor cores, 1-term S and PV)
    fa_kernel<<<dim3(BB*HH, SS_/128), 256, FA_SMEM>>>();
    // out = attn @ wo
    mma_gemm_t<0><<<dim3(DD/128, ROWS/128), 256, GEMM_SMEM>>>(
        attnH, woh, out, nullptr, nullptr, ROWS, DD, HH*HD);
}

// round 13
// speedup vs baseline: 9.2209x; 1.0331x over previous
#include <cuda_runtime.h>
#include <cuda_fp16.h>
#include <math.h>
#include <cstdint>

// Problem constants
#define BB 2
#define SS_ 2048
#define DD 2048
#define HH 16
#define KVH 8
#define HD 128
#define KVR 512
#define ROWS (BB*SS_)          // 4096
#define QCOLS (HH*2*HD)        // 4096
#define KVCOLS (KVR+HD)        // 640
#define NQA (QCOLS+KVCOLS)     // 4736
#define KVBCOLS (KVH*2*HD)     // 2048

// fp32 scratch
__device__ float g_kv  [(size_t)ROWS*KVCOLS];
__device__ float g_cos [SS_*64];
__device__ float g_sin [SS_*64];

// fp16 activations (single fp16)
__device__ __half g_xH   [(size_t)ROWS*DD];
__device__ __half g_kvcH [(size_t)ROWS*KVR];
__device__ __half g_attnH[(size_t)ROWS*(HH*HD)];
__device__ __half g_qH   [(size_t)ROWS*QCOLS];
__device__ __half g_kH   [(size_t)BB*KVH*SS_*256];
__device__ __half g_vH   [(size_t)BB*KVH*SS_*128];

// transposed fp16 weights  WT[n][k] (single fp16)
__device__ __half g_wqaT_hi[(size_t)NQA*DD];      // wq ++ wkv_a
__device__ __half g_wbT_hi[(size_t)KVBCOLS*KVR];
__device__ __half g_woT_hi[(size_t)DD*(HH*HD)];

// ---------------------------------------------------------------------------
// helpers
// ---------------------------------------------------------------------------
__device__ __forceinline__ uint32_t smem_u32(const void* p) {
    uint32_t a;
    asm("{ .reg .u64 t; cvta.to.shared.u64 t, %1; cvt.u32.u64 %0, t; }"
        : "=r"(a) : "l"(p));
    return a;
}
#define SWZ(o) ((o) ^ (((o) >> 3) & 0x70))

__device__ __forceinline__ void cp16(uint32_t dst, const void* src) {
    asm volatile("cp.async.cg.shared.global [%0], [%1], 16;" :: "r"(dst), "l"(src));
}
__device__ __forceinline__ void cp_commit() {
    asm volatile("cp.async.commit_group;" ::: "memory");
}
__device__ __forceinline__ void cp_wait1() {
    asm volatile("cp.async.wait_group 1;" ::: "memory");
}
__device__ __forceinline__ void cp_wait2() {
    asm volatile("cp.async.wait_group 2;" ::: "memory");
}
__device__ __forceinline__ void ldsm_x4(uint32_t (&r)[4], uint32_t addr) {
    asm volatile("ldmatrix.sync.aligned.m8n8.x4.shared.b16 {%0,%1,%2,%3}, [%4];"
                 : "=r"(r[0]), "=r"(r[1]), "=r"(r[2]), "=r"(r[3]) : "r"(addr));
}
__device__ __forceinline__ void ldsm_x4_t(uint32_t (&r)[4], uint32_t addr) {
    asm volatile("ldmatrix.sync.aligned.m8n8.x4.trans.shared.b16 {%0,%1,%2,%3}, [%4];"
                 : "=r"(r[0]), "=r"(r[1]), "=r"(r[2]), "=r"(r[3]) : "r"(addr));
}
__device__ __forceinline__ void mma16816(float* d, const uint32_t* a, const uint32_t* b) {
    asm volatile(
        "mma.sync.aligned.m16n8k16.row.col.f32.f16.f16.f32 "
        "{%0,%1,%2,%3},{%4,%5,%6,%7},{%8,%9},{%0,%1,%2,%3};"
        : "+f"(d[0]), "+f"(d[1]), "+f"(d[2]), "+f"(d[3])
        : "r"(a[0]), "r"(a[1]), "r"(a[2]), "r"(a[3]), "r"(b[0]), "r"(b[1]));
}
__device__ __forceinline__ uint32_t pack_h2(__half a, __half b) {
    return (uint32_t)__half_as_ushort(a) | ((uint32_t)__half_as_ushort(b) << 16);
}
__device__ __forceinline__ uint32_t pack_single(float f0, float f1) {
    return pack_h2(__float2half_rn(f0), __float2half_rn(f1));
}

// ---------------------------------------------------------------------------
// Fused prep kernel: trig table + 4 weight transposes + x->fp16 convert.
// One launch; blockIdx-range dispatch. Math identical to the former kernels.
// Block budget (256 thr each):
//   [0, 512)                 trig (4 rows of 64 per block)
//   [512, 512+8192)          cvt_half(x)
//   then transposes: wq 8192, wkv_a 1280, wkv_b 1024, wo 4096
// total = 23296
// ---------------------------------------------------------------------------
#define PREP_TRIG    512
#define PREP_CVT     8192
#define PREP_WQ      8192
#define PREP_WA      1280
#define PREP_WB      1024
#define PREP_WO      4096
#define PREP_BLOCKS  (PREP_TRIG + PREP_CVT + PREP_WQ + PREP_WA + PREP_WB + PREP_WO)

__device__ __forceinline__ void transpose_tile(const float* __restrict__ W,
                                               __half* __restrict__ T,
                                               int K, int N, int bx, int by,
                                               int tid) {
    __shared__ float ts[32][33];
    int k0 = by * 32, n0 = bx * 32;
    int tx = tid & 31, ty = tid >> 5;  // 32x8
#pragma unroll
    for (int i = 0; i < 4; i++)
        ts[ty + 8*i][tx] = W[(size_t)(k0 + ty + 8*i)*N + n0 + tx];
    __syncthreads();
#pragma unroll
    for (int i = 0; i < 4; i++) {
        int n = ty + 8*i;
        T[(size_t)(n0 + n)*K + k0 + tx] = __float2half_rn(ts[tx][n]);
    }
}

__global__ void __launch_bounds__(256) prep_kernel(
        const int* __restrict__ pos_ids,
        const float* __restrict__ x,
        const float* __restrict__ wq,
        const float* __restrict__ wkv_a,
        const float* __restrict__ wkv_b,
        const float* __restrict__ wo) {
    int blk = blockIdx.x;
    int tid = threadIdx.x;

    if (blk < PREP_TRIG) {
        int s = blk * 4 + (tid >> 6);
        int i = tid & 63;
        double freq = 40.0 * pow(10000.0, -((double)(2*i)) / 128.0);
        float ang = (float)pos_ids[s] * (float)freq;
        g_cos[s*64 + i] = (float)cos((double)ang);
        g_sin[s*64 + i] = (float)sin((double)ang);
        return;
    }
    blk -= PREP_TRIG;
    if (blk < PREP_CVT) {
        size_t i = ((size_t)blk * 256 + tid) * 4;
        float4 v = *(const float4*)(x + i);
        *(uint2*)(g_xH + i) = make_uint2(pack_single(v.x, v.y), pack_single(v.z, v.w));
        return;
    }
    blk -= PREP_CVT;
    if (blk < PREP_WQ) {              // wq: K=DD, N=QCOLS, nx=128
        transpose_tile(wq, g_wqaT_hi, DD, QCOLS, blk & 127, blk >> 7, tid);
        return;
    }
    blk -= PREP_WQ;
    if (blk < PREP_WA) {              // wkv_a: K=DD, N=KVCOLS, nx=20
        transpose_tile(wkv_a, g_wqaT_hi + (size_t)QCOLS*DD, DD, KVCOLS,
                       blk % 20, blk / 20, tid);
        return;
    }
    blk -= PREP_WA;
    if (blk < PREP_WB) {              // wkv_b: K=KVR, N=KVBCOLS, nx=64
        transpose_tile(wkv_b, g_wbT_hi, KVR, KVBCOLS, blk & 63, blk >> 6, tid);
        return;
    }
    blk -= PREP_WB;
    {                                 // wo: K=HH*HD, N=DD, nx=64
        transpose_tile(wo, g_woT_hi, HH*HD, DD, blk & 63, blk >> 6, tid);
    }
}

// ---------------------------------------------------------------------------
// fp16 GEMM (1 term), 3-stage cp.async pipeline.
// MODE 0: C fp32.
// MODE 1: N=NQA; cc<QCOLS: rope(q_pe) -> qH; else fp32 -> g_kv.
// MODE 2: scatter k_nope -> OH, v -> O2H (head-major, single fp16).
// ---------------------------------------------------------------------------
#define GEMM_SMEM (3*32768)   // 96 KB

template<int MODE>
__global__ void __launch_bounds__(256)
mma_gemm_t(const __half* __restrict__ A,
           const __half* __restrict__ B,
           float* __restrict__ C,
           __half* __restrict__ OH, __half* __restrict__ O2H,
           int M, int N, int K) {
    extern __shared__ char sm[];
    uint32_t sb = smem_u32(sm);
    const int tid = threadIdx.x, lane = tid & 31, wid = tid >> 5;
    const int row0 = blockIdx.y * 128, col0 = blockIdx.x * 128;
    const int wm = (wid >> 2) * 64, wn = (wid & 3) * 32;
    const int NC = K >> 6;

    float acc[4][4][4];
#pragma unroll
    for (int mi = 0; mi < 4; mi++)
#pragma unroll
        for (int ni = 0; ni < 4; ni++)
#pragma unroll
            for (int r = 0; r < 4; r++) acc[mi][ni][r] = 0.f;

    auto load_chunk = [&](int cc, int buf) {
        const __half* gA = A + (size_t)row0 * K + cc * 64;
        const __half* gB = B + (size_t)col0 * K + cc * 64;
        uint32_t base = sb + (uint32_t)buf * 32768;
#pragma unroll
        for (int i = 0; i < 4; i++) {
            int idx = tid + i * 256;
            int r = idx >> 3, s = idx & 7;
            cp16(base + SWZ((uint32_t)(r * 128 + s * 16)), gA + (size_t)r * K + s * 8);
        }
#pragma unroll
        for (int i = 0; i < 4; i++) {
            int idx = tid + i * 256;
            int r = idx >> 3, s = idx & 7;
            cp16(base + 16384 + SWZ((uint32_t)(r * 128 + s * 16)), gB + (size_t)r * K + s * 8);
        }
    };

    load_chunk(0, 0); cp_commit();
    if (NC > 1) load_chunk(1, 1);
    cp_commit();

    for (int c = 0; c < NC; c++) {
        if (c + 2 < NC) load_chunk(c + 2, (c + 2) % 3);
        cp_commit();
        cp_wait2();
        __syncthreads();

        uint32_t sA = sb + (uint32_t)(c % 3) * 32768;
        uint32_t sB = sA + 16384;
        uint32_t Breg[4][4];
#pragma unroll
        for (int kk = 0; kk < 4; kk++) {
            if ((kk & 1) == 0) {
                int kh = kk >> 1;
#pragma unroll
                for (int ni = 0; ni < 4; ni++) {
                    uint32_t addr = sB + SWZ((uint32_t)((wn + ni*8 + (lane & 7)) * 128
                                                        + kh*64 + (lane >> 3) * 16));
                    ldsm_x4(Breg[ni], addr);
                }
            }
            uint32_t Areg[4][4];
#pragma unroll
            for (int mi = 0; mi < 4; mi++) {
                uint32_t addr = sA + SWZ((uint32_t)((wm + mi*16 + (lane & 15)) * 128
                                                    + kk*32 + (lane >> 4) * 16));
                ldsm_x4(Areg[mi], addr);
            }
#pragma unroll
            for (int mi = 0; mi < 4; mi++)
#pragma unroll
                for (int ni = 0; ni < 4; ni++)
                    mma16816(acc[mi][ni], Areg[mi], &Breg[ni][2 * (kk & 1)]);
        }
        __syncthreads();
    }

    // epilogue
#pragma unroll
    for (int mi = 0; mi < 4; mi++) {
        int r0 = row0 + wm + mi * 16 + (lane >> 2);
#pragma unroll
        for (int ni = 0; ni < 4; ni++) {
            int cc = col0 + wn + ni * 8 + (lane & 3) * 2;
            float a0 = acc[mi][ni][0], a1 = acc[mi][ni][1];
            float a2 = acc[mi][ni][2], a3 = acc[mi][ni][3];
            if (MODE == 0) {
                *(float2*)(C + (size_t)r0 * N + cc)       = make_float2(a0, a1);
                *(float2*)(C + (size_t)(r0 + 8) * N + cc) = make_float2(a2, a3);
            } else if (MODE == 1) {
                if (cc < QCOLS) {
                    int d = cc & 255;
                    if (d >= 128) {
                        int i = (d - 128) >> 1;
                        int s0 = r0 & (SS_-1), s1 = (r0 + 8) & (SS_-1);
                        float c0 = g_cos[s0*64 + i], sn0 = g_sin[s0*64 + i];
                        float c1 = g_cos[s1*64 + i], sn1 = g_sin[s1*64 + i];
                        float xr = a0, xi = a1;
                        a0 = xr*c0 - xi*sn0; a1 = xr*sn0 + xi*c0;
                        xr = a2; xi = a3;
                        a2 = xr*c1 - xi*sn1; a3 = xr*sn1 + xi*c1;
                    }
                    size_t o0 = (size_t)r0 * QCOLS + cc, o1 = (size_t)(r0 + 8) * QCOLS + cc;
                    *(uint32_t*)(OH + o0) = pack_single(a0, a1);
                    *(uint32_t*)(OH + o1) = pack_single(a2, a3);
                } else {
                    int kc = cc - QCOLS;
                    *(float2*)(C + (size_t)r0 * KVCOLS + kc)       = make_float2(a0, a1);
                    *(float2*)(C + (size_t)(r0 + 8) * KVCOLS + kc) = make_float2(a2, a3);
                }
            } else {
                int hk = cc >> 8, d = cc & 255;
                int b0 = r0 >> 11, s0 = r0 & (SS_-1);
                int b1 = (r0+8) >> 11, s1 = (r0+8) & (SS_-1);
                if (d < 128) {
                    size_t o0 = ((size_t)(b0*KVH + hk)*SS_ + s0)*256 + d;
                    size_t o1 = ((size_t)(b1*KVH + hk)*SS_ + s1)*256 + d;
                    *(uint32_t*)(OH + o0) = pack_single(a0, a1);
                    *(uint32_t*)(OH + o1) = pack_single(a2, a3);
                } else {
                    size_t o0 = ((size_t)(b0*KVH + hk)*SS_ + s0)*128 + (d - 128);
                    size_t o1 = ((size_t)(b1*KVH + hk)*SS_ + s1)*128 + (d - 128);
                    *(uint32_t*)(O2H + o0) = pack_single(a0, a1);
                    *(uint32_t*)(O2H + o1) = pack_single(a2, a3);
                }
            }
        }
    }
}

// ---------------------------------------------------------------------------
// LayerNorm -> kvc single fp16 ; RoPE(k_pe) -> single fp16 replicated into g_kH
// ---------------------------------------------------------------------------
__global__ void ln_rope_kv_kernel(const float* __restrict__ kvns) {
    int row = blockIdx.x;
    int tid = threadIdx.x;
    const float* x = g_kv + (size_t)row * KVCOLS;
    __shared__ float red[256];

    float v0 = x[tid], v1 = x[tid + 256];
    red[tid] = v0 + v1;
    __syncthreads();
#pragma unroll
    for (int off = 128; off > 0; off >>= 1) {
        if (tid < off) red[tid] += red[tid + off];
        __syncthreads();
    }
    float mean = red[0] * (1.f / 512.f);
    __syncthreads();
    float d0 = v0 - mean, d1 = v1 - mean;
    red[tid] = d0*d0 + d1*d1;
    __syncthreads();
#pragma unroll
    for (int off = 128; off > 0; off >>= 1) {
        if (tid < off) red[tid] += red[tid + off];
        __syncthreads();
    }
    float inv = rsqrtf(red[0] * (1.f / 512.f) + 1e-5f);
    size_t o = (size_t)row * KVR;
    g_kvcH[o + tid]       = __float2half_rn(d0 * inv * kvns[tid]);
    g_kvcH[o + tid + 256] = __float2half_rn(d1 * inv * kvns[tid + 256]);

    if (tid < 64) {
        int s = row & (SS_ - 1);
        int b = row >> 11;
        float c = g_cos[s*64 + tid], sn = g_sin[s*64 + tid];
        float xr = x[KVR + 2*tid], xi = x[KVR + 2*tid + 1];
        uint32_t hh = pack_single(xr*c - xi*sn, xr*sn + xi*c);
#pragma unroll
        for (int hk = 0; hk < KVH; hk++) {
            size_t base = ((size_t)(b*KVH + hk)*SS_ + s)*256 + 128 + 2*tid;
            *(uint32_t*)(g_kH + base) = hh;
        }
    }
}

// ---------------------------------------------------------------------------
// Tensor-core flash attention (fp16): S = 1 term, PV = 1 term.
// K double-buffered, V overlapped. SMEM 110 KB -> 2 CTAs/SM.
// ---------------------------------------------------------------------------
#define FA_QH_OFF 0                // 128 x 528 = 67584
#define FA_K0_OFF 67584            // two K stages of 16896
#define FA_KSTG   16896
#define FA_V_OFF  101376           // 8704
#define FA_SMEM   110080
#define QSTB 528
#define VSTB 272

__global__ void __launch_bounds__(256) fa_kernel() {
    const int tid = threadIdx.x, lane = tid & 31, wid = tid >> 5;
    const int b = blockIdx.x >> 4, h = blockIdx.x & 15, hk = h >> 1;
    const int qt = 15 - (int)blockIdx.y;   // big tiles first
    extern __shared__ char sm[];
    uint32_t sb = smem_u32(sm);

    const size_t kbase = (size_t)(b*KVH + hk) * SS_;
    const int NKT = 4*qt + 4;

    auto loadK = [&](int kt, int buf) {
        uint32_t kb = sb + FA_K0_OFF + (uint32_t)buf * FA_KSTG;
        const __half* khp = g_kH + (kbase + kt*32)*256;
#pragma unroll
        for (int i = 0; i < 4; i++) {
            int idx = tid + i*256, r = idx >> 5, c = idx & 31;
            cp16(kb + r*QSTB + c*16, khp + (size_t)r*256 + c*8);
        }
    };
    auto loadV = [&](int kt) {
        const __half* vhp = g_vH + (kbase + kt*32)*128;
#pragma unroll
        for (int i = 0; i < 2; i++) {
            int idx = tid + i*256, r = idx >> 4, c = idx & 15;
            cp16(sb + FA_V_OFF + r*VSTB + c*16, vhp + (size_t)r*128 + c*8);
        }
    };

    // prologue: Q, K0, V0 (three commit groups)
    {
        const __half* qh = g_qH + ((size_t)(b*SS_ + qt*128))*QCOLS + h*256;
#pragma unroll
        for (int i = 0; i < 16; i++) {
            int idx = tid + i*256, r = idx >> 5, c = idx & 31;
            cp16(sb + FA_QH_OFF + r*QSTB + c*16, qh + (size_t)r*QCOLS + c*8);
        }
        cp_commit();
    }
    loadK(0, 0); cp_commit();
    loadV(0);    cp_commit();

    const int wm = wid * 16;
    float mrow0 = -1e30f, mrow1 = -1e30f;
    float lrow0 = 0.f, lrow1 = 0.f;
    float o[16][4];
#pragma unroll
    for (int nf = 0; nf < 16; nf++)
#pragma unroll
        for (int e = 0; e < 4; e++) o[nf][e] = 0.f;

    const float scale = 0.08838834764831845f;

    for (int kt = 0; kt < NKT; kt++) {
        cp_wait1();              // Q+K(kt) done; V(kt) may be in flight
        __syncthreads();
        if (kt + 1 < NKT) loadK(kt + 1, (kt + 1) & 1);
        cp_commit();

        uint32_t kbuf = sb + FA_K0_OFF + (uint32_t)(kt & 1) * FA_KSTG;

        // ---- S = Q K^T (1 term) ----
        float s4[4][4];
#pragma unroll
        for (int f = 0; f < 4; f++)
#pragma unroll
            for (int e = 0; e < 4; e++) s4[f][e] = 0.f;

#pragma unroll
        for (int kc = 0; kc < 16; kc++) {
            uint32_t ah[4];
            uint32_t aaddr = sb + FA_QH_OFF + (uint32_t)(wm + (lane & 15))*QSTB
                             + (uint32_t)(kc*16 + (lane >> 4)*8)*2;
            ldsm_x4(ah, aaddr);
#pragma unroll
            for (int nb = 0; nb < 2; nb++) {
                uint32_t baddr = kbuf
                    + (uint32_t)(nb*16 + (lane >> 4)*8 + (lane & 7))*QSTB
                    + (uint32_t)(kc*16 + ((lane >> 3) & 1)*8)*2;
                uint32_t bh[4];
                ldsm_x4(bh, baddr);
                mma16816(s4[2*nb],   ah, bh);
                mma16816(s4[2*nb+1], ah, bh+2);
            }
        }

        // ---- scale + causal mask ----
        if (kt >= 4*qt) {
            int grow0 = qt*128 + wm + (lane >> 2);
#pragma unroll
            for (int f = 0; f < 4; f++)
#pragma unroll
                for (int e = 0; e < 4; e++) {
                    int col = kt*32 + f*8 + (lane & 3)*2 + (e & 1);
                    int row = grow0 + (e >> 1)*8;
                    float v = s4[f][e] * scale;
                    s4[f][e] = (col > row) ? -1e9f : v;
                }
        } else {
#pragma unroll
            for (int f = 0; f < 4; f++)
#pragma unroll
                for (int e = 0; e < 4; e++) s4[f][e] *= scale;
        }

        // ---- online softmax ----
        float rm0 = -1e30f, rm1 = -1e30f;
#pragma unroll
        for (int f = 0; f < 4; f++) {
            rm0 = fmaxf(rm0, fmaxf(s4[f][0], s4[f][1]));
            rm1 = fmaxf(rm1, fmaxf(s4[f][2], s4[f][3]));
        }
        rm0 = fmaxf(rm0, __shfl_xor_sync(0xffffffffu, rm0, 1));
        rm0 = fmaxf(rm0, __shfl_xor_sync(0xffffffffu, rm0, 2));
        rm1 = fmaxf(rm1, __shfl_xor_sync(0xffffffffu, rm1, 1));
        rm1 = fmaxf(rm1, __shfl_xor_sync(0xffffffffu, rm1, 2));
        float mn0 = fmaxf(mrow0, rm0), mn1 = fmaxf(mrow1, rm1);
        float al0 = __expf(mrow0 - mn0), al1 = __expf(mrow1 - mn1);
        float rs0 = 0.f, rs1 = 0.f;
#pragma unroll
        for (int f = 0; f < 4; f++) {
            s4[f][0] = __expf(s4[f][0] - mn0); rs0 += s4[f][0];
            s4[f][1] = __expf(s4[f][1] - mn0); rs0 += s4[f][1];
            s4[f][2] = __expf(s4[f][2] - mn1); rs1 += s4[f][2];
            s4[f][3] = __expf(s4[f][3] - mn1); rs1 += s4[f][3];
        }
        rs0 += __shfl_xor_sync(0xffffffffu, rs0, 1);
        rs0 += __shfl_xor_sync(0xffffffffu, rs0, 2);
        rs1 += __shfl_xor_sync(0xffffffffu, rs1, 1);
        rs1 += __shfl_xor_sync(0xffffffffu, rs1, 2);
        lrow0 = lrow0*al0 + rs0; mrow0 = mn0;
        lrow1 = lrow1*al1 + rs1; mrow1 = mn1;

#pragma unroll
        for (int nf = 0; nf < 16; nf++) {
            o[nf][0] *= al0; o[nf][1] *= al0;
            o[nf][2] *= al1; o[nf][3] *= al1;
        }

        // ---- P fragments (single fp16) ----
        uint32_t ph[2][4];
#pragma unroll
        for (int c = 0; c < 2; c++) {
#pragma unroll
            for (int g = 0; g < 2; g++) {
                ph[c][2*g]   = pack_single(s4[2*c+g][0], s4[2*c+g][1]);
                ph[c][2*g+1] = pack_single(s4[2*c+g][2], s4[2*c+g][3]);
            }
        }

        // V(kt) ready; K(kt+1) may still be in flight
        cp_wait1();
        __syncthreads();

        // ---- O += P V (1 term) ----
#pragma unroll
        for (int c = 0; c < 2; c++) {
#pragma unroll
            for (int nb = 0; nb < 8; nb++) {
                uint32_t vaddr = sb + FA_V_OFF
                    + (uint32_t)(c*16 + ((lane >> 3) & 1)*8 + (lane & 7))*VSTB
                    + (uint32_t)(nb*16 + (lane >> 4)*8)*2;
                uint32_t bh[4];
                ldsm_x4_t(bh, vaddr);
                mma16816(o[2*nb],   ph[c], bh);
                mma16816(o[2*nb+1], ph[c], bh+2);
            }
        }

        __syncthreads();                 // all warps done reading V buffer
        if (kt + 1 < NKT) loadV(kt + 1);
        cp_commit();
    }

    // ---- epilogue: normalize, stage in SMEM, write single fp16 ----
    __syncthreads();
    float inv0 = 1.f / lrow0, inv1 = 1.f / lrow1;
    float* st = (float*)sm;   // reuse Q area (128 x 132 floats = 67584 B)
#pragma unroll
    for (int nf = 0; nf < 16; nf++) {
        int c0 = nf*8 + (lane & 3)*2;
        int r0 = wm + (lane >> 2);
        *(float2*)&st[r0*132 + c0]       = make_float2(o[nf][0]*inv0, o[nf][1]*inv0);
        *(float2*)&st[(r0 + 8)*132 + c0] = make_float2(o[nf][2]*inv1, o[nf][3]*inv1);
    }
    __syncthreads();
#pragma unroll
    for (int i = 0; i < 32; i++) {
        int idx = tid + i*256, r = idx >> 6, c = (idx & 63)*2;
        float f0 = st[r*132 + c], f1 = st[r*132 + c + 1];
        size_t off = ((size_t)(b*SS_ + qt*128 + r))*(HH*HD) + h*128 + c;
        *(uint32_t*)(g_attnH + off) = pack_single(f0, f1);
    }
}

// ---------------------------------------------------------------------------
extern "C" void kernel_launch(void* const* d_in, const int* in_sizes, int n_in,
                              void* d_out, int out_size) {
    const float* x     = (const float*)d_in[0];
    const float* wq    = (const float*)d_in[1];
    const float* wkv_a = (const float*)d_in[2];
    const float* kvns  = (const float*)d_in[3];
    const float* wkv_b = (const float*)d_in[4];
    const float* wo    = (const float*)d_in[5];
    const int*   pos   = (const int*)d_in[7];
    float* out = (float*)d_out;

    float *kv;
    cudaGetSymbolAddress((void**)&kv, g_kv);
    __half *xH,*kvcH,*attnH,*qH,*kH,*vH;
    cudaGetSymbolAddress((void**)&xH,    g_xH);
    cudaGetSymbolAddress((void**)&kvcH,  g_kvcH);
    cudaGetSymbolAddress((void**)&attnH, g_attnH);
    cudaGetSymbolAddress((void**)&qH,    g_qH);
    cudaGetSymbolAddress((void**)&kH,    g_kH);
    cudaGetSymbolAddress((void**)&vH,    g_vH);
    __half *wqah,*wbh,*woh;
    cudaGetSymbolAddress((void**)&wqah, g_wqaT_hi);
    cudaGetSymbolAddress((void**)&wbh,  g_wbT_hi);
    cudaGetSymbolAddress((void**)&woh,  g_woT_hi);

    cudaFuncSetAttribute((const void*)mma_gemm_t<0>, cudaFuncAttributeMaxDynamicSharedMemorySize, GEMM_SMEM);
    cudaFuncSetAttribute((const void*)mma_gemm_t<1>, cudaFuncAttributeMaxDynamicSharedMemorySize, GEMM_SMEM);
    cudaFuncSetAttribute((const void*)mma_gemm_t<2>, cudaFuncAttributeMaxDynamicSharedMemorySize, GEMM_SMEM);
    cudaFuncSetAttribute(fa_kernel, cudaFuncAttributeMaxDynamicSharedMemorySize, FA_SMEM);

    // fused prep: trig + weight transposes + x->fp16 (one launch)
    prep_kernel<<<PREP_BLOCKS, 256>>>(pos, x, wq, wkv_a, wkv_b, wo);

    // [q | kv] = x @ [wq | wkv_a]  (rope q -> qH, fp32 kv)
    mma_gemm_t<1><<<dim3(NQA/128, ROWS/128), 256, GEMM_SMEM>>>(
        xH, wqah, kv, qH, nullptr, ROWS, NQA, DD);
    // layernorm -> kvc fp16 ; roped k_pe -> g_kH (replicated)
    ln_rope_kv_kernel<<<ROWS, 256>>>(kvns);
    // kvb = kv_c @ wkv_b -> k_nope/v head-major (single fp16)
    mma_gemm_t<2><<<dim3(KVBCOLS/128, ROWS/128), 256, GEMM_SMEM>>>(
        kvcH, wbh, nullptr, kH, vH, ROWS, KVBCOLS, KVR);
    // flash attention (fp16 tensor cores, 1-term S and PV)
    fa_kernel<<<dim3(BB*HH, SS_/128), 256, FA_SMEM>>>();
    // out = attn @ wo
    mma_gemm_t<0><<<dim3(DD/128, ROWS/128), 256, GEMM_SMEM>>>(
        attnH, woh, out, nullptr, nullptr, ROWS, DD, HH*HD);
}